// round 5
// baseline (speedup 1.0000x reference)
#include <cuda_runtime.h>
#include <cuda_bf16.h>
#include <math.h>

// Problem constants (fixed by setup_inputs)
#define Bz   2
#define C    64
#define H    128
#define W    128
#define OUT  256
#define TILE 64          // pixels per block (one row segment)
#define NTHR 256

// smem layout (in floats)
#define OFF_W1   0        // w1s[c*68+i],   64x68 = 4352
#define OFF_W2   4352     // w2s[c*68+i],   64x68 = 4352 (only 64 cols valid)
#define OFF_WC   8704     // wcp[(e*8+d)*68+c], 32x68 = 2176
#define OFF_WE   10880    // wes[(e*64+c)*8+d], 2048 (original layout)
#define OFF_WR   12928    // wrs[e*68+i],   4x68 = 272
#define OFF_WO   13200    // wos[o*68+i],   2x68 = 136
#define OFF_B1   13336    // 64
#define OFF_B2   13400    // 64
#define OFF_BR   13464    // 4
#define OFF_BO   13468    // 2 (+pad)
#define OFF_INP  13472    // inps[p*76+i], 64x76 = 4864 (aliased: embs[p*68+i])
#define OFF_HID  18336    // hidden[p*68+c] / fea0[p*68+c] / phase-1 staging tmp[c*34+j]
#define OFF_RS   22688    // rs[p*8+e], 512
#define OFF_OFS  23200    // offs[p*2+o], 128
#define OFF_CMP  23328    // cmps[p*12+d], 768
#define SMEM_FLOATS 24096
#define SMEM_BYTES (SMEM_FLOATS * 4)

#define INP_S 76
#define EMB_S 68
#define FEA_S 68

typedef unsigned long long u64t;

__device__ __forceinline__ u64t fma2(u64t a, u64t b, u64t c) {
    u64t d;
    asm("fma.rn.f32x2 %0, %1, %2, %3;" : "=l"(d) : "l"(a), "l"(b), "l"(c));
    return d;
}
__device__ __forceinline__ float hadd2(u64t v) {
    float lo, hi;
    asm("mov.b64 {%0, %1}, %2;" : "=f"(lo), "=f"(hi) : "l"(v));
    return lo + hi;
}
__device__ __forceinline__ float4 ld4(const float* p) {
    return *reinterpret_cast<const float4*>(p);
}
__device__ __forceinline__ ulonglong2 ld2u(const float* p) {
    return *reinterpret_cast<const ulonglong2*>(p);
}

__device__ __forceinline__ float bilin(const float* __restrict__ img, float fx, float fy) {
    float x0f = floorf(fx), y0f = floorf(fy);
    float wx1 = fx - x0f, wy1 = fy - y0f;
    float wx0 = 1.0f - wx1, wy0 = 1.0f - wy1;
    int x0 = (int)x0f, y0 = (int)y0f;
    int xi0 = min(max(x0, 0), W - 1), yi0 = min(max(y0, 0), H - 1);
    int xi1 = min(max(x0 + 1, 0), W - 1), yi1 = min(max(y0 + 1, 0), H - 1);
    bool vx0 = (x0f >= 0.0f) && (x0f <= (float)(W - 1));
    bool vx1 = (x0f >= -1.0f) && (x0f <= (float)(W - 2));
    bool vy0 = (y0f >= 0.0f) && (y0f <= (float)(H - 1));
    bool vy1 = (y0f >= -1.0f) && (y0f <= (float)(H - 2));
    float v00 = (vx0 && vy0) ? __ldg(img + yi0 * W + xi0) : 0.0f;
    float v10 = (vx1 && vy0) ? __ldg(img + yi0 * W + xi1) : 0.0f;
    float v01 = (vx0 && vy1) ? __ldg(img + yi1 * W + xi0) : 0.0f;
    float v11 = (vx1 && vy1) ? __ldg(img + yi1 * W + xi1) : 0.0f;
    return v00 * (wx0 * wy0) + v10 * (wx1 * wy0) + v01 * (wx0 * wy1) + v11 * (wx1 * wy1);
}

__global__ __launch_bounds__(NTHR, 2)
void SCAB_upsample_20650202759886_kernel(
    const float* __restrict__ x,
    const float* __restrict__ wcmp,   // (4,8,64)
    const float* __restrict__ wexp,   // (4,64,8)
    const float* __restrict__ w1,     // (64,68)
    const float* __restrict__ b1,
    const float* __restrict__ w2,     // (64,64)
    const float* __restrict__ b2,
    const float* __restrict__ wr,     // (4,64)
    const float* __restrict__ br,
    const float* __restrict__ wo,     // (2,64)
    const float* __restrict__ bo,
    float* __restrict__ out)
{
    extern __shared__ float sm[];
    float* w1s  = sm + OFF_W1;
    float* w2s  = sm + OFF_W2;
    float* wcp  = sm + OFF_WC;
    float* wes  = sm + OFF_WE;
    float* wrs  = sm + OFF_WR;
    float* wos  = sm + OFF_WO;
    float* b1s  = sm + OFF_B1;
    float* b2s  = sm + OFF_B2;
    float* brs  = sm + OFF_BR;
    float* bos  = sm + OFF_BO;
    float* inps = sm + OFF_INP;   // also embs (stride 68) after phase 3
    float* embs = sm + OFF_INP;
    float* hidf = sm + OFF_HID;   // staging tmp / hidden / fea0 union
    float* rs   = sm + OFF_RS;
    float* offs = sm + OFF_OFS;
    float* cmps = sm + OFF_CMP;

    const int t  = threadIdx.x;
    const int oy = blockIdx.y;
    const int bz = blockIdx.z;
    const int ox0 = blockIdx.x * TILE;

    // ---- stage weights ----
    for (int i = t; i < 64 * 68; i += NTHR) w1s[i] = w1[i];
    for (int i = t; i < 64 * 64; i += NTHR) { int c = i >> 6, k = i & 63; w2s[c * 68 + k] = w2[i]; }
    for (int i = t; i < 32 * 64; i += NTHR) { int ed = i >> 6, c = i & 63; wcp[ed * 68 + c] = wcmp[i]; }
    for (int i = t; i < 2048;    i += NTHR) wes[i] = wexp[i];
    if (t < 256) { int e = t >> 6, k = t & 63; wrs[e * 68 + k] = wr[t]; }
    if (t < 128) { int o = t >> 6, k = t & 63; wos[o * 68 + k] = wo[t]; }
    if (t < 64) { b1s[t] = b1[t]; b2s[t] = b2[t]; }
    if (t < 4) brs[t] = br[t];
    if (t < 2) bos[t] = bo[t];
    __syncthreads();

    const float inv127 = 2.0f / 127.0f;

    // ---- phase 1a: stage + vertical lerp of source rows into tmp = hidf[c*34+j] ----
    // fy is constant across the block (single output row); x footprint is 34 cols.
    float gy_blk = ((oy + 0.5f) / 2.0f - 0.5f) * inv127 - 1.0f;
    float fy_blk = ((gy_blk + 1.0f) * (float)H - 1.0f) * 0.5f;
    float gx_blk = ((ox0 + 0.5f) / 2.0f - 0.5f) * inv127 - 1.0f;
    float fx_blk = ((gx_blk + 1.0f) * (float)W - 1.0f) * 0.5f;
    const int m_blk = (int)floorf(fx_blk);
    {
        float y0f = floorf(fy_blk);
        float wy1 = fy_blk - y0f, wy0 = 1.0f - wy1;
        int y0 = (int)y0f;
        bool vy0 = (y0 >= 0) && (y0 <= H - 1);
        bool vy1 = (y0 >= -1) && (y0 <= H - 2);
        int yi0 = min(max(y0, 0), H - 1);
        int yi1 = min(max(y0 + 1, 0), H - 1);
        const float* xb = x + (size_t)bz * C * H * W;
        #pragma unroll 1
        for (int i = t; i < 64 * 34; i += NTHR) {
            int c = i / 34, j = i - c * 34;
            int xs = m_blk + j;
            bool vx = (xs >= 0) && (xs <= W - 1);
            int xc = min(max(xs, 0), W - 1);
            const float* base = xb + c * (H * W);
            float v0 = (vx && vy0) ? __ldg(base + yi0 * W + xc) : 0.0f;
            float v1 = (vx && vy1) ? __ldg(base + yi1 * W + xc) : 0.0f;
            hidf[c * 34 + j] = v0 * wy0 + v1 * wy1;
        }
    }
    __syncthreads();

    // ---- phase 1b: horizontal lerp + coords -> inps (stride 76), vector stores ----
    {
        const int p  = t & 63;
        const int cb = t >> 6;
        const int ox = ox0 + p;
        float gx = ((ox + 0.5f) / 2.0f - 0.5f) * inv127 - 1.0f;
        float fx = ((gx + 1.0f) * (float)W - 1.0f) * 0.5f;
        float x0f = floorf(fx);
        float wx1 = fx - x0f, wx0 = 1.0f - wx1;
        int j0 = (int)x0f - m_blk;         // in [0, 32]
        if (cb == 0) {
            float ah = (oy + 0.5f) / 2.0f;
            float aw = (ox + 0.5f) / 2.0f;
            *reinterpret_cast<float4*>(&inps[p * INP_S]) =
                make_float4(0.5f, 0.5f,
                            ah - floorf(ah + 0.001f) - 0.5f,
                            aw - floorf(aw + 0.001f) - 0.5f);
        }
        #pragma unroll 1
        for (int k4 = 0; k4 < 4; k4++) {
            float4 v;
            #pragma unroll
            for (int kk = 0; kk < 4; kk++) {
                int c = cb * 16 + k4 * 4 + kk;
                float tL = hidf[c * 34 + j0];
                float tR = hidf[c * 34 + j0 + 1];
                ((float*)&v)[kk] = tL * wx0 + tR * wx1;
            }
            *reinterpret_cast<float4*>(&inps[p * INP_S + 4 + cb * 16 + k4 * 4]) = v;
        }
    }
    __syncthreads();

    // ---- phase 2: layer1 (68 -> 64), relu. thread = (pixel, 16-ch group) ----
    {
        const int p = t & 63, g = t >> 6;
        ulonglong2 A[17];
        #pragma unroll
        for (int i = 0; i < 17; i++) A[i] = ld2u(&inps[p * INP_S + i * 4]);
        const float* wbase = w1s + g * 16 * 68;
        const float* bb    = b1s + g * 16;
        float* hrow = &hidf[p * 68 + g * 16];
        #pragma unroll 1
        for (int cc = 0; cc < 4; cc++) {
            float4 o4;
            #pragma unroll
            for (int c4 = 0; c4 < 4; c4++) {
                const float* wrow = wbase + (cc * 4 + c4) * 68;
                u64t a0 = 0ull, a1 = 0ull;
                #pragma unroll
                for (int i = 0; i < 17; i++) {
                    ulonglong2 wv = ld2u(wrow + i * 4);
                    a0 = fma2(wv.x, A[i].x, a0);
                    a1 = fma2(wv.y, A[i].y, a1);
                }
                float s = hadd2(a0) + hadd2(a1) + bb[cc * 4 + c4];
                ((float*)&o4)[c4] = fmaxf(s, 0.0f);
            }
            *reinterpret_cast<float4*>(hrow + cc * 4) = o4;
        }
    }
    __syncthreads();

    // ---- phase 3: layer2 (64 -> 64), relu -> embs (stride 68, aliases inps) ----
    {
        const int p = t & 63, g = t >> 6;
        ulonglong2 A[16];
        #pragma unroll
        for (int i = 0; i < 16; i++) A[i] = ld2u(&hidf[p * 68 + i * 4]);
        const float* wbase = w2s + g * 16 * 68;
        const float* bb    = b2s + g * 16;
        float erow[16];
        #pragma unroll 1
        for (int cc = 0; cc < 4; cc++) {
            #pragma unroll
            for (int c4 = 0; c4 < 4; c4++) {
                const float* wrow = wbase + (cc * 4 + c4) * 68;
                u64t a0 = 0ull, a1 = 0ull;
                #pragma unroll
                for (int i = 0; i < 16; i++) {
                    ulonglong2 wv = ld2u(wrow + i * 4);
                    a0 = fma2(wv.x, A[i].x, a0);
                    a1 = fma2(wv.y, A[i].y, a1);
                }
                float s = hadd2(a0) + hadd2(a1) + bb[cc * 4 + c4];
                erow[cc * 4 + c4] = fmaxf(s, 0.0f);
            }
        }
        // embs aliases inps; all inps reads finished at the sync above
        float* ebase = &embs[p * EMB_S + g * 16];
        #pragma unroll
        for (int cc = 0; cc < 4; cc++)
            *reinterpret_cast<float4*>(ebase + cc * 4) =
                *reinterpret_cast<const float4*>(&erow[cc * 4]);
    }
    __syncthreads();

    // ---- phase 4: r (sigmoid) + offsets, f32x2 ----
    {
        const int p = t >> 2, e = t & 3;
        const float* erow = &embs[p * EMB_S];
        const float* wrr = wrs + e * 68;
        const float* wor = wos + (e & 1) * 68;
        u64t r0 = 0ull, r1 = 0ull, o0 = 0ull, o1 = 0ull;
        #pragma unroll
        for (int i = 0; i < 16; i++) {
            ulonglong2 ev  = ld2u(erow + i * 4);
            ulonglong2 wrv = ld2u(wrr + i * 4);
            ulonglong2 wov = ld2u(wor + i * 4);
            r0 = fma2(wrv.x, ev.x, r0);
            r1 = fma2(wrv.y, ev.y, r1);
            o0 = fma2(wov.x, ev.x, o0);
            o1 = fma2(wov.y, ev.y, o1);
        }
        float accR = hadd2(r0) + hadd2(r1) + brs[e];
        rs[p * 8 + e] = 1.0f / (1.0f + __expf(-accR));
        if (e < 2) offs[p * 2 + e] = hadd2(o0) + hadd2(o1) + bos[e];
    }
    __syncthreads();

    // ---- phase 5: fea0 sample (with offsets) -> hidf (stride 68) ----
    {
        const int p  = t & 63;
        const int cb = t >> 6;
        const int ox = ox0 + p;
        float gx = ((ox + 0.5f) / 2.0f - 0.5f) * inv127 - 1.0f;
        float gy = ((oy + 0.5f) / 2.0f - 0.5f) * inv127 - 1.0f;
        float ix = gx + offs[p * 2 + 0] * inv127;
        float iy = gy + offs[p * 2 + 1] * inv127;
        float fx = ((ix + 1.0f) * (float)W - 1.0f) * 0.5f;
        float fy = ((iy + 1.0f) * (float)H - 1.0f) * 0.5f;
        const float* xb = x + (size_t)bz * C * H * W;
        #pragma unroll 4
        for (int k = 0; k < 16; k++) {
            int c = cb * 16 + k;
            hidf[p * FEA_S + c] = bilin(xb + c * (H * W), fx, fy);
        }
    }
    __syncthreads();

    // ---- phase 6: comp[d] = sum_e r_e * (wc[e,d,:]·fea0). thread = (pixel, d-pair) ----
    {
        const int p = t & 63, dg = t >> 6;   // d pair (2dg, 2dg+1)
        ulonglong2 Fv[16];
        #pragma unroll
        for (int i = 0; i < 16; i++) Fv[i] = ld2u(&hidf[p * FEA_S + i * 4]);
        float4 rv = ld4(&rs[p * 8]);
        float comp0 = 0.0f, comp1 = 0.0f;
        #pragma unroll
        for (int e = 0; e < 4; e++) {
            const float* w0 = &wcp[(e * 8 + 2 * dg) * 68];
            const float* w1r = w0 + 68;
            u64t a0 = 0ull, a1 = 0ull, c0 = 0ull, c1 = 0ull;
            #pragma unroll
            for (int i = 0; i < 16; i++) {
                ulonglong2 wv0 = ld2u(w0 + i * 4);
                ulonglong2 wv1 = ld2u(w1r + i * 4);
                a0 = fma2(wv0.x, Fv[i].x, a0);
                a1 = fma2(wv0.y, Fv[i].y, a1);
                c0 = fma2(wv1.x, Fv[i].x, c0);
                c1 = fma2(wv1.y, Fv[i].y, c1);
            }
            float re = ((const float*)&rv)[e];
            comp0 = fmaf(re, hadd2(a0) + hadd2(a1), comp0);
            comp1 = fmaf(re, hadd2(c0) + hadd2(c1), comp1);
        }
        cmps[p * 12 + 2 * dg]     = comp0;
        cmps[p * 12 + 2 * dg + 1] = comp1;
    }
    __syncthreads();

    // ---- phase 7: expand + residual + store, f32x2 ----
    {
        const int p  = t & 63;
        const int cb = t >> 6;
        ulonglong2 cr0 = ld2u(&cmps[p * 12]);
        ulonglong2 cr1 = ld2u(&cmps[p * 12 + 4]);
        float4 rv = ld4(&rs[p * 8]);
        const int ox = ox0 + p;
        float* ob = out + (((size_t)bz * C + cb * 16) * OUT + oy) * OUT + ox;
        #pragma unroll 1
        for (int k4 = 0; k4 < 4; k4++) {
            float4 f4 = ld4(&hidf[p * FEA_S + cb * 16 + k4 * 4]);
            #pragma unroll
            for (int kk = 0; kk < 4; kk++) {
                int c = cb * 16 + k4 * 4 + kk;
                float acc = ((const float*)&f4)[kk];
                #pragma unroll
                for (int e = 0; e < 4; e++) {
                    const float* werow = &wes[(e * 64 + c) * 8];
                    ulonglong2 wv = ld2u(werow);
                    ulonglong2 wv2 = ld2u(werow + 4);
                    u64t s2 = fma2(wv.x, cr0.x, 0ull);
                    s2 = fma2(wv.y, cr0.y, s2);
                    s2 = fma2(wv2.x, cr1.x, s2);
                    s2 = fma2(wv2.y, cr1.y, s2);
                    acc = fmaf(((const float*)&rv)[e], hadd2(s2), acc);
                }
                ob[(size_t)(k4 * 4 + kk) * OUT * OUT] = acc;
            }
        }
    }
}

extern "C" void kernel_launch(void* const* d_in, const int* in_sizes, int n_in,
                              void* d_out, int out_size) {
    (void)in_sizes; (void)n_in; (void)out_size;
    const float* x    = (const float*)d_in[0];
    const float* wcmp = (const float*)d_in[1];
    const float* wexp = (const float*)d_in[2];
    const float* w1   = (const float*)d_in[3];
    const float* b1   = (const float*)d_in[4];
    const float* w2   = (const float*)d_in[5];
    const float* b2   = (const float*)d_in[6];
    const float* wr   = (const float*)d_in[7];
    const float* br   = (const float*)d_in[8];
    const float* wo   = (const float*)d_in[9];
    const float* bo   = (const float*)d_in[10];
    float* out = (float*)d_out;

    cudaFuncSetAttribute(SCAB_upsample_20650202759886_kernel,
                         cudaFuncAttributeMaxDynamicSharedMemorySize, SMEM_BYTES);
    dim3 grid(OUT / TILE, OUT, Bz);
    SCAB_upsample_20650202759886_kernel<<<grid, NTHR, SMEM_BYTES>>>(
        x, wcmp, wexp, w1, b1, w2, b2, wr, br, wo, bo, out);
}

// round 6
// speedup vs baseline: 1.3563x; 1.3563x over previous
#include <cuda_runtime.h>
#include <cuda_bf16.h>
#include <math.h>

// Problem constants (fixed by setup_inputs)
#define Bz   2
#define C    64
#define H    128
#define W    128
#define OUT  256
#define TILE 64
#define NTHR 256
#define NPX  (Bz * OUT * OUT)

// ---------------- global scratch (static, allowed) ----------------
__device__ float g_rs  [NPX * 4];
__device__ float g_offs[NPX * 2];
__device__ float g_fea0[NPX * 64];

// ---------------- K1 smem layout (floats) ----------------
#define K1_W1   0        // 64x68 = 4352
#define K1_W2   4352     // 64x68 = 4352
#define K1_WR   8704     // 4x68  = 272
#define K1_WO   8976     // 2x68  = 136
#define K1_B1   9112
#define K1_B2   9176
#define K1_BR   9240
#define K1_BO   9244
#define K1_INP  9248     // inps[p*76+i] 64x76 = 4864 (aliased embs[p*68+i])
#define K1_HID  14112    // hidden[p*68+c] 64x68 = 4352
#define K1_FLOATS 18464
#define K1_BYTES (K1_FLOATS * 4)

// ---------------- K3 smem layout (floats) ----------------
#define K3_WC   0        // wcp[(e*8+d)*68+c] 32x68 = 2176
#define K3_WE   2176     // wes[(e*64+c)*8+d] = 2048
#define K3_CMP  4224     // cmps[p*12+d] = 768
#define K3_FLOATS 4992
#define K3_BYTES (K3_FLOATS * 4)

#define INP_S 76
#define EMB_S 68

typedef unsigned long long u64t;

__device__ __forceinline__ u64t fma2(u64t a, u64t b, u64t c) {
    u64t d;
    asm("fma.rn.f32x2 %0, %1, %2, %3;" : "=l"(d) : "l"(a), "l"(b), "l"(c));
    return d;
}
__device__ __forceinline__ float hadd2(u64t v) {
    float lo, hi;
    asm("mov.b64 {%0, %1}, %2;" : "=f"(lo), "=f"(hi) : "l"(v));
    return lo + hi;
}
__device__ __forceinline__ float4 ld4(const float* p) {
    return *reinterpret_cast<const float4*>(p);
}
__device__ __forceinline__ ulonglong2 ld2u(const float* p) {
    return *reinterpret_cast<const ulonglong2*>(p);
}

__device__ __forceinline__ float bilin(const float* __restrict__ img, float fx, float fy) {
    float x0f = floorf(fx), y0f = floorf(fy);
    float wx1 = fx - x0f, wy1 = fy - y0f;
    float wx0 = 1.0f - wx1, wy0 = 1.0f - wy1;
    int x0 = (int)x0f, y0 = (int)y0f;
    int xi0 = min(max(x0, 0), W - 1), yi0 = min(max(y0, 0), H - 1);
    int xi1 = min(max(x0 + 1, 0), W - 1), yi1 = min(max(y0 + 1, 0), H - 1);
    bool vx0 = (x0f >= 0.0f) && (x0f <= (float)(W - 1));
    bool vx1 = (x0f >= -1.0f) && (x0f <= (float)(W - 2));
    bool vy0 = (y0f >= 0.0f) && (y0f <= (float)(H - 1));
    bool vy1 = (y0f >= -1.0f) && (y0f <= (float)(H - 2));
    float v00 = (vx0 && vy0) ? __ldg(img + yi0 * W + xi0) : 0.0f;
    float v10 = (vx1 && vy0) ? __ldg(img + yi0 * W + xi1) : 0.0f;
    float v01 = (vx0 && vy1) ? __ldg(img + yi1 * W + xi0) : 0.0f;
    float v11 = (vx1 && vy1) ? __ldg(img + yi1 * W + xi1) : 0.0f;
    return v00 * (wx0 * wy0) + v10 * (wx1 * wy0) + v01 * (wx0 * wy1) + v11 * (wx1 * wy1);
}

// =================== K1: phases 1-4 (coords, sample1, MLP, heads) ===================
__global__ __launch_bounds__(NTHR, 2)
void scab_k1(const float* __restrict__ x,
             const float* __restrict__ w1, const float* __restrict__ b1,
             const float* __restrict__ w2, const float* __restrict__ b2,
             const float* __restrict__ wr, const float* __restrict__ br,
             const float* __restrict__ wo, const float* __restrict__ bo)
{
    extern __shared__ float sm[];
    float* w1s  = sm + K1_W1;
    float* w2s  = sm + K1_W2;
    float* wrs  = sm + K1_WR;
    float* wos  = sm + K1_WO;
    float* b1s  = sm + K1_B1;
    float* b2s  = sm + K1_B2;
    float* brs  = sm + K1_BR;
    float* bos  = sm + K1_BO;
    float* inps = sm + K1_INP;   // aliased embs after phase 3
    float* embs = sm + K1_INP;
    float* hidf = sm + K1_HID;

    const int t  = threadIdx.x;
    const int oy = blockIdx.y;
    const int bz = blockIdx.z;
    const int ox0 = blockIdx.x * TILE;

    for (int i = t; i < 64 * 68; i += NTHR) w1s[i] = w1[i];
    for (int i = t; i < 64 * 64; i += NTHR) { int c = i >> 6, k = i & 63; w2s[c * 68 + k] = w2[i]; }
    if (t < 256) { int e = t >> 6, k = t & 63; wrs[e * 68 + k] = wr[t]; }
    if (t < 128) { int o = t >> 6, k = t & 63; wos[o * 68 + k] = wo[t]; }
    if (t < 64) { b1s[t] = b1[t]; b2s[t] = b2[t]; }
    if (t < 4) brs[t] = br[t];
    if (t < 2) bos[t] = bo[t];
    __syncthreads();

    const float inv127 = 2.0f / 127.0f;

    // ---- phase 1: coords + pre_fea sample -> inps ----
    {
        const int p  = t & 63;
        const int cb = t >> 6;
        const int ox = ox0 + p;
        float gx = ((ox + 0.5f) / 2.0f - 0.5f) * inv127 - 1.0f;
        float gy = ((oy + 0.5f) / 2.0f - 0.5f) * inv127 - 1.0f;
        float fx = ((gx + 1.0f) * (float)W - 1.0f) * 0.5f;
        float fy = ((gy + 1.0f) * (float)H - 1.0f) * 0.5f;
        if (cb == 0) {
            float ah = (oy + 0.5f) / 2.0f;
            float aw = (ox + 0.5f) / 2.0f;
            *reinterpret_cast<float4*>(&inps[p * INP_S]) =
                make_float4(0.5f, 0.5f,
                            ah - floorf(ah + 0.001f) - 0.5f,
                            aw - floorf(aw + 0.001f) - 0.5f);
        }
        const float* xb = x + (size_t)bz * C * H * W;
        #pragma unroll 4
        for (int k = 0; k < 16; k++) {
            int c = cb * 16 + k;
            inps[p * INP_S + 4 + c] = bilin(xb + c * (H * W), fx, fy);
        }
    }
    __syncthreads();

    // ---- phase 2: layer1 (68 -> 64), relu ----
    {
        const int p = t & 63, g = t >> 6;
        ulonglong2 A[17];
        #pragma unroll
        for (int i = 0; i < 17; i++) A[i] = ld2u(&inps[p * INP_S + i * 4]);
        const float* wbase = w1s + g * 16 * 68;
        const float* bb    = b1s + g * 16;
        float* hrow = &hidf[p * 68 + g * 16];
        #pragma unroll 1
        for (int cc = 0; cc < 4; cc++) {
            float4 o4;
            #pragma unroll
            for (int c4 = 0; c4 < 4; c4++) {
                const float* wrow = wbase + (cc * 4 + c4) * 68;
                u64t a0 = 0ull, a1 = 0ull;
                #pragma unroll
                for (int i = 0; i < 17; i++) {
                    ulonglong2 wv = ld2u(wrow + i * 4);
                    a0 = fma2(wv.x, A[i].x, a0);
                    a1 = fma2(wv.y, A[i].y, a1);
                }
                float s = hadd2(a0) + hadd2(a1) + bb[cc * 4 + c4];
                ((float*)&o4)[c4] = fmaxf(s, 0.0f);
            }
            *reinterpret_cast<float4*>(hrow + cc * 4) = o4;
        }
    }
    __syncthreads();

    // ---- phase 3: layer2 (64 -> 64), relu -> embs (aliases inps) ----
    {
        const int p = t & 63, g = t >> 6;
        ulonglong2 A[16];
        #pragma unroll
        for (int i = 0; i < 16; i++) A[i] = ld2u(&hidf[p * 68 + i * 4]);
        const float* wbase = w2s + g * 16 * 68;
        const float* bb    = b2s + g * 16;
        float erow[16];
        #pragma unroll 1
        for (int cc = 0; cc < 4; cc++) {
            #pragma unroll
            for (int c4 = 0; c4 < 4; c4++) {
                const float* wrow = wbase + (cc * 4 + c4) * 68;
                u64t a0 = 0ull, a1 = 0ull;
                #pragma unroll
                for (int i = 0; i < 16; i++) {
                    ulonglong2 wv = ld2u(wrow + i * 4);
                    a0 = fma2(wv.x, A[i].x, a0);
                    a1 = fma2(wv.y, A[i].y, a1);
                }
                float s = hadd2(a0) + hadd2(a1) + bb[cc * 4 + c4];
                erow[cc * 4 + c4] = fmaxf(s, 0.0f);
            }
        }
        float* ebase = &embs[p * EMB_S + g * 16];
        #pragma unroll
        for (int cc = 0; cc < 4; cc++)
            *reinterpret_cast<float4*>(ebase + cc * 4) =
                *reinterpret_cast<const float4*>(&erow[cc * 4]);
    }
    __syncthreads();

    // ---- phase 4: r (sigmoid) + offsets -> global ----
    {
        const int p = t >> 2, e = t & 3;
        const float* erow = &embs[p * EMB_S];
        const float* wrr = wrs + e * 68;
        const float* wor = wos + (e & 1) * 68;
        u64t r0 = 0ull, r1 = 0ull, o0 = 0ull, o1 = 0ull;
        #pragma unroll
        for (int i = 0; i < 16; i++) {
            ulonglong2 ev  = ld2u(erow + i * 4);
            ulonglong2 wrv = ld2u(wrr + i * 4);
            ulonglong2 wov = ld2u(wor + i * 4);
            r0 = fma2(wrv.x, ev.x, r0);
            r1 = fma2(wrv.y, ev.y, r1);
            o0 = fma2(wov.x, ev.x, o0);
            o1 = fma2(wov.y, ev.y, o1);
        }
        float accR = hadd2(r0) + hadd2(r1) + brs[e];
        const int pxg = ((bz * OUT + oy) * OUT) + ox0 + p;
        g_rs[pxg * 4 + e] = 1.0f / (1.0f + __expf(-accR));
        if (e < 2) g_offs[pxg * 2 + e] = hadd2(o0) + hadd2(o1) + bos[e];
    }
}

// =================== K2: phase 5 (offset sample -> g_fea0[px][c]) ===================
__global__ __launch_bounds__(NTHR, 4)
void scab_k2(const float* __restrict__ x)
{
    const int t  = threadIdx.x;
    const int oy = blockIdx.y;
    const int bz = blockIdx.z;
    const int ox0 = blockIdx.x * TILE;
    const int p  = t & 63;
    const int cb = t >> 6;
    const int ox = ox0 + p;
    const int pxg = ((bz * OUT + oy) * OUT) + ox;

    const float inv127 = 2.0f / 127.0f;
    float gx = ((ox + 0.5f) / 2.0f - 0.5f) * inv127 - 1.0f;
    float gy = ((oy + 0.5f) / 2.0f - 0.5f) * inv127 - 1.0f;
    float ix = gx + g_offs[pxg * 2 + 0] * inv127;
    float iy = gy + g_offs[pxg * 2 + 1] * inv127;
    float fx = ((ix + 1.0f) * (float)W - 1.0f) * 0.5f;
    float fy = ((iy + 1.0f) * (float)H - 1.0f) * 0.5f;
    const float* xb = x + (size_t)bz * C * H * W;
    float* fb = &g_fea0[(size_t)pxg * 64 + cb * 16];
    #pragma unroll 1
    for (int k4 = 0; k4 < 4; k4++) {
        float4 v;
        #pragma unroll
        for (int kk = 0; kk < 4; kk++) {
            int c = cb * 16 + k4 * 4 + kk;
            ((float*)&v)[kk] = bilin(xb + c * (H * W), fx, fy);
        }
        *reinterpret_cast<float4*>(fb + k4 * 4) = v;
    }
}

// =================== K3: phases 6-7 (compress, expand, residual, store) ===================
__global__ __launch_bounds__(NTHR, 4)
void scab_k3(const float* __restrict__ wcmp,
             const float* __restrict__ wexp,
             float* __restrict__ out)
{
    extern __shared__ float sm[];
    float* wcp  = sm + K3_WC;
    float* wes  = sm + K3_WE;
    float* cmps = sm + K3_CMP;

    const int t  = threadIdx.x;
    const int oy = blockIdx.y;
    const int bz = blockIdx.z;
    const int ox0 = blockIdx.x * TILE;

    for (int i = t; i < 32 * 64; i += NTHR) { int ed = i >> 6, c = i & 63; wcp[ed * 68 + c] = wcmp[i]; }
    for (int i = t; i < 2048;    i += NTHR) wes[i] = wexp[i];
    __syncthreads();

    const int p = t & 63;
    const int pxg = ((bz * OUT + oy) * OUT) + ox0 + p;
    const float* frow = &g_fea0[(size_t)pxg * 64];
    float4 rv = ld4(&g_rs[pxg * 4]);

    // ---- phase 6: comp[d] = sum_e r_e * (wc[e,d,:]·fea0). thread = (px, d-pair),
    //      streaming chunks, folded single-u64 accumulators ----
    {
        const int dg = t >> 6;           // d pair (2dg, 2dg+1)
        u64t acc[4][2];
        #pragma unroll
        for (int e = 0; e < 4; e++) { acc[e][0] = 0ull; acc[e][1] = 0ull; }
        #pragma unroll 4
        for (int c4 = 0; c4 < 16; c4++) {
            ulonglong2 Fv = ld2u(frow + c4 * 4);
            #pragma unroll
            for (int e = 0; e < 4; e++) {
                const float* w0 = &wcp[(e * 8 + 2 * dg) * 68 + c4 * 4];
                ulonglong2 wv0 = ld2u(w0);
                ulonglong2 wv1 = ld2u(w0 + 68);
                acc[e][0] = fma2(wv0.x, Fv.x, acc[e][0]);
                acc[e][0] = fma2(wv0.y, Fv.y, acc[e][0]);
                acc[e][1] = fma2(wv1.x, Fv.x, acc[e][1]);
                acc[e][1] = fma2(wv1.y, Fv.y, acc[e][1]);
            }
        }
        float comp0 = 0.0f, comp1 = 0.0f;
        #pragma unroll
        for (int e = 0; e < 4; e++) {
            float re = ((const float*)&rv)[e];
            comp0 = fmaf(re, hadd2(acc[e][0]), comp0);
            comp1 = fmaf(re, hadd2(acc[e][1]), comp1);
        }
        cmps[p * 12 + 2 * dg]     = comp0;
        cmps[p * 12 + 2 * dg + 1] = comp1;
    }
    __syncthreads();

    // ---- phase 7: expand + residual + store ----
    {
        const int cb = t >> 6;
        ulonglong2 cr0 = ld2u(&cmps[p * 12]);
        ulonglong2 cr1 = ld2u(&cmps[p * 12 + 4]);
        const int ox = ox0 + p;
        float* ob = out + (((size_t)bz * C + cb * 16) * OUT + oy) * OUT + ox;
        #pragma unroll 1
        for (int k4 = 0; k4 < 4; k4++) {
            float4 f4 = ld4(frow + cb * 16 + k4 * 4);
            #pragma unroll
            for (int kk = 0; kk < 4; kk++) {
                int c = cb * 16 + k4 * 4 + kk;
                float acc = ((const float*)&f4)[kk];
                #pragma unroll
                for (int e = 0; e < 4; e++) {
                    const float* werow = &wes[(e * 64 + c) * 8];
                    ulonglong2 wv = ld2u(werow);
                    ulonglong2 wv2 = ld2u(werow + 4);
                    u64t s2 = fma2(wv.x, cr0.x, 0ull);
                    s2 = fma2(wv.y, cr0.y, s2);
                    s2 = fma2(wv2.x, cr1.x, s2);
                    s2 = fma2(wv2.y, cr1.y, s2);
                    acc = fmaf(((const float*)&rv)[e], hadd2(s2), acc);
                }
                ob[(size_t)(k4 * 4 + kk) * OUT * OUT] = acc;
            }
        }
    }
}

extern "C" void kernel_launch(void* const* d_in, const int* in_sizes, int n_in,
                              void* d_out, int out_size) {
    (void)in_sizes; (void)n_in; (void)out_size;
    const float* x    = (const float*)d_in[0];
    const float* wcmp = (const float*)d_in[1];
    const float* wexp = (const float*)d_in[2];
    const float* w1   = (const float*)d_in[3];
    const float* b1   = (const float*)d_in[4];
    const float* w2   = (const float*)d_in[5];
    const float* b2   = (const float*)d_in[6];
    const float* wr   = (const float*)d_in[7];
    const float* br   = (const float*)d_in[8];
    const float* wo   = (const float*)d_in[9];
    const float* bo   = (const float*)d_in[10];
    float* out = (float*)d_out;

    cudaFuncSetAttribute(scab_k1, cudaFuncAttributeMaxDynamicSharedMemorySize, K1_BYTES);
    cudaFuncSetAttribute(scab_k3, cudaFuncAttributeMaxDynamicSharedMemorySize, K3_BYTES);

    dim3 grid(OUT / TILE, OUT, Bz);
    scab_k1<<<grid, NTHR, K1_BYTES>>>(x, w1, b1, w2, b2, wr, br, wo, bo);
    scab_k2<<<grid, NTHR>>>(x);
    scab_k3<<<grid, NTHR, K3_BYTES>>>(wcmp, wexp, out);
}

// round 7
// speedup vs baseline: 1.8268x; 1.3470x over previous
#include <cuda_runtime.h>
#include <cuda_bf16.h>
#include <math.h>

// Problem constants (fixed by setup_inputs)
#define Bz   2
#define C    64
#define H    128
#define W    128
#define OUT  256
#define TILE 64
#define NTHR 256
#define NPX  (Bz * OUT * OUT)

// ---------------- global scratch (static, allowed) ----------------
__device__ float g_rs  [NPX * 4];
__device__ float g_offs[NPX * 2];

// ---------------- K1 smem layout (floats) ----------------
#define K1_W1   0        // 64x68 = 4352
#define K1_W2   4352     // 64x68 = 4352
#define K1_WR   8704     // 4x68  = 272
#define K1_WO   8976     // 2x68  = 136
#define K1_B1   9112
#define K1_B2   9176
#define K1_BR   9240
#define K1_BO   9244
#define K1_INP  9248     // inps[p*76+i] 64x76 = 4864 (aliased embs[p*68+i])
#define K1_HID  14112    // hidden[p*68+c] 64x68 = 4352
#define K1_FLOATS 18464
#define K1_BYTES (K1_FLOATS * 4)

// ---------------- K23 smem layout (floats) ----------------
#define K2_WC   0        // wcp[(e*8+d)*68+c] 32x68 = 2176
#define K2_WE   2176     // wes[(e*64+c)*8+d] = 2048
#define K2_FEA  4224     // fea[p*68+c] 64x68 = 4352
#define K2_CMP  8576     // cmps[p*12+d] = 768
#define K2_FLOATS 9344
#define K2_BYTES (K2_FLOATS * 4)

#define INP_S 76
#define EMB_S 68
#define FEA_S 68

typedef unsigned long long u64t;

__device__ __forceinline__ u64t fma2(u64t a, u64t b, u64t c) {
    u64t d;
    asm("fma.rn.f32x2 %0, %1, %2, %3;" : "=l"(d) : "l"(a), "l"(b), "l"(c));
    return d;
}
__device__ __forceinline__ float hadd2(u64t v) {
    float lo, hi;
    asm("mov.b64 {%0, %1}, %2;" : "=f"(lo), "=f"(hi) : "l"(v));
    return lo + hi;
}
__device__ __forceinline__ float4 ld4(const float* p) {
    return *reinterpret_cast<const float4*>(p);
}
__device__ __forceinline__ ulonglong2 ld2u(const float* p) {
    return *reinterpret_cast<const ulonglong2*>(p);
}

__device__ __forceinline__ float bilin(const float* __restrict__ img, float fx, float fy) {
    float x0f = floorf(fx), y0f = floorf(fy);
    float wx1 = fx - x0f, wy1 = fy - y0f;
    float wx0 = 1.0f - wx1, wy0 = 1.0f - wy1;
    int x0 = (int)x0f, y0 = (int)y0f;
    int xi0 = min(max(x0, 0), W - 1), yi0 = min(max(y0, 0), H - 1);
    int xi1 = min(max(x0 + 1, 0), W - 1), yi1 = min(max(y0 + 1, 0), H - 1);
    bool vx0 = (x0f >= 0.0f) && (x0f <= (float)(W - 1));
    bool vx1 = (x0f >= -1.0f) && (x0f <= (float)(W - 2));
    bool vy0 = (y0f >= 0.0f) && (y0f <= (float)(H - 1));
    bool vy1 = (y0f >= -1.0f) && (y0f <= (float)(H - 2));
    float v00 = (vx0 && vy0) ? __ldg(img + yi0 * W + xi0) : 0.0f;
    float v10 = (vx1 && vy0) ? __ldg(img + yi0 * W + xi1) : 0.0f;
    float v01 = (vx0 && vy1) ? __ldg(img + yi1 * W + xi0) : 0.0f;
    float v11 = (vx1 && vy1) ? __ldg(img + yi1 * W + xi1) : 0.0f;
    return v00 * (wx0 * wy0) + v10 * (wx1 * wy0) + v01 * (wx0 * wy1) + v11 * (wx1 * wy1);
}

// =================== K1: phases 1-4 (coords, sample1, MLP, heads) ===================
__global__ __launch_bounds__(NTHR, 3)
void scab_k1(const float* __restrict__ x,
             const float* __restrict__ w1, const float* __restrict__ b1,
             const float* __restrict__ w2, const float* __restrict__ b2,
             const float* __restrict__ wr, const float* __restrict__ br,
             const float* __restrict__ wo, const float* __restrict__ bo)
{
    extern __shared__ float sm[];
    float* w1s  = sm + K1_W1;
    float* w2s  = sm + K1_W2;
    float* wrs  = sm + K1_WR;
    float* wos  = sm + K1_WO;
    float* b1s  = sm + K1_B1;
    float* b2s  = sm + K1_B2;
    float* brs  = sm + K1_BR;
    float* bos  = sm + K1_BO;
    float* inps = sm + K1_INP;   // aliased embs after phase 3
    float* embs = sm + K1_INP;
    float* hidf = sm + K1_HID;

    const int t  = threadIdx.x;
    const int oy = blockIdx.y;
    const int bz = blockIdx.z;
    const int ox0 = blockIdx.x * TILE;

    for (int i = t; i < 64 * 68; i += NTHR) w1s[i] = w1[i];
    for (int i = t; i < 64 * 64; i += NTHR) { int c = i >> 6, k = i & 63; w2s[c * 68 + k] = w2[i]; }
    if (t < 256) { int e = t >> 6, k = t & 63; wrs[e * 68 + k] = wr[t]; }
    if (t < 128) { int o = t >> 6, k = t & 63; wos[o * 68 + k] = wo[t]; }
    if (t < 64) { b1s[t] = b1[t]; b2s[t] = b2[t]; }
    if (t < 4) brs[t] = br[t];
    if (t < 2) bos[t] = bo[t];
    __syncthreads();

    const float inv127 = 2.0f / 127.0f;

    // ---- phase 1: coords + pre_fea sample -> inps ----
    {
        const int p  = t & 63;
        const int cb = t >> 6;
        const int ox = ox0 + p;
        float gx = ((ox + 0.5f) / 2.0f - 0.5f) * inv127 - 1.0f;
        float gy = ((oy + 0.5f) / 2.0f - 0.5f) * inv127 - 1.0f;
        float fx = ((gx + 1.0f) * (float)W - 1.0f) * 0.5f;
        float fy = ((gy + 1.0f) * (float)H - 1.0f) * 0.5f;
        if (cb == 0) {
            float ah = (oy + 0.5f) / 2.0f;
            float aw = (ox + 0.5f) / 2.0f;
            *reinterpret_cast<float4*>(&inps[p * INP_S]) =
                make_float4(0.5f, 0.5f,
                            ah - floorf(ah + 0.001f) - 0.5f,
                            aw - floorf(aw + 0.001f) - 0.5f);
        }
        const float* xb = x + (size_t)bz * C * H * W;
        #pragma unroll 4
        for (int k = 0; k < 16; k++) {
            int c = cb * 16 + k;
            inps[p * INP_S + 4 + c] = bilin(xb + c * (H * W), fx, fy);
        }
    }
    __syncthreads();

    // ---- phase 2: layer1 (68 -> 64), relu. K-split halves, 16 packed partials ----
    {
        const int p = t & 63, g = t >> 6;
        const float* wbase = w1s + g * 16 * 68;
        u64t acc[16];
        #pragma unroll
        for (int c = 0; c < 16; c++) acc[c] = 0ull;
        {   // half 0: K floats 0..35
            ulonglong2 A[9];
            #pragma unroll
            for (int i = 0; i < 9; i++) A[i] = ld2u(&inps[p * INP_S + i * 4]);
            #pragma unroll
            for (int c = 0; c < 16; c++) {
                const float* wrow = wbase + c * 68;
                #pragma unroll
                for (int i = 0; i < 9; i++) {
                    ulonglong2 wv = ld2u(wrow + i * 4);
                    acc[c] = fma2(wv.x, A[i].x, acc[c]);
                    acc[c] = fma2(wv.y, A[i].y, acc[c]);
                }
            }
        }
        {   // half 1: K floats 36..67
            ulonglong2 A[8];
            #pragma unroll
            for (int i = 0; i < 8; i++) A[i] = ld2u(&inps[p * INP_S + 36 + i * 4]);
            #pragma unroll
            for (int c = 0; c < 16; c++) {
                const float* wrow = wbase + c * 68 + 36;
                #pragma unroll
                for (int i = 0; i < 8; i++) {
                    ulonglong2 wv = ld2u(wrow + i * 4);
                    acc[c] = fma2(wv.x, A[i].x, acc[c]);
                    acc[c] = fma2(wv.y, A[i].y, acc[c]);
                }
            }
        }
        const float* bb = b1s + g * 16;
        float* hrow = &hidf[p * 68 + g * 16];
        #pragma unroll
        for (int cc = 0; cc < 4; cc++) {
            float4 o4;
            #pragma unroll
            for (int k = 0; k < 4; k++)
                ((float*)&o4)[k] = fmaxf(hadd2(acc[cc * 4 + k]) + bb[cc * 4 + k], 0.0f);
            *reinterpret_cast<float4*>(hrow + cc * 4) = o4;
        }
    }
    __syncthreads();

    // ---- phase 3: layer2 (64 -> 64), relu -> embs (aliases inps) ----
    {
        const int p = t & 63, g = t >> 6;
        const float* wbase = w2s + g * 16 * 68;
        u64t acc[16];
        #pragma unroll
        for (int c = 0; c < 16; c++) acc[c] = 0ull;
        #pragma unroll 1
        for (int h = 0; h < 2; h++) {
            ulonglong2 A[8];
            #pragma unroll
            for (int i = 0; i < 8; i++) A[i] = ld2u(&hidf[p * 68 + h * 32 + i * 4]);
            #pragma unroll
            for (int c = 0; c < 16; c++) {
                const float* wrow = wbase + c * 68 + h * 32;
                #pragma unroll
                for (int i = 0; i < 8; i++) {
                    ulonglong2 wv = ld2u(wrow + i * 4);
                    acc[c] = fma2(wv.x, A[i].x, acc[c]);
                    acc[c] = fma2(wv.y, A[i].y, acc[c]);
                }
            }
        }
        const float* bb = b2s + g * 16;
        float erow[16];
        #pragma unroll
        for (int c = 0; c < 16; c++)
            erow[c] = fmaxf(hadd2(acc[c]) + bb[c], 0.0f);
        __syncthreads();   // all hidf reads done before embs (aliases inps) overwrite? embs!=hidf; sync for inps alias safety of phase-2 readers
        float* ebase = &embs[p * EMB_S + (t >> 6) * 16];
        #pragma unroll
        for (int cc = 0; cc < 4; cc++)
            *reinterpret_cast<float4*>(ebase + cc * 4) =
                *reinterpret_cast<const float4*>(&erow[cc * 4]);
    }
    __syncthreads();

    // ---- phase 4: r (sigmoid) + offsets -> global ----
    {
        const int p = t >> 2, e = t & 3;
        const float* erow = &embs[p * EMB_S];
        const float* wrr = wrs + e * 68;
        const float* wor = wos + (e & 1) * 68;
        u64t r0 = 0ull, r1 = 0ull, o0 = 0ull, o1 = 0ull;
        #pragma unroll
        for (int i = 0; i < 16; i++) {
            ulonglong2 ev  = ld2u(erow + i * 4);
            ulonglong2 wrv = ld2u(wrr + i * 4);
            ulonglong2 wov = ld2u(wor + i * 4);
            r0 = fma2(wrv.x, ev.x, r0);
            r1 = fma2(wrv.y, ev.y, r1);
            o0 = fma2(wov.x, ev.x, o0);
            o1 = fma2(wov.y, ev.y, o1);
        }
        float accR = hadd2(r0) + hadd2(r1) + brs[e];
        const int pxg = ((bz * OUT + oy) * OUT) + ox0 + p;
        g_rs[pxg * 4 + e] = 1.0f / (1.0f + __expf(-accR));
        if (e < 2) g_offs[pxg * 2 + e] = hadd2(o0) + hadd2(o1) + bos[e];
    }
}

// =================== K23: phases 5-7 fused (sample2, compress, expand, store) ===================
__global__ __launch_bounds__(NTHR, 3)
void scab_k23(const float* __restrict__ x,
              const float* __restrict__ wcmp,
              const float* __restrict__ wexp,
              float* __restrict__ out)
{
    extern __shared__ float sm[];
    float* wcp  = sm + K2_WC;
    float* wes  = sm + K2_WE;
    float* fea  = sm + K2_FEA;
    float* cmps = sm + K2_CMP;

    const int t  = threadIdx.x;
    const int oy = blockIdx.y;
    const int bz = blockIdx.z;
    const int ox0 = blockIdx.x * TILE;

    for (int i = t; i < 32 * 64; i += NTHR) { int ed = i >> 6, c = i & 63; wcp[ed * 68 + c] = wcmp[i]; }
    for (int i = t; i < 2048;    i += NTHR) wes[i] = wexp[i];

    const int p  = t & 63;
    const int cb = t >> 6;
    const int ox = ox0 + p;
    const int pxg = ((bz * OUT + oy) * OUT) + ox;

    // ---- phase 5: offset sample -> smem fea[p*68+c] ----
    {
        const float inv127 = 2.0f / 127.0f;
        float gx = ((ox + 0.5f) / 2.0f - 0.5f) * inv127 - 1.0f;
        float gy = ((oy + 0.5f) / 2.0f - 0.5f) * inv127 - 1.0f;
        float ix = gx + g_offs[pxg * 2 + 0] * inv127;
        float iy = gy + g_offs[pxg * 2 + 1] * inv127;
        float fx = ((ix + 1.0f) * (float)W - 1.0f) * 0.5f;
        float fy = ((iy + 1.0f) * (float)H - 1.0f) * 0.5f;
        const float* xb = x + (size_t)bz * C * H * W;
        #pragma unroll 4
        for (int k = 0; k < 16; k++) {
            int c = cb * 16 + k;
            fea[p * FEA_S + c] = bilin(xb + c * (H * W), fx, fy);
        }
    }
    __syncthreads();

    const float* frow = &fea[p * FEA_S];
    float4 rv = ld4(&g_rs[pxg * 4]);

    // ---- phase 6: comp[d] = sum_e r_e * (wc[e,d,:]·fea0). thread = (px, d-pair) ----
    {
        const int dg = t >> 6;           // d pair (2dg, 2dg+1)
        u64t acc[4][2];
        #pragma unroll
        for (int e = 0; e < 4; e++) { acc[e][0] = 0ull; acc[e][1] = 0ull; }
        #pragma unroll 4
        for (int c4 = 0; c4 < 16; c4++) {
            ulonglong2 Fv = ld2u(frow + c4 * 4);
            #pragma unroll
            for (int e = 0; e < 4; e++) {
                const float* w0 = &wcp[(e * 8 + 2 * dg) * 68 + c4 * 4];
                ulonglong2 wv0 = ld2u(w0);
                ulonglong2 wv1 = ld2u(w0 + 68);
                acc[e][0] = fma2(wv0.x, Fv.x, acc[e][0]);
                acc[e][0] = fma2(wv0.y, Fv.y, acc[e][0]);
                acc[e][1] = fma2(wv1.x, Fv.x, acc[e][1]);
                acc[e][1] = fma2(wv1.y, Fv.y, acc[e][1]);
            }
        }
        float comp0 = 0.0f, comp1 = 0.0f;
        #pragma unroll
        for (int e = 0; e < 4; e++) {
            float re = ((const float*)&rv)[e];
            comp0 = fmaf(re, hadd2(acc[e][0]), comp0);
            comp1 = fmaf(re, hadd2(acc[e][1]), comp1);
        }
        cmps[p * 12 + 2 * dg]     = comp0;
        cmps[p * 12 + 2 * dg + 1] = comp1;
    }
    __syncthreads();

    // ---- phase 7: expand + residual + store ----
    {
        ulonglong2 cr0 = ld2u(&cmps[p * 12]);
        ulonglong2 cr1 = ld2u(&cmps[p * 12 + 4]);
        float* ob = out + (((size_t)bz * C + cb * 16) * OUT + oy) * OUT + ox;
        #pragma unroll 1
        for (int k4 = 0; k4 < 4; k4++) {
            float4 f4 = ld4(frow + cb * 16 + k4 * 4);
            #pragma unroll
            for (int kk = 0; kk < 4; kk++) {
                int c = cb * 16 + k4 * 4 + kk;
                float acc = ((const float*)&f4)[kk];
                #pragma unroll
                for (int e = 0; e < 4; e++) {
                    const float* werow = &wes[(e * 64 + c) * 8];
                    ulonglong2 wv = ld2u(werow);
                    ulonglong2 wv2 = ld2u(werow + 4);
                    u64t s2 = fma2(wv.x, cr0.x, 0ull);
                    s2 = fma2(wv.y, cr0.y, s2);
                    s2 = fma2(wv2.x, cr1.x, s2);
                    s2 = fma2(wv2.y, cr1.y, s2);
                    acc = fmaf(((const float*)&rv)[e], hadd2(s2), acc);
                }
                ob[(size_t)(k4 * 4 + kk) * OUT * OUT] = acc;
            }
        }
    }
}

extern "C" void kernel_launch(void* const* d_in, const int* in_sizes, int n_in,
                              void* d_out, int out_size) {
    (void)in_sizes; (void)n_in; (void)out_size;
    const float* x    = (const float*)d_in[0];
    const float* wcmp = (const float*)d_in[1];
    const float* wexp = (const float*)d_in[2];
    const float* w1   = (const float*)d_in[3];
    const float* b1   = (const float*)d_in[4];
    const float* w2   = (const float*)d_in[5];
    const float* b2   = (const float*)d_in[6];
    const float* wr   = (const float*)d_in[7];
    const float* br   = (const float*)d_in[8];
    const float* wo   = (const float*)d_in[9];
    const float* bo   = (const float*)d_in[10];
    float* out = (float*)d_out;

    cudaFuncSetAttribute(scab_k1,  cudaFuncAttributeMaxDynamicSharedMemorySize, K1_BYTES);
    cudaFuncSetAttribute(scab_k23, cudaFuncAttributeMaxDynamicSharedMemorySize, K2_BYTES);

    dim3 grid(OUT / TILE, OUT, Bz);
    scab_k1<<<grid, NTHR, K1_BYTES>>>(x, w1, b1, w2, b2, wr, br, wo, bo);
    scab_k23<<<grid, NTHR, K2_BYTES>>>(x, wcmp, wexp, out);
}

// round 8
// speedup vs baseline: 1.8523x; 1.0139x over previous
#include <cuda_runtime.h>
#include <cuda_bf16.h>
#include <math.h>

// Problem constants (fixed by setup_inputs)
#define Bz   2
#define C    64
#define H    128
#define W    128
#define OUT  256
#define TILE 64
#define NTHR 256
#define NPX  (Bz * OUT * OUT)

// ---------------- global scratch (static, allowed) ----------------
__device__ float g_rs  [NPX * 4];
__device__ float g_offs[NPX * 2];

// ---------------- K1 smem layout (floats) ----------------
#define K1_W1   0        // 64x68 = 4352
#define K1_W2   4352     // 64x68 = 4352
#define K1_WR   8704     // 4x68  = 272
#define K1_WO   8976     // 2x68  = 136
#define K1_B1   9112
#define K1_B2   9176
#define K1_BR   9240
#define K1_BO   9244
#define K1_INP  9248     // inps[p*76+i] 64x76 = 4864 (aliased embs[p*68+i])
#define K1_HID  14112    // staging strip 64x34 / hidden[p*68+c] 64x68 = 4352
#define K1_FLOATS 18464
#define K1_BYTES (K1_FLOATS * 4)

// ---------------- K23 smem layout (floats) ----------------
#define K2_WC   0        // wcp[(e*8+d)*68+c] 32x68 = 2176
#define K2_WE   2176     // wes[(e*64+c)*8+d] = 2048
#define K2_FEA  4224     // fea[p*68+c] 64x68 = 4352
#define K2_CMP  8576     // cmps[p*12+d] = 768
#define K2_FLOATS 9344
#define K2_BYTES (K2_FLOATS * 4)

#define INP_S 76
#define EMB_S 68
#define FEA_S 68

typedef unsigned long long u64t;

__device__ __forceinline__ u64t fma2(u64t a, u64t b, u64t c) {
    u64t d;
    asm("fma.rn.f32x2 %0, %1, %2, %3;" : "=l"(d) : "l"(a), "l"(b), "l"(c));
    return d;
}
__device__ __forceinline__ float hadd2(u64t v) {
    float lo, hi;
    asm("mov.b64 {%0, %1}, %2;" : "=f"(lo), "=f"(hi) : "l"(v));
    return lo + hi;
}
__device__ __forceinline__ float4 ld4(const float* p) {
    return *reinterpret_cast<const float4*>(p);
}
__device__ __forceinline__ ulonglong2 ld2u(const float* p) {
    return *reinterpret_cast<const ulonglong2*>(p);
}

__device__ __forceinline__ float bilin(const float* __restrict__ img, float fx, float fy) {
    float x0f = floorf(fx), y0f = floorf(fy);
    float wx1 = fx - x0f, wy1 = fy - y0f;
    float wx0 = 1.0f - wx1, wy0 = 1.0f - wy1;
    int x0 = (int)x0f, y0 = (int)y0f;
    int xi0 = min(max(x0, 0), W - 1), yi0 = min(max(y0, 0), H - 1);
    int xi1 = min(max(x0 + 1, 0), W - 1), yi1 = min(max(y0 + 1, 0), H - 1);
    bool vx0 = (x0f >= 0.0f) && (x0f <= (float)(W - 1));
    bool vx1 = (x0f >= -1.0f) && (x0f <= (float)(W - 2));
    bool vy0 = (y0f >= 0.0f) && (y0f <= (float)(H - 1));
    bool vy1 = (y0f >= -1.0f) && (y0f <= (float)(H - 2));
    float v00 = (vx0 && vy0) ? __ldg(img + yi0 * W + xi0) : 0.0f;
    float v10 = (vx1 && vy0) ? __ldg(img + yi0 * W + xi1) : 0.0f;
    float v01 = (vx0 && vy1) ? __ldg(img + yi1 * W + xi0) : 0.0f;
    float v11 = (vx1 && vy1) ? __ldg(img + yi1 * W + xi1) : 0.0f;
    return v00 * (wx0 * wy0) + v10 * (wx1 * wy0) + v01 * (wx0 * wy1) + v11 * (wx1 * wy1);
}

// =================== K1: phases 1-4 (coords, sample1, MLP, heads) ===================
__global__ __launch_bounds__(NTHR, 3)
void scab_k1(const float* __restrict__ x,
             const float* __restrict__ w1, const float* __restrict__ b1,
             const float* __restrict__ w2, const float* __restrict__ b2,
             const float* __restrict__ wr, const float* __restrict__ br,
             const float* __restrict__ wo, const float* __restrict__ bo)
{
    extern __shared__ float sm[];
    float* w1s  = sm + K1_W1;
    float* w2s  = sm + K1_W2;
    float* wrs  = sm + K1_WR;
    float* wos  = sm + K1_WO;
    float* b1s  = sm + K1_B1;
    float* b2s  = sm + K1_B2;
    float* brs  = sm + K1_BR;
    float* bos  = sm + K1_BO;
    float* inps = sm + K1_INP;   // aliased embs after phase 3
    float* embs = sm + K1_INP;
    float* hidf = sm + K1_HID;   // staging strip (phase 1) then hidden

    const int t  = threadIdx.x;
    const int oy = blockIdx.y;
    const int bz = blockIdx.z;
    const int ox0 = blockIdx.x * TILE;

    for (int i = t; i < 64 * 68; i += NTHR) w1s[i] = w1[i];
    for (int i = t; i < 64 * 64; i += NTHR) { int c = i >> 6, k = i & 63; w2s[c * 68 + k] = w2[i]; }
    if (t < 256) { int e = t >> 6, k = t & 63; wrs[e * 68 + k] = wr[t]; }
    if (t < 128) { int o = t >> 6, k = t & 63; wos[o * 68 + k] = wo[t]; }
    if (t < 64) { b1s[t] = b1[t]; b2s[t] = b2[t]; }
    if (t < 4) brs[t] = br[t];
    if (t < 2) bos[t] = bo[t];
    __syncthreads();

    const float inv127 = 2.0f / 127.0f;

    // ---- phase 1a: stage + vertical lerp of the 2 source rows into hidf[c*34+j] ----
    // fy is block-constant (one output row); x footprint of this block is 34 columns.
    float gx_blk = ((ox0 + 0.5f) / 2.0f - 0.5f) * inv127 - 1.0f;
    float fx_blk = ((gx_blk + 1.0f) * (float)W - 1.0f) * 0.5f;
    const int m_blk = (int)floorf(fx_blk);
    {
        float gy = ((oy + 0.5f) / 2.0f - 0.5f) * inv127 - 1.0f;
        float fy = ((gy + 1.0f) * (float)H - 1.0f) * 0.5f;
        float y0f = floorf(fy);
        float wy1 = fy - y0f, wy0 = 1.0f - wy1;
        int y0 = (int)y0f;
        bool vy0 = (y0 >= 0) && (y0 <= H - 1);
        bool vy1 = (y0 >= -1) && (y0 <= H - 2);
        int yi0 = min(max(y0, 0), H - 1);
        int yi1 = min(max(y0 + 1, 0), H - 1);
        const float* xb = x + (size_t)bz * C * H * W;
        #pragma unroll 1
        for (int i = t; i < 64 * 34; i += NTHR) {
            int c = i / 34, j = i - c * 34;
            int xs = m_blk + j;
            bool vx = (xs >= 0) && (xs <= W - 1);
            int xc = min(max(xs, 0), W - 1);
            const float* base = xb + c * (H * W);
            float v0 = (vx && vy0) ? __ldg(base + yi0 * W + xc) : 0.0f;
            float v1 = (vx && vy1) ? __ldg(base + yi1 * W + xc) : 0.0f;
            hidf[c * 34 + j] = v0 * wy0 + v1 * wy1;
        }
    }
    __syncthreads();

    // ---- phase 1b: horizontal lerp + coords -> inps (stride 76) ----
    {
        const int p  = t & 63;
        const int cb = t >> 6;
        const int ox = ox0 + p;
        float gx = ((ox + 0.5f) / 2.0f - 0.5f) * inv127 - 1.0f;
        float fx = ((gx + 1.0f) * (float)W - 1.0f) * 0.5f;
        float x0f = floorf(fx);
        float wx1 = fx - x0f, wx0 = 1.0f - wx1;
        int j0 = (int)x0f - m_blk;   // in [0, 32]
        if (cb == 0) {
            float ah = (oy + 0.5f) / 2.0f;
            float aw = (ox + 0.5f) / 2.0f;
            *reinterpret_cast<float4*>(&inps[p * INP_S]) =
                make_float4(0.5f, 0.5f,
                            ah - floorf(ah + 0.001f) - 0.5f,
                            aw - floorf(aw + 0.001f) - 0.5f);
        }
        #pragma unroll 1
        for (int k4 = 0; k4 < 4; k4++) {
            float4 v;
            #pragma unroll
            for (int kk = 0; kk < 4; kk++) {
                int c = cb * 16 + k4 * 4 + kk;
                float tL = hidf[c * 34 + j0];
                float tR = hidf[c * 34 + j0 + 1];
                ((float*)&v)[kk] = tL * wx0 + tR * wx1;
            }
            *reinterpret_cast<float4*>(&inps[p * INP_S + 4 + cb * 16 + k4 * 4]) = v;
        }
    }
    __syncthreads();

    // ---- phase 2: layer1 (68 -> 64), relu. K-split halves, 16 packed partials ----
    {
        const int p = t & 63, g = t >> 6;
        const float* wbase = w1s + g * 16 * 68;
        u64t acc[16];
        #pragma unroll
        for (int c = 0; c < 16; c++) acc[c] = 0ull;
        {   // half 0: K floats 0..35
            ulonglong2 A[9];
            #pragma unroll
            for (int i = 0; i < 9; i++) A[i] = ld2u(&inps[p * INP_S + i * 4]);
            #pragma unroll
            for (int c = 0; c < 16; c++) {
                const float* wrow = wbase + c * 68;
                #pragma unroll
                for (int i = 0; i < 9; i++) {
                    ulonglong2 wv = ld2u(wrow + i * 4);
                    acc[c] = fma2(wv.x, A[i].x, acc[c]);
                    acc[c] = fma2(wv.y, A[i].y, acc[c]);
                }
            }
        }
        {   // half 1: K floats 36..67
            ulonglong2 A[8];
            #pragma unroll
            for (int i = 0; i < 8; i++) A[i] = ld2u(&inps[p * INP_S + 36 + i * 4]);
            #pragma unroll
            for (int c = 0; c < 16; c++) {
                const float* wrow = wbase + c * 68 + 36;
                #pragma unroll
                for (int i = 0; i < 8; i++) {
                    ulonglong2 wv = ld2u(wrow + i * 4);
                    acc[c] = fma2(wv.x, A[i].x, acc[c]);
                    acc[c] = fma2(wv.y, A[i].y, acc[c]);
                }
            }
        }
        const float* bb = b1s + g * 16;
        float* hrow = &hidf[p * 68 + g * 16];
        __syncthreads();   // staging strip fully consumed before hidden overwrites
        #pragma unroll
        for (int cc = 0; cc < 4; cc++) {
            float4 o4;
            #pragma unroll
            for (int k = 0; k < 4; k++)
                ((float*)&o4)[k] = fmaxf(hadd2(acc[cc * 4 + k]) + bb[cc * 4 + k], 0.0f);
            *reinterpret_cast<float4*>(hrow + cc * 4) = o4;
        }
    }
    __syncthreads();

    // ---- phase 3: layer2 (64 -> 64), relu -> embs (aliases inps) ----
    {
        const int p = t & 63, g = t >> 6;
        const float* wbase = w2s + g * 16 * 68;
        u64t acc[16];
        #pragma unroll
        for (int c = 0; c < 16; c++) acc[c] = 0ull;
        #pragma unroll 1
        for (int h = 0; h < 2; h++) {
            ulonglong2 A[8];
            #pragma unroll
            for (int i = 0; i < 8; i++) A[i] = ld2u(&hidf[p * 68 + h * 32 + i * 4]);
            #pragma unroll
            for (int c = 0; c < 16; c++) {
                const float* wrow = wbase + c * 68 + h * 32;
                #pragma unroll
                for (int i = 0; i < 8; i++) {
                    ulonglong2 wv = ld2u(wrow + i * 4);
                    acc[c] = fma2(wv.x, A[i].x, acc[c]);
                    acc[c] = fma2(wv.y, A[i].y, acc[c]);
                }
            }
        }
        const float* bb = b2s + g * 16;
        float erow[16];
        #pragma unroll
        for (int c = 0; c < 16; c++)
            erow[c] = fmaxf(hadd2(acc[c]) + bb[c], 0.0f);
        __syncthreads();   // inps readers (phase 2) done before embs overwrite
        float* ebase = &embs[p * EMB_S + (t >> 6) * 16];
        #pragma unroll
        for (int cc = 0; cc < 4; cc++)
            *reinterpret_cast<float4*>(ebase + cc * 4) =
                *reinterpret_cast<const float4*>(&erow[cc * 4]);
    }
    __syncthreads();

    // ---- phase 4: r (sigmoid) + offsets -> global ----
    {
        const int p = t >> 2, e = t & 3;
        const float* erow = &embs[p * EMB_S];
        const float* wrr = wrs + e * 68;
        const float* wor = wos + (e & 1) * 68;
        u64t r0 = 0ull, r1 = 0ull, o0 = 0ull, o1 = 0ull;
        #pragma unroll
        for (int i = 0; i < 16; i++) {
            ulonglong2 ev  = ld2u(erow + i * 4);
            ulonglong2 wrv = ld2u(wrr + i * 4);
            ulonglong2 wov = ld2u(wor + i * 4);
            r0 = fma2(wrv.x, ev.x, r0);
            r1 = fma2(wrv.y, ev.y, r1);
            o0 = fma2(wov.x, ev.x, o0);
            o1 = fma2(wov.y, ev.y, o1);
        }
        float accR = hadd2(r0) + hadd2(r1) + brs[e];
        const int pxg = ((bz * OUT + oy) * OUT) + ox0 + p;
        g_rs[pxg * 4 + e] = 1.0f / (1.0f + __expf(-accR));
        if (e < 2) g_offs[pxg * 2 + e] = hadd2(o0) + hadd2(o1) + bos[e];
    }
}

// =================== K23: phases 5-7 fused (sample2, compress, expand, store) ===================
__global__ __launch_bounds__(NTHR, 3)
void scab_k23(const float* __restrict__ x,
              const float* __restrict__ wcmp,
              const float* __restrict__ wexp,
              float* __restrict__ out)
{
    extern __shared__ float sm[];
    float* wcp  = sm + K2_WC;
    float* wes  = sm + K2_WE;
    float* fea  = sm + K2_FEA;
    float* cmps = sm + K2_CMP;

    const int t  = threadIdx.x;
    const int oy = blockIdx.y;
    const int bz = blockIdx.z;
    const int ox0 = blockIdx.x * TILE;
    const int wid  = t >> 5;
    const int lane = t & 31;

    for (int i = t; i < 32 * 64; i += NTHR) { int ed = i >> 6, c = i & 63; wcp[ed * 68 + c] = wcmp[i]; }
    for (int i = t; i < 2048;    i += NTHR) wes[i] = wexp[i];

    const int p  = t & 63;
    const int cb = t >> 6;
    const int ox = ox0 + p;
    const int pxg = ((bz * OUT + oy) * OUT) + ox;

    // ---- phase 5: offset sample -> smem fea[p*68+c], vectorized stores ----
    {
        const float inv127 = 2.0f / 127.0f;
        float gx = ((ox + 0.5f) / 2.0f - 0.5f) * inv127 - 1.0f;
        float gy = ((oy + 0.5f) / 2.0f - 0.5f) * inv127 - 1.0f;
        float ix = gx + g_offs[pxg * 2 + 0] * inv127;
        float iy = gy + g_offs[pxg * 2 + 1] * inv127;
        float fx = ((ix + 1.0f) * (float)W - 1.0f) * 0.5f;
        float fy = ((iy + 1.0f) * (float)H - 1.0f) * 0.5f;
        const float* xb = x + (size_t)bz * C * H * W;
        #pragma unroll 1
        for (int k4 = 0; k4 < 4; k4++) {
            float4 v;
            #pragma unroll
            for (int kk = 0; kk < 4; kk++) {
                int c = cb * 16 + k4 * 4 + kk;
                ((float*)&v)[kk] = bilin(xb + c * (H * W), fx, fy);
            }
            *reinterpret_cast<float4*>(&fea[p * FEA_S + cb * 16 + k4 * 4]) = v;
        }
    }
    __syncthreads();

    // ---- phase 6: comp[d] = sum_e r_e * (wc[e,d,:]·fea0). thread = (px, d-pair) ----
    {
        const float* frow = &fea[p * FEA_S];
        float4 rv = ld4(&g_rs[pxg * 4]);
        const int dg = t >> 6;           // d pair (2dg, 2dg+1)
        u64t acc[4][2];
        #pragma unroll
        for (int e = 0; e < 4; e++) { acc[e][0] = 0ull; acc[e][1] = 0ull; }
        #pragma unroll 4
        for (int c4 = 0; c4 < 16; c4++) {
            ulonglong2 Fv = ld2u(frow + c4 * 4);
            #pragma unroll
            for (int e = 0; e < 4; e++) {
                const float* w0 = &wcp[(e * 8 + 2 * dg) * 68 + c4 * 4];
                ulonglong2 wv0 = ld2u(w0);
                ulonglong2 wv1 = ld2u(w0 + 68);
                acc[e][0] = fma2(wv0.x, Fv.x, acc[e][0]);
                acc[e][0] = fma2(wv0.y, Fv.y, acc[e][0]);
                acc[e][1] = fma2(wv1.x, Fv.x, acc[e][1]);
                acc[e][1] = fma2(wv1.y, Fv.y, acc[e][1]);
            }
        }
        float comp0 = 0.0f, comp1 = 0.0f;
        #pragma unroll
        for (int e = 0; e < 4; e++) {
            float re = ((const float*)&rv)[e];
            comp0 = fmaf(re, hadd2(acc[e][0]), comp0);
            comp1 = fmaf(re, hadd2(acc[e][1]), comp1);
        }
        cmps[p * 12 + 2 * dg]     = comp0;
        cmps[p * 12 + 2 * dg + 1] = comp1;
    }
    __syncthreads();

    // ---- phase 7: expand + residual + store. warp = 8-channel group,
    //      lane carries BOTH px halves so each wexp row is broadcast once ----
    {
        const int g = wid;
        const int p0 = lane, p1 = lane + 32;
        const int px0 = ((bz * OUT + oy) * OUT) + ox0 + p0;
        const int px1 = px0 + 32;
        ulonglong2 cA0 = ld2u(&cmps[p0 * 12]);
        ulonglong2 cB0 = ld2u(&cmps[p0 * 12 + 4]);
        ulonglong2 cA1 = ld2u(&cmps[p1 * 12]);
        ulonglong2 cB1 = ld2u(&cmps[p1 * 12 + 4]);
        float4 rv0 = ld4(&g_rs[px0 * 4]);
        float4 rv1 = ld4(&g_rs[px1 * 4]);
        float fe0[8], fe1[8];
        *reinterpret_cast<float4*>(&fe0[0]) = ld4(&fea[p0 * FEA_S + g * 8]);
        *reinterpret_cast<float4*>(&fe0[4]) = ld4(&fea[p0 * FEA_S + g * 8 + 4]);
        *reinterpret_cast<float4*>(&fe1[0]) = ld4(&fea[p1 * FEA_S + g * 8]);
        *reinterpret_cast<float4*>(&fe1[4]) = ld4(&fea[p1 * FEA_S + g * 8 + 4]);
        float* ob = out + (((size_t)bz * C + g * 8) * OUT + oy) * OUT + ox0 + p0;
        #pragma unroll
        for (int k = 0; k < 8; k++) {
            int c = g * 8 + k;
            float acc0 = fe0[k];
            float acc1 = fe1[k];
            #pragma unroll
            for (int e = 0; e < 4; e++) {
                const float* werow = &wes[(e * 64 + c) * 8];
                ulonglong2 wv  = ld2u(werow);
                ulonglong2 wv2 = ld2u(werow + 4);
                u64t s0 = fma2(wv.x, cA0.x, 0ull);
                s0 = fma2(wv.y, cA0.y, s0);
                s0 = fma2(wv2.x, cB0.x, s0);
                s0 = fma2(wv2.y, cB0.y, s0);
                u64t s1 = fma2(wv.x, cA1.x, 0ull);
                s1 = fma2(wv.y, cA1.y, s1);
                s1 = fma2(wv2.x, cB1.x, s1);
                s1 = fma2(wv2.y, cB1.y, s1);
                acc0 = fmaf(((const float*)&rv0)[e], hadd2(s0), acc0);
                acc1 = fmaf(((const float*)&rv1)[e], hadd2(s1), acc1);
            }
            ob[(size_t)k * OUT * OUT]      = acc0;
            ob[(size_t)k * OUT * OUT + 32] = acc1;
        }
    }
}

extern "C" void kernel_launch(void* const* d_in, const int* in_sizes, int n_in,
                              void* d_out, int out_size) {
    (void)in_sizes; (void)n_in; (void)out_size;
    const float* x    = (const float*)d_in[0];
    const float* wcmp = (const float*)d_in[1];
    const float* wexp = (const float*)d_in[2];
    const float* w1   = (const float*)d_in[3];
    const float* b1   = (const float*)d_in[4];
    const float* w2   = (const float*)d_in[5];
    const float* b2   = (const float*)d_in[6];
    const float* wr   = (const float*)d_in[7];
    const float* br   = (const float*)d_in[8];
    const float* wo   = (const float*)d_in[9];
    const float* bo   = (const float*)d_in[10];
    float* out = (float*)d_out;

    cudaFuncSetAttribute(scab_k1,  cudaFuncAttributeMaxDynamicSharedMemorySize, K1_BYTES);
    cudaFuncSetAttribute(scab_k23, cudaFuncAttributeMaxDynamicSharedMemorySize, K2_BYTES);

    dim3 grid(OUT / TILE, OUT, Bz);
    scab_k1<<<grid, NTHR, K1_BYTES>>>(x, w1, b1, w2, b2, wr, br, wo, bo);
    scab_k23<<<grid, NTHR, K2_BYTES>>>(x, wcmp, wexp, out);
}

// round 10
// speedup vs baseline: 2.3902x; 1.2904x over previous
#include <cuda_runtime.h>
#include <cuda_bf16.h>
#include <cstdint>
#include <math.h>

// Problem constants (fixed by setup_inputs)
#define Bz   2
#define C    64
#define H    128
#define W    128
#define OUT  256
#define TILE 64
#define NTHR 256
#define NPX  (Bz * OUT * OUT)

// ---------------- global scratch (static, allowed) ----------------
__device__ float g_rs  [NPX * 4];
__device__ float g_offs[NPX * 2];

// ================= K1 smem layout (bytes) =================
// EMB region: fp32 emb[64][68] = 17408; its first 8704B double as fp32 strip[64][34]
#define E_OFF    0
#define A1_OFF   17408   // bf16 acts [64 rows x 88 cols] = 11264 (cols 0..79 used, K-pad 68..79)
#define HID_OFF  28672   // bf16 hidden [64 rows x 72 cols] = 9216
#define W1P_OFF  37888   // uint32 w1 pairs [64][41] = 10496
#define W2P_OFF  48384   // uint32 w2 pairs [64][33] = 8448
#define WRS_OFF  56832   // fp32 wr [4][64] = 1024
#define WOS_OFF  57856   // fp32 wo [2][64] = 512
#define B1S_OFF  58368   // fp32 [64]
#define B2S_OFF  58624   // fp32 [64]
#define BRS_OFF  58880   // fp32 [4]
#define BOS_OFF  58896   // fp32 [2]
#define K1_SMEM  58912

// ================= K23 smem layout (floats) =================
#define K2_WC   0        // wcp[(e*8+d)*68+c] 32x68 = 2176
#define K2_WE   2176     // wes[(e*64+c)*8+d] = 2048
#define K2_FEA  4224     // fea[p*68+c] 64x68 = 4352
#define K2_CMP  8576     // cmps[p*12+d] = 768
#define K2_FLOATS 9344
#define K2_BYTES (K2_FLOATS * 4)
#define FEA_S 68

typedef unsigned long long u64t;

__device__ __forceinline__ u64t fma2(u64t a, u64t b, u64t c) {
    u64t d; asm("fma.rn.f32x2 %0, %1, %2, %3;" : "=l"(d) : "l"(a), "l"(b), "l"(c)); return d;
}
__device__ __forceinline__ float hadd2(u64t v) {
    float lo, hi; asm("mov.b64 {%0, %1}, %2;" : "=f"(lo), "=f"(hi) : "l"(v)); return lo + hi;
}
__device__ __forceinline__ float4 ld4(const float* p) { return *reinterpret_cast<const float4*>(p); }
__device__ __forceinline__ ulonglong2 ld2u(const float* p) { return *reinterpret_cast<const ulonglong2*>(p); }

__device__ __forceinline__ uint32_t smem_to_u32(const void* p) {
    uint32_t a;
    asm("{ .reg .u64 t; cvta.to.shared.u64 t, %1; cvt.u32.u64 %0, t; }" : "=r"(a) : "l"(p));
    return a;
}
__device__ __forceinline__ uint32_t packbf(float lo, float hi) {
    uint32_t r; asm("cvt.rn.bf16x2.f32 %0, %1, %2;" : "=r"(r) : "f"(hi), "f"(lo)); return r;
}

// bf16 HMMA m16n8k16, fp32 accum (baseline sm_80+ feature — no 'a' target gating)
__device__ __forceinline__ void mma16816(float* c, const uint32_t* a, uint32_t b0, uint32_t b1) {
    asm volatile("mma.sync.aligned.m16n8k16.row.col.f32.bf16.bf16.f32 "
        "{%0,%1,%2,%3}, {%4,%5,%6,%7}, {%8,%9}, {%0,%1,%2,%3};"
        : "+f"(c[0]), "+f"(c[1]), "+f"(c[2]), "+f"(c[3])
        : "r"(a[0]), "r"(a[1]), "r"(a[2]), "r"(a[3]), "r"(b0), "r"(b1));
}
__device__ __forceinline__ void ldmat4(uint32_t* a, uint32_t addr) {
    asm volatile("ldmatrix.sync.aligned.m8n8.x4.shared.b16 {%0,%1,%2,%3}, [%4];"
        : "=r"(a[0]), "=r"(a[1]), "=r"(a[2]), "=r"(a[3]) : "r"(addr));
}

__device__ __forceinline__ float bilin(const float* __restrict__ img, float fx, float fy) {
    float x0f = floorf(fx), y0f = floorf(fy);
    float wx1 = fx - x0f, wy1 = fy - y0f;
    float wx0 = 1.0f - wx1, wy0 = 1.0f - wy1;
    int x0 = (int)x0f, y0 = (int)y0f;
    int xi0 = min(max(x0, 0), W - 1), yi0 = min(max(y0, 0), H - 1);
    int xi1 = min(max(x0 + 1, 0), W - 1), yi1 = min(max(y0 + 1, 0), H - 1);
    bool vx0 = (x0f >= 0.0f) && (x0f <= (float)(W - 1));
    bool vx1 = (x0f >= -1.0f) && (x0f <= (float)(W - 2));
    bool vy0 = (y0f >= 0.0f) && (y0f <= (float)(H - 1));
    bool vy1 = (y0f >= -1.0f) && (y0f <= (float)(H - 2));
    float v00 = (vx0 && vy0) ? __ldg(img + yi0 * W + xi0) : 0.0f;
    float v10 = (vx1 && vy0) ? __ldg(img + yi0 * W + xi1) : 0.0f;
    float v01 = (vx0 && vy1) ? __ldg(img + yi1 * W + xi0) : 0.0f;
    float v11 = (vx1 && vy1) ? __ldg(img + yi1 * W + xi1) : 0.0f;
    return v00 * (wx0 * wy0) + v10 * (wx1 * wy0) + v01 * (wx0 * wy1) + v11 * (wx1 * wy1);
}

// =================== K1: phases 1-4 with bf16 HMMA MLP. block = 64 px ===================
__global__ __launch_bounds__(NTHR, 3)
void scab_k1(const float* __restrict__ x,
             const float* __restrict__ w1, const float* __restrict__ b1,
             const float* __restrict__ w2, const float* __restrict__ b2,
             const float* __restrict__ wr, const float* __restrict__ br,
             const float* __restrict__ wo, const float* __restrict__ bo)
{
    extern __shared__ char smc[];
    float* emb   = (float*)(smc + E_OFF);     // [64][68] fp32 (first 8704B alias strip[64][34])
    float* strip = (float*)(smc + E_OFF);
    uint32_t* w1p = (uint32_t*)(smc + W1P_OFF);
    uint32_t* w2p = (uint32_t*)(smc + W2P_OFF);
    float* wrs = (float*)(smc + WRS_OFF);
    float* wos = (float*)(smc + WOS_OFF);
    float* b1s = (float*)(smc + B1S_OFF);
    float* b2s = (float*)(smc + B2S_OFF);
    float* brs = (float*)(smc + BRS_OFF);
    float* bos = (float*)(smc + BOS_OFF);
    const uint32_t smb = smem_to_u32(smc);

    const int t = threadIdx.x;
    const int wid = t >> 5;
    const int lane = t & 31;
    const int oy = blockIdx.y;
    const int bz = blockIdx.z;
    const int ox0 = blockIdx.x * TILE;

    // ---- stage weights: bf16 pairs in B-fragment-friendly layout ----
    for (int i = t; i < 64 * 40; i += NTHR) {
        int n = i / 40, kp = i - n * 40, k = kp * 2;
        float v0 = (k     < 68) ? w1[n * 68 + k    ] : 0.0f;
        float v1 = (k + 1 < 68) ? w1[n * 68 + k + 1] : 0.0f;
        w1p[n * 41 + kp] = packbf(v0, v1);
    }
    for (int i = t; i < 64 * 32; i += NTHR) {
        int n = i / 32, kp = i - n * 32, k = kp * 2;
        w2p[n * 33 + kp] = packbf(w2[n * 64 + k], w2[n * 64 + k + 1]);
    }
    if (t < 256) wrs[t] = wr[t];
    if (t < 128) wos[t] = wo[t];
    if (t < 64) { b1s[t] = b1[t]; b2s[t] = b2[t]; }
    if (t < 4) brs[t] = br[t];
    if (t < 2) bos[t] = bo[t];

    const float inv127 = 2.0f / 127.0f;

    // ---- phase 1a: stage + vertical lerp -> strip[c][j], 64 x 34 ----
    float gx_blk = ((ox0 + 0.5f) / 2.0f - 0.5f) * inv127 - 1.0f;
    float fx_blk = ((gx_blk + 1.0f) * (float)W - 1.0f) * 0.5f;
    const int m_blk = (int)floorf(fx_blk);
    {
        float gy = ((oy + 0.5f) / 2.0f - 0.5f) * inv127 - 1.0f;
        float fy = ((gy + 1.0f) * (float)H - 1.0f) * 0.5f;
        float y0f = floorf(fy);
        float wy1 = fy - y0f, wy0 = 1.0f - wy1;
        int y0 = (int)y0f;
        bool vy0 = (y0 >= 0) && (y0 <= H - 1);
        bool vy1 = (y0 >= -1) && (y0 <= H - 2);
        int yi0 = min(max(y0, 0), H - 1);
        int yi1 = min(max(y0 + 1, 0), H - 1);
        const float* xb = x + (size_t)bz * C * H * W;
        #pragma unroll 1
        for (int i = t; i < 64 * 34; i += NTHR) {
            int c = i / 34, j = i - c * 34;
            int xs = m_blk + j;
            bool vx = (xs >= 0) && (xs <= W - 1);
            int xc = min(max(xs, 0), W - 1);
            const float* base = xb + c * (H * W);
            float v0 = (vx && vy0) ? __ldg(base + yi0 * W + xc) : 0.0f;
            float v1 = (vx && vy1) ? __ldg(base + yi1 * W + xc) : 0.0f;
            strip[c * 34 + j] = v0 * wy0 + v1 * wy1;
        }
    }
    __syncthreads();

    // ---- phase 1b: horizontal lerp + coords -> A1 bf16 [p][88] (cols 0..79, K-pad zero) ----
    {
        const int p  = t & 63;
        const int cb = t >> 6;
        const int ox = ox0 + p;
        float gx = ((ox + 0.5f) / 2.0f - 0.5f) * inv127 - 1.0f;
        float fx = ((gx + 1.0f) * (float)W - 1.0f) * 0.5f;
        float x0f = floorf(fx);
        float wx1 = fx - x0f, wx0 = 1.0f - wx1;
        int j0 = (int)x0f - m_blk;   // [0, 32]
        char* a1 = smc + A1_OFF + p * 176;   // 88 cols * 2B
        #define A1PAIR(col, v0, v1) \
            (*(uint32_t*)(a1 + (col) * 2) = packbf((v0), (v1)))
        if (cb == 0) {
            float ah = (oy + 0.5f) / 2.0f;
            float aw = (ox + 0.5f) / 2.0f;
            A1PAIR(0, 0.5f, 0.5f);
            A1PAIR(2, ah - floorf(ah + 0.001f) - 0.5f, aw - floorf(aw + 0.001f) - 0.5f);
        }
        #pragma unroll 1
        for (int c2 = 0; c2 < 8; c2++) {
            int ch = cb * 16 + 2 * c2;
            float u0 = strip[ch * 34 + j0] * wx0 + strip[ch * 34 + j0 + 1] * wx1;
            float u1 = strip[(ch + 1) * 34 + j0] * wx0 + strip[(ch + 1) * 34 + j0 + 1] * wx1;
            A1PAIR(4 + ch, u0, u1);
        }
        if (cb == 3) {
            #pragma unroll
            for (int z = 68; z < 80; z += 2) A1PAIR(z, 0.0f, 0.0f);
        }
        #undef A1PAIR
    }
    __syncthreads();

    // ---- layer1: hidden = relu(A1 . w1^T + b1) via HMMA. warp = (mtile, nhalf) ----
    const int mt = wid >> 1;        // m-tile 0..3 (16 rows each)
    const int nh = wid & 1;         // n-half 0..1 (32 cols each)
    const int r0 = lane >> 2;       // fragment row within tile
    const int q  = lane & 3;        // fragment col quad
    {
        float acc[4][4];
        #pragma unroll
        for (int nt = 0; nt < 4; nt++)
            #pragma unroll
            for (int i = 0; i < 4; i++) acc[nt][i] = 0.0f;
        #pragma unroll
        for (int kc = 0; kc < 5; kc++) {
            uint32_t a[4];
            ldmat4(a, smb + A1_OFF +
                   (uint32_t)(((mt * 16 + (lane & 15)) * 88 + kc * 16 + (lane >> 4) * 8) * 2));
            #pragma unroll
            for (int nt = 0; nt < 4; nt++) {
                int n = nh * 32 + nt * 8 + r0;
                uint32_t b0 = w1p[n * 41 + kc * 8 + q];
                uint32_t b1f = w1p[n * 41 + kc * 8 + q + 4];
                mma16816(acc[nt], a, b0, b1f);
            }
        }
        #pragma unroll
        for (int nt = 0; nt < 4; nt++) {
            int c0 = nh * 32 + nt * 8 + q * 2;
            float bb0 = b1s[c0], bb1 = b1s[c0 + 1];
            uint32_t lo = packbf(fmaxf(acc[nt][0] + bb0, 0.0f), fmaxf(acc[nt][1] + bb1, 0.0f));
            uint32_t hi = packbf(fmaxf(acc[nt][2] + bb0, 0.0f), fmaxf(acc[nt][3] + bb1, 0.0f));
            *(uint32_t*)(smc + HID_OFF + ((mt * 16 + r0) * 72 + c0) * 2)     = lo;
            *(uint32_t*)(smc + HID_OFF + ((mt * 16 + r0 + 8) * 72 + c0) * 2) = hi;
        }
    }
    __syncthreads();

    // ---- layer2: emb = relu(hidden . w2^T + b2) -> fp32 emb[64][68] (aliases strip; strip dead) ----
    {
        float acc[4][4];
        #pragma unroll
        for (int nt = 0; nt < 4; nt++)
            #pragma unroll
            for (int i = 0; i < 4; i++) acc[nt][i] = 0.0f;
        #pragma unroll
        for (int kc = 0; kc < 4; kc++) {
            uint32_t a[4];
            ldmat4(a, smb + HID_OFF +
                   (uint32_t)(((mt * 16 + (lane & 15)) * 72 + kc * 16 + (lane >> 4) * 8) * 2));
            #pragma unroll
            for (int nt = 0; nt < 4; nt++) {
                int n = nh * 32 + nt * 8 + r0;
                uint32_t b0 = w2p[n * 33 + kc * 8 + q];
                uint32_t b1f = w2p[n * 33 + kc * 8 + q + 4];
                mma16816(acc[nt], a, b0, b1f);
            }
        }
        #pragma unroll
        for (int nt = 0; nt < 4; nt++) {
            int c0 = nh * 32 + nt * 8 + q * 2;
            float bb0 = b2s[c0], bb1 = b2s[c0 + 1];
            float2 lo = make_float2(fmaxf(acc[nt][0] + bb0, 0.0f), fmaxf(acc[nt][1] + bb1, 0.0f));
            float2 hi = make_float2(fmaxf(acc[nt][2] + bb0, 0.0f), fmaxf(acc[nt][3] + bb1, 0.0f));
            *(float2*)(emb + (mt * 16 + r0) * 68 + c0)       = lo;
            *(float2*)(emb + (mt * 16 + r0 + 8) * 68 + c0)   = hi;
        }
    }
    __syncthreads();

    // ---- phase 4: r (sigmoid) + offsets -> global. thread = (px, e) ----
    {
        const int p = t >> 2, e = t & 3;
        const float* erow = emb + p * 68;
        const float* wrr = wrs + e * 64;
        const float* wor = wos + (e & 1) * 64;
        u64t rA = 0ull, rB = 0ull, oA = 0ull, oB = 0ull;
        #pragma unroll
        for (int i = 0; i < 16; i++) {
            ulonglong2 ev  = ld2u(erow + i * 4);
            ulonglong2 wrv = ld2u(wrr + i * 4);
            ulonglong2 wov = ld2u(wor + i * 4);
            rA = fma2(wrv.x, ev.x, rA);
            rB = fma2(wrv.y, ev.y, rB);
            oA = fma2(wov.x, ev.x, oA);
            oB = fma2(wov.y, ev.y, oB);
        }
        float accR = hadd2(rA) + hadd2(rB) + brs[e];
        const int pxg = ((bz * OUT + oy) * OUT) + ox0 + p;
        g_rs[pxg * 4 + e] = 1.0f / (1.0f + __expf(-accR));
        if (e < 2) g_offs[pxg * 2 + e] = hadd2(oA) + hadd2(oB) + bos[e];
    }
}

// =================== K23: phases 5-7 fused (identical to R8) ===================
__global__ __launch_bounds__(NTHR, 3)
void scab_k23(const float* __restrict__ x,
              const float* __restrict__ wcmp,
              const float* __restrict__ wexp,
              float* __restrict__ out)
{
    extern __shared__ float sm[];
    float* wcp  = sm + K2_WC;
    float* wes  = sm + K2_WE;
    float* fea  = sm + K2_FEA;
    float* cmps = sm + K2_CMP;

    const int t  = threadIdx.x;
    const int oy = blockIdx.y;
    const int bz = blockIdx.z;
    const int ox0 = blockIdx.x * TILE;
    const int wid  = t >> 5;
    const int lane = t & 31;

    for (int i = t; i < 32 * 64; i += NTHR) { int ed = i >> 6, c = i & 63; wcp[ed * 68 + c] = wcmp[i]; }
    for (int i = t; i < 2048;    i += NTHR) wes[i] = wexp[i];

    const int p  = t & 63;
    const int cb = t >> 6;
    const int ox = ox0 + p;
    const int pxg = ((bz * OUT + oy) * OUT) + ox;

    {
        const float inv127 = 2.0f / 127.0f;
        float gx = ((ox + 0.5f) / 2.0f - 0.5f) * inv127 - 1.0f;
        float gy = ((oy + 0.5f) / 2.0f - 0.5f) * inv127 - 1.0f;
        float ix = gx + g_offs[pxg * 2 + 0] * inv127;
        float iy = gy + g_offs[pxg * 2 + 1] * inv127;
        float fx = ((ix + 1.0f) * (float)W - 1.0f) * 0.5f;
        float fy = ((iy + 1.0f) * (float)H - 1.0f) * 0.5f;
        const float* xb = x + (size_t)bz * C * H * W;
        #pragma unroll 1
        for (int k4 = 0; k4 < 4; k4++) {
            float4 v;
            #pragma unroll
            for (int kk = 0; kk < 4; kk++) {
                int c = cb * 16 + k4 * 4 + kk;
                ((float*)&v)[kk] = bilin(xb + c * (H * W), fx, fy);
            }
            *reinterpret_cast<float4*>(&fea[p * FEA_S + cb * 16 + k4 * 4]) = v;
        }
    }
    __syncthreads();

    {
        const float* frow = &fea[p * FEA_S];
        float4 rv = ld4(&g_rs[pxg * 4]);
        const int dg = t >> 6;
        u64t acc[4][2];
        #pragma unroll
        for (int e = 0; e < 4; e++) { acc[e][0] = 0ull; acc[e][1] = 0ull; }
        #pragma unroll 4
        for (int c4 = 0; c4 < 16; c4++) {
            ulonglong2 Fv = ld2u(frow + c4 * 4);
            #pragma unroll
            for (int e = 0; e < 4; e++) {
                const float* w0 = &wcp[(e * 8 + 2 * dg) * 68 + c4 * 4];
                ulonglong2 wv0 = ld2u(w0);
                ulonglong2 wv1 = ld2u(w0 + 68);
                acc[e][0] = fma2(wv0.x, Fv.x, acc[e][0]);
                acc[e][0] = fma2(wv0.y, Fv.y, acc[e][0]);
                acc[e][1] = fma2(wv1.x, Fv.x, acc[e][1]);
                acc[e][1] = fma2(wv1.y, Fv.y, acc[e][1]);
            }
        }
        float comp0 = 0.0f, comp1 = 0.0f;
        #pragma unroll
        for (int e = 0; e < 4; e++) {
            float re = ((const float*)&rv)[e];
            comp0 = fmaf(re, hadd2(acc[e][0]), comp0);
            comp1 = fmaf(re, hadd2(acc[e][1]), comp1);
        }
        cmps[p * 12 + 2 * dg]     = comp0;
        cmps[p * 12 + 2 * dg + 1] = comp1;
    }
    __syncthreads();

    {
        const int g = wid;
        const int p0 = lane, p1 = lane + 32;
        const int px0 = ((bz * OUT + oy) * OUT) + ox0 + p0;
        const int px1 = px0 + 32;
        ulonglong2 cA0 = ld2u(&cmps[p0 * 12]);
        ulonglong2 cB0 = ld2u(&cmps[p0 * 12 + 4]);
        ulonglong2 cA1 = ld2u(&cmps[p1 * 12]);
        ulonglong2 cB1 = ld2u(&cmps[p1 * 12 + 4]);
        float4 rv0 = ld4(&g_rs[px0 * 4]);
        float4 rv1 = ld4(&g_rs[px1 * 4]);
        float fe0[8], fe1[8];
        *reinterpret_cast<float4*>(&fe0[0]) = ld4(&fea[p0 * FEA_S + g * 8]);
        *reinterpret_cast<float4*>(&fe0[4]) = ld4(&fea[p0 * FEA_S + g * 8 + 4]);
        *reinterpret_cast<float4*>(&fe1[0]) = ld4(&fea[p1 * FEA_S + g * 8]);
        *reinterpret_cast<float4*>(&fe1[4]) = ld4(&fea[p1 * FEA_S + g * 8 + 4]);
        float* ob = out + (((size_t)bz * C + g * 8) * OUT + oy) * OUT + ox0 + p0;
        #pragma unroll
        for (int k = 0; k < 8; k++) {
            int c = g * 8 + k;
            float acc0 = fe0[k];
            float acc1 = fe1[k];
            #pragma unroll
            for (int e = 0; e < 4; e++) {
                const float* werow = &wes[(e * 64 + c) * 8];
                ulonglong2 wv  = ld2u(werow);
                ulonglong2 wv2 = ld2u(werow + 4);
                u64t s0 = fma2(wv.x, cA0.x, 0ull);
                s0 = fma2(wv.y, cA0.y, s0);
                s0 = fma2(wv2.x, cB0.x, s0);
                s0 = fma2(wv2.y, cB0.y, s0);
                u64t s1 = fma2(wv.x, cA1.x, 0ull);
                s1 = fma2(wv.y, cA1.y, s1);
                s1 = fma2(wv2.x, cB1.x, s1);
                s1 = fma2(wv2.y, cB1.y, s1);
                acc0 = fmaf(((const float*)&rv0)[e], hadd2(s0), acc0);
                acc1 = fmaf(((const float*)&rv1)[e], hadd2(s1), acc1);
            }
            ob[(size_t)k * OUT * OUT]      = acc0;
            ob[(size_t)k * OUT * OUT + 32] = acc1;
        }
    }
}

extern "C" void kernel_launch(void* const* d_in, const int* in_sizes, int n_in,
                              void* d_out, int out_size) {
    (void)in_sizes; (void)n_in; (void)out_size;
    const float* x    = (const float*)d_in[0];
    const float* wcmp = (const float*)d_in[1];
    const float* wexp = (const float*)d_in[2];
    const float* w1   = (const float*)d_in[3];
    const float* b1   = (const float*)d_in[4];
    const float* w2   = (const float*)d_in[5];
    const float* b2   = (const float*)d_in[6];
    const float* wr   = (const float*)d_in[7];
    const float* br   = (const float*)d_in[8];
    const float* wo   = (const float*)d_in[9];
    const float* bo   = (const float*)d_in[10];
    float* out = (float*)d_out;

    cudaFuncSetAttribute(scab_k1,  cudaFuncAttributeMaxDynamicSharedMemorySize, K1_SMEM);
    cudaFuncSetAttribute(scab_k23, cudaFuncAttributeMaxDynamicSharedMemorySize, K2_BYTES);

    dim3 grid(OUT / TILE, OUT, Bz);
    scab_k1<<<grid, NTHR, K1_SMEM>>>(x, w1, b1, w2, b2, wr, br, wo, bo);
    scab_k23<<<grid, NTHR, K2_BYTES>>>(x, wcmp, wexp, out);
}

// round 11
// speedup vs baseline: 2.7085x; 1.1332x over previous
#include <cuda_runtime.h>
#include <cuda_bf16.h>
#include <cstdint>
#include <math.h>

// Problem constants (fixed by setup_inputs)
#define Bz   2
#define C    64
#define H    128
#define W    128
#define OUT  256
#define TILE 64
#define NTHR 256
#define NPX  (Bz * OUT * OUT)

// ---------------- global scratch (static, allowed) ----------------
__device__ float g_rs  [NPX * 4];
__device__ float g_offs[NPX * 2];

// ================= K1 smem layout (bytes) =================
#define E_OFF    0       // fp32 emb[64][68] = 17408; first 8704B alias strip[64][34]
#define A1_OFF   17408   // bf16 acts [64 x 88] = 11264
#define HID_OFF  28672   // bf16 hidden [64 x 72] = 9216
#define W1P_OFF  37888   // uint32 w1 pairs [64][41] = 10496
#define W2P_OFF  48384   // uint32 w2 pairs [64][33] = 8448
#define WRS_OFF  56832
#define WOS_OFF  57856
#define B1S_OFF  58368
#define B2S_OFF  58624
#define BRS_OFF  58880
#define BOS_OFF  58896
#define K1_SMEM  58912

// ================= K23 smem layout (bytes) =================
#define F_OFF    0       // fp32 fea[64][68] = 17408
#define FB_OFF   17408   // bf16 fea [64 x 72] = 9216
#define T_OFF    26624   // fp32 T[64][36] = 9216
#define UB_OFF   35840   // bf16 u [64 x 40] = 5120
#define WCB_OFF  40960   // uint32 wc pairs [32][33] = 4224
#define WEB_OFF  45184   // uint32 wexp' pairs [64][17] = 4352
#define K23_SMEM 49536
#define FEA_S 68

typedef unsigned long long u64t;

__device__ __forceinline__ float4 ld4(const float* p) { return *reinterpret_cast<const float4*>(p); }

__device__ __forceinline__ uint32_t smem_to_u32(const void* p) {
    uint32_t a;
    asm("{ .reg .u64 t; cvta.to.shared.u64 t, %1; cvt.u32.u64 %0, t; }" : "=r"(a) : "l"(p));
    return a;
}
__device__ __forceinline__ uint32_t packbf(float lo, float hi) {
    uint32_t r; asm("cvt.rn.bf16x2.f32 %0, %1, %2;" : "=r"(r) : "f"(hi), "f"(lo)); return r;
}
__device__ __forceinline__ u64t fma2(u64t a, u64t b, u64t c) {
    u64t d; asm("fma.rn.f32x2 %0, %1, %2, %3;" : "=l"(d) : "l"(a), "l"(b), "l"(c)); return d;
}
__device__ __forceinline__ float hadd2(u64t v) {
    float lo, hi; asm("mov.b64 {%0, %1}, %2;" : "=f"(lo), "=f"(hi) : "l"(v)); return lo + hi;
}
__device__ __forceinline__ ulonglong2 ld2u(const float* p) { return *reinterpret_cast<const ulonglong2*>(p); }

// bf16 HMMA m16n8k16, fp32 accum
__device__ __forceinline__ void mma16816(float* c, const uint32_t* a, uint32_t b0, uint32_t b1) {
    asm volatile("mma.sync.aligned.m16n8k16.row.col.f32.bf16.bf16.f32 "
        "{%0,%1,%2,%3}, {%4,%5,%6,%7}, {%8,%9}, {%0,%1,%2,%3};"
        : "+f"(c[0]), "+f"(c[1]), "+f"(c[2]), "+f"(c[3])
        : "r"(a[0]), "r"(a[1]), "r"(a[2]), "r"(a[3]), "r"(b0), "r"(b1));
}
__device__ __forceinline__ void ldmat4(uint32_t* a, uint32_t addr) {
    asm volatile("ldmatrix.sync.aligned.m8n8.x4.shared.b16 {%0,%1,%2,%3}, [%4];"
        : "=r"(a[0]), "=r"(a[1]), "=r"(a[2]), "=r"(a[3]) : "r"(addr));
}

__device__ __forceinline__ float bilin(const float* __restrict__ img, float fx, float fy) {
    float x0f = floorf(fx), y0f = floorf(fy);
    float wx1 = fx - x0f, wy1 = fy - y0f;
    float wx0 = 1.0f - wx1, wy0 = 1.0f - wy1;
    int x0 = (int)x0f, y0 = (int)y0f;
    int xi0 = min(max(x0, 0), W - 1), yi0 = min(max(y0, 0), H - 1);
    int xi1 = min(max(x0 + 1, 0), W - 1), yi1 = min(max(y0 + 1, 0), H - 1);
    bool vx0 = (x0f >= 0.0f) && (x0f <= (float)(W - 1));
    bool vx1 = (x0f >= -1.0f) && (x0f <= (float)(W - 2));
    bool vy0 = (y0f >= 0.0f) && (y0f <= (float)(H - 1));
    bool vy1 = (y0f >= -1.0f) && (y0f <= (float)(H - 2));
    float v00 = (vx0 && vy0) ? __ldg(img + yi0 * W + xi0) : 0.0f;
    float v10 = (vx1 && vy0) ? __ldg(img + yi0 * W + xi1) : 0.0f;
    float v01 = (vx0 && vy1) ? __ldg(img + yi1 * W + xi0) : 0.0f;
    float v11 = (vx1 && vy1) ? __ldg(img + yi1 * W + xi1) : 0.0f;
    return v00 * (wx0 * wy0) + v10 * (wx1 * wy0) + v01 * (wx0 * wy1) + v11 * (wx1 * wy1);
}

// =================== K1: phases 1-4 (identical to R10) ===================
__global__ __launch_bounds__(NTHR, 3)
void scab_k1(const float* __restrict__ x,
             const float* __restrict__ w1, const float* __restrict__ b1,
             const float* __restrict__ w2, const float* __restrict__ b2,
             const float* __restrict__ wr, const float* __restrict__ br,
             const float* __restrict__ wo, const float* __restrict__ bo)
{
    extern __shared__ char smc[];
    float* emb   = (float*)(smc + E_OFF);
    float* strip = (float*)(smc + E_OFF);
    uint32_t* w1p = (uint32_t*)(smc + W1P_OFF);
    uint32_t* w2p = (uint32_t*)(smc + W2P_OFF);
    float* wrs = (float*)(smc + WRS_OFF);
    float* wos = (float*)(smc + WOS_OFF);
    float* b1s = (float*)(smc + B1S_OFF);
    float* b2s = (float*)(smc + B2S_OFF);
    float* brs = (float*)(smc + BRS_OFF);
    float* bos = (float*)(smc + BOS_OFF);
    const uint32_t smb = smem_to_u32(smc);

    const int t = threadIdx.x;
    const int wid = t >> 5;
    const int lane = t & 31;
    const int oy = blockIdx.y;
    const int bz = blockIdx.z;
    const int ox0 = blockIdx.x * TILE;

    for (int i = t; i < 64 * 40; i += NTHR) {
        int n = i / 40, kp = i - n * 40, k = kp * 2;
        float v0 = (k     < 68) ? w1[n * 68 + k    ] : 0.0f;
        float v1 = (k + 1 < 68) ? w1[n * 68 + k + 1] : 0.0f;
        w1p[n * 41 + kp] = packbf(v0, v1);
    }
    for (int i = t; i < 64 * 32; i += NTHR) {
        int n = i / 32, kp = i - n * 32, k = kp * 2;
        w2p[n * 33 + kp] = packbf(w2[n * 64 + k], w2[n * 64 + k + 1]);
    }
    if (t < 256) wrs[t] = wr[t];
    if (t < 128) wos[t] = wo[t];
    if (t < 64) { b1s[t] = b1[t]; b2s[t] = b2[t]; }
    if (t < 4) brs[t] = br[t];
    if (t < 2) bos[t] = bo[t];

    const float inv127 = 2.0f / 127.0f;

    float gx_blk = ((ox0 + 0.5f) / 2.0f - 0.5f) * inv127 - 1.0f;
    float fx_blk = ((gx_blk + 1.0f) * (float)W - 1.0f) * 0.5f;
    const int m_blk = (int)floorf(fx_blk);
    {
        float gy = ((oy + 0.5f) / 2.0f - 0.5f) * inv127 - 1.0f;
        float fy = ((gy + 1.0f) * (float)H - 1.0f) * 0.5f;
        float y0f = floorf(fy);
        float wy1 = fy - y0f, wy0 = 1.0f - wy1;
        int y0 = (int)y0f;
        bool vy0 = (y0 >= 0) && (y0 <= H - 1);
        bool vy1 = (y0 >= -1) && (y0 <= H - 2);
        int yi0 = min(max(y0, 0), H - 1);
        int yi1 = min(max(y0 + 1, 0), H - 1);
        const float* xb = x + (size_t)bz * C * H * W;
        #pragma unroll 1
        for (int i = t; i < 64 * 34; i += NTHR) {
            int c = i / 34, j = i - c * 34;
            int xs = m_blk + j;
            bool vx = (xs >= 0) && (xs <= W - 1);
            int xc = min(max(xs, 0), W - 1);
            const float* base = xb + c * (H * W);
            float v0 = (vx && vy0) ? __ldg(base + yi0 * W + xc) : 0.0f;
            float v1 = (vx && vy1) ? __ldg(base + yi1 * W + xc) : 0.0f;
            strip[c * 34 + j] = v0 * wy0 + v1 * wy1;
        }
    }
    __syncthreads();

    {
        const int p  = t & 63;
        const int cb = t >> 6;
        const int ox = ox0 + p;
        float gx = ((ox + 0.5f) / 2.0f - 0.5f) * inv127 - 1.0f;
        float fx = ((gx + 1.0f) * (float)W - 1.0f) * 0.5f;
        float x0f = floorf(fx);
        float wx1 = fx - x0f, wx0 = 1.0f - wx1;
        int j0 = (int)x0f - m_blk;
        char* a1 = smc + A1_OFF + p * 176;
        #define A1PAIR(col, v0, v1) \
            (*(uint32_t*)(a1 + (col) * 2) = packbf((v0), (v1)))
        if (cb == 0) {
            float ah = (oy + 0.5f) / 2.0f;
            float aw = (ox + 0.5f) / 2.0f;
            A1PAIR(0, 0.5f, 0.5f);
            A1PAIR(2, ah - floorf(ah + 0.001f) - 0.5f, aw - floorf(aw + 0.001f) - 0.5f);
        }
        #pragma unroll 1
        for (int c2 = 0; c2 < 8; c2++) {
            int ch = cb * 16 + 2 * c2;
            float u0 = strip[ch * 34 + j0] * wx0 + strip[ch * 34 + j0 + 1] * wx1;
            float u1 = strip[(ch + 1) * 34 + j0] * wx0 + strip[(ch + 1) * 34 + j0 + 1] * wx1;
            A1PAIR(4 + ch, u0, u1);
        }
        if (cb == 3) {
            #pragma unroll
            for (int z = 68; z < 80; z += 2) A1PAIR(z, 0.0f, 0.0f);
        }
        #undef A1PAIR
    }
    __syncthreads();

    const int mt = wid >> 1;
    const int nh = wid & 1;
    const int r0 = lane >> 2;
    const int q  = lane & 3;
    {
        float acc[4][4];
        #pragma unroll
        for (int nt = 0; nt < 4; nt++)
            #pragma unroll
            for (int i = 0; i < 4; i++) acc[nt][i] = 0.0f;
        #pragma unroll
        for (int kc = 0; kc < 5; kc++) {
            uint32_t a[4];
            ldmat4(a, smb + A1_OFF +
                   (uint32_t)(((mt * 16 + (lane & 15)) * 88 + kc * 16 + (lane >> 4) * 8) * 2));
            #pragma unroll
            for (int nt = 0; nt < 4; nt++) {
                int n = nh * 32 + nt * 8 + r0;
                uint32_t b0 = w1p[n * 41 + kc * 8 + q];
                uint32_t b1f = w1p[n * 41 + kc * 8 + q + 4];
                mma16816(acc[nt], a, b0, b1f);
            }
        }
        #pragma unroll
        for (int nt = 0; nt < 4; nt++) {
            int c0 = nh * 32 + nt * 8 + q * 2;
            float bb0 = b1s[c0], bb1 = b1s[c0 + 1];
            uint32_t lo = packbf(fmaxf(acc[nt][0] + bb0, 0.0f), fmaxf(acc[nt][1] + bb1, 0.0f));
            uint32_t hi = packbf(fmaxf(acc[nt][2] + bb0, 0.0f), fmaxf(acc[nt][3] + bb1, 0.0f));
            *(uint32_t*)(smc + HID_OFF + ((mt * 16 + r0) * 72 + c0) * 2)     = lo;
            *(uint32_t*)(smc + HID_OFF + ((mt * 16 + r0 + 8) * 72 + c0) * 2) = hi;
        }
    }
    __syncthreads();

    {
        float acc[4][4];
        #pragma unroll
        for (int nt = 0; nt < 4; nt++)
            #pragma unroll
            for (int i = 0; i < 4; i++) acc[nt][i] = 0.0f;
        #pragma unroll
        for (int kc = 0; kc < 4; kc++) {
            uint32_t a[4];
            ldmat4(a, smb + HID_OFF +
                   (uint32_t)(((mt * 16 + (lane & 15)) * 72 + kc * 16 + (lane >> 4) * 8) * 2));
            #pragma unroll
            for (int nt = 0; nt < 4; nt++) {
                int n = nh * 32 + nt * 8 + r0;
                uint32_t b0 = w2p[n * 33 + kc * 8 + q];
                uint32_t b1f = w2p[n * 33 + kc * 8 + q + 4];
                mma16816(acc[nt], a, b0, b1f);
            }
        }
        #pragma unroll
        for (int nt = 0; nt < 4; nt++) {
            int c0 = nh * 32 + nt * 8 + q * 2;
            float bb0 = b2s[c0], bb1 = b2s[c0 + 1];
            float2 lo = make_float2(fmaxf(acc[nt][0] + bb0, 0.0f), fmaxf(acc[nt][1] + bb1, 0.0f));
            float2 hi = make_float2(fmaxf(acc[nt][2] + bb0, 0.0f), fmaxf(acc[nt][3] + bb1, 0.0f));
            *(float2*)(emb + (mt * 16 + r0) * 68 + c0)     = lo;
            *(float2*)(emb + (mt * 16 + r0 + 8) * 68 + c0) = hi;
        }
    }
    __syncthreads();

    {
        const int p = t >> 2, e = t & 3;
        const float* erow = emb + p * 68;
        const float* wrr = wrs + e * 64;
        const float* wor = wos + (e & 1) * 64;
        u64t rA = 0ull, rB = 0ull, oA = 0ull, oB = 0ull;
        #pragma unroll
        for (int i = 0; i < 16; i++) {
            ulonglong2 ev  = ld2u(erow + i * 4);
            ulonglong2 wrv = ld2u(wrr + i * 4);
            ulonglong2 wov = ld2u(wor + i * 4);
            rA = fma2(wrv.x, ev.x, rA);
            rB = fma2(wrv.y, ev.y, rB);
            oA = fma2(wov.x, ev.x, oA);
            oB = fma2(wov.y, ev.y, oB);
        }
        float accR = hadd2(rA) + hadd2(rB) + brs[e];
        const int pxg = ((bz * OUT + oy) * OUT) + ox0 + p;
        g_rs[pxg * 4 + e] = 1.0f / (1.0f + __expf(-accR));
        if (e < 2) g_offs[pxg * 2 + e] = hadd2(oA) + hadd2(oB) + bos[e];
    }
}

// =================== K23: sample2 + GEMM-ified compress/expand ===================
__global__ __launch_bounds__(NTHR, 3)
void scab_k23(const float* __restrict__ x,
              const float* __restrict__ wcmp,
              const float* __restrict__ wexp,
              float* __restrict__ out)
{
    extern __shared__ char smc[];
    float* fea = (float*)(smc + F_OFF);      // [64][68] fp32
    float* Ts  = (float*)(smc + T_OFF);      // [64][36] fp32
    uint32_t* wcb = (uint32_t*)(smc + WCB_OFF);  // [32][33]
    uint32_t* web = (uint32_t*)(smc + WEB_OFF);  // [64][17]
    const uint32_t smb = smem_to_u32(smc);

    const int t  = threadIdx.x;
    const int wid = t >> 5;
    const int lane = t & 31;
    const int oy = blockIdx.y;
    const int bz = blockIdx.z;
    const int ox0 = blockIdx.x * TILE;

    // ---- stage weights as bf16 B-fragment pairs ----
    // wcb[ed][kp] <- wcmp[ed*64 + 2kp..+1]   (ed = e*8+d, k = c)
    for (int i = t; i < 32 * 32; i += NTHR) {
        int n = i >> 5, kp = i & 31;
        wcb[n * 33 + kp] = packbf(wcmp[n * 64 + 2 * kp], wcmp[n * 64 + 2 * kp + 1]);
    }
    // web[c][kp] <- wexp'[c][ed=2kp..+1], wexp'[c][e*8+d] = wexp[(e*64+c)*8+d]
    for (int i = t; i < 64 * 16; i += NTHR) {
        int n = i >> 4, kp = i & 15;
        int ed0 = 2 * kp, ed1 = 2 * kp + 1;
        float v0 = wexp[(((ed0 >> 3) * 64) + n) * 8 + (ed0 & 7)];
        float v1 = wexp[(((ed1 >> 3) * 64) + n) * 8 + (ed1 & 7)];
        web[n * 17 + kp] = packbf(v0, v1);
    }

    const int p  = t & 63;
    const int cb = t >> 6;
    const int ox = ox0 + p;
    const int pxg = ((bz * OUT + oy) * OUT) + ox;

    // ---- phase 5: offset sample -> fea fp32 + feab bf16 ----
    {
        const float inv127 = 2.0f / 127.0f;
        float gx = ((ox + 0.5f) / 2.0f - 0.5f) * inv127 - 1.0f;
        float gy = ((oy + 0.5f) / 2.0f - 0.5f) * inv127 - 1.0f;
        float ix = gx + g_offs[pxg * 2 + 0] * inv127;
        float iy = gy + g_offs[pxg * 2 + 1] * inv127;
        float fx = ((ix + 1.0f) * (float)W - 1.0f) * 0.5f;
        float fy = ((iy + 1.0f) * (float)H - 1.0f) * 0.5f;
        const float* xb = x + (size_t)bz * C * H * W;
        #pragma unroll 1
        for (int k4 = 0; k4 < 4; k4++) {
            float4 v;
            #pragma unroll
            for (int kk = 0; kk < 4; kk++) {
                int c = cb * 16 + k4 * 4 + kk;
                ((float*)&v)[kk] = bilin(xb + c * (H * W), fx, fy);
            }
            *reinterpret_cast<float4*>(&fea[p * FEA_S + cb * 16 + k4 * 4]) = v;
            uint2 pk = make_uint2(packbf(v.x, v.y), packbf(v.z, v.w));
            *(uint2*)(smc + FB_OFF + (p * 72 + cb * 16 + k4 * 4) * 2) = pk;
        }
    }
    __syncthreads();

    const int mt = wid >> 1;
    const int nh = wid & 1;
    const int r0 = lane >> 2;
    const int q  = lane & 3;

    // ---- G1: T[64,32] = feab . wc^T (M=64, N=32, K=64) ----
    {
        float acc[2][4];
        #pragma unroll
        for (int nt = 0; nt < 2; nt++)
            #pragma unroll
            for (int i = 0; i < 4; i++) acc[nt][i] = 0.0f;
        #pragma unroll
        for (int kc = 0; kc < 4; kc++) {
            uint32_t a[4];
            ldmat4(a, smb + FB_OFF +
                   (uint32_t)(((mt * 16 + (lane & 15)) * 72 + kc * 16 + (lane >> 4) * 8) * 2));
            #pragma unroll
            for (int nt = 0; nt < 2; nt++) {
                int n = nh * 16 + nt * 8 + r0;
                uint32_t b0 = wcb[n * 33 + kc * 8 + q];
                uint32_t b1f = wcb[n * 33 + kc * 8 + q + 4];
                mma16816(acc[nt], a, b0, b1f);
            }
        }
        #pragma unroll
        for (int nt = 0; nt < 2; nt++) {
            int c0 = nh * 16 + nt * 8 + q * 2;
            *(float2*)(Ts + (mt * 16 + r0) * 36 + c0)     = make_float2(acc[nt][0], acc[nt][1]);
            *(float2*)(Ts + (mt * 16 + r0 + 8) * 36 + c0) = make_float2(acc[nt][2], acc[nt][3]);
        }
    }
    __syncthreads();

    // ---- glue: comp_d = sum_e r_e T[e*8+d]; u[e*8+d] = r_e * comp_d -> bf16 ----
    if (t < 64) {
        float4 rv = ld4(&g_rs[(((bz * OUT + oy) * OUT) + ox0 + t) * 4]);
        float Tv[32];
        #pragma unroll
        for (int i = 0; i < 8; i++)
            *reinterpret_cast<float4*>(&Tv[i * 4]) = ld4(&Ts[t * 36 + i * 4]);
        float comp[8];
        #pragma unroll
        for (int d = 0; d < 8; d++) {
            comp[d] = rv.x * Tv[d] + rv.y * Tv[8 + d] + rv.z * Tv[16 + d] + rv.w * Tv[24 + d];
        }
        uint32_t up[16];
        #pragma unroll
        for (int e = 0; e < 4; e++) {
            float re = ((const float*)&rv)[e];
            #pragma unroll
            for (int dp = 0; dp < 4; dp++)
                up[e * 4 + dp] = packbf(re * comp[2 * dp], re * comp[2 * dp + 1]);
        }
        #pragma unroll
        for (int i = 0; i < 4; i++)
            *(uint4*)(smc + UB_OFF + t * 80 + i * 16) = *reinterpret_cast<uint4*>(&up[i * 4]);
    }
    __syncthreads();

    // ---- G2: corr[64,64] = u . wexp'^T (M=64, N=64, K=32); out = fea + corr ----
    {
        float acc[4][4];
        #pragma unroll
        for (int nt = 0; nt < 4; nt++)
            #pragma unroll
            for (int i = 0; i < 4; i++) acc[nt][i] = 0.0f;
        #pragma unroll
        for (int kc = 0; kc < 2; kc++) {
            uint32_t a[4];
            ldmat4(a, smb + UB_OFF +
                   (uint32_t)(((mt * 16 + (lane & 15)) * 40 + kc * 16 + (lane >> 4) * 8) * 2));
            #pragma unroll
            for (int nt = 0; nt < 4; nt++) {
                int n = nh * 32 + nt * 8 + r0;
                uint32_t b0 = web[n * 17 + kc * 8 + q];
                uint32_t b1f = web[n * 17 + kc * 8 + q + 4];
                mma16816(acc[nt], a, b0, b1f);
            }
        }
        const int p0 = mt * 16 + r0, p1 = p0 + 8;
        #pragma unroll
        for (int nt = 0; nt < 4; nt++) {
            int c0 = nh * 32 + nt * 8 + q * 2;
            float2 f0 = *(const float2*)(fea + p0 * FEA_S + c0);
            float2 f1 = *(const float2*)(fea + p1 * FEA_S + c0);
            size_t base0 = (((size_t)bz * C + c0) * OUT + oy) * OUT + ox0;
            size_t base1 = base0 + (size_t)OUT * OUT;
            out[base0 + p0] = f0.x + acc[nt][0];
            out[base1 + p0] = f0.y + acc[nt][1];
            out[base0 + p1] = f1.x + acc[nt][2];
            out[base1 + p1] = f1.y + acc[nt][3];
        }
    }
}

extern "C" void kernel_launch(void* const* d_in, const int* in_sizes, int n_in,
                              void* d_out, int out_size) {
    (void)in_sizes; (void)n_in; (void)out_size;
    const float* x    = (const float*)d_in[0];
    const float* wcmp = (const float*)d_in[1];
    const float* wexp = (const float*)d_in[2];
    const float* w1   = (const float*)d_in[3];
    const float* b1   = (const float*)d_in[4];
    const float* w2   = (const float*)d_in[5];
    const float* b2   = (const float*)d_in[6];
    const float* wr   = (const float*)d_in[7];
    const float* br   = (const float*)d_in[8];
    const float* wo   = (const float*)d_in[9];
    const float* bo   = (const float*)d_in[10];
    float* out = (float*)d_out;

    cudaFuncSetAttribute(scab_k1,  cudaFuncAttributeMaxDynamicSharedMemorySize, K1_SMEM);
    cudaFuncSetAttribute(scab_k23, cudaFuncAttributeMaxDynamicSharedMemorySize, K23_SMEM);

    dim3 grid(OUT / TILE, OUT, Bz);
    scab_k1<<<grid, NTHR, K1_SMEM>>>(x, w1, b1, w2, b2, wr, br, wo, bo);
    scab_k23<<<grid, NTHR, K23_SMEM>>>(x, wcmp, wexp, out);
}

// round 12
// speedup vs baseline: 2.7665x; 1.0214x over previous
#include <cuda_runtime.h>
#include <cuda_bf16.h>
#include <cstdint>
#include <math.h>

// Problem constants (fixed by setup_inputs)
#define Bz   2
#define C    64
#define H    128
#define W    128
#define OUT  256
#define TILE 64
#define NTHR 256

// ================= fused smem layout (bytes) =================
// persistent region
#define WCB_OFF 0        // u32 wc pairs [32][33] = 4224
#define WEB_OFF 4224     // u32 wexp' pairs [64][17] = 4352
#define WRS_OFF 8576     // fp32 wr [4][64] = 1024
#define WOS_OFF 9600     // fp32 wo [2][64] = 512
#define B1S_OFF 10112    // fp32 [64]
#define B2S_OFF 10368    // fp32 [64]
#define BRS_OFF 10624    // fp32 [4]
#define BOS_OFF 10640    // fp32 [2]
#define RS_OFF  10656    // fp32 rs[64][4] = 1024
#define OF_OFF  11680    // fp32 offs[64][2] = 512
#define CW_OFF  12192    // float4 cw[64] = 1024
#define CI_OFF  13216    // int4 ci[64] = 1024
#define DYN     14336
// dynamic region (phases alias)
#define E_OFF   (DYN + 0)       // fp32 strip[64][34] / emb[64][68] / fea[64][68] = 17408
#define A1_OFF  (DYN + 17408)   // bf16 A1 [64 x 88] = 11264 ; later feab [64 x 72] = 9216
#define HID_OFF (DYN + 28672)   // bf16 hid [64 x 72] = 9216 ; later fp32 T [64][36] = 9216
#define W1P_OFF (DYN + 37888)   // u32 w1 pairs [64][41] = 10496 ; later bf16 u [64 x 40] = 5120
#define W2P_OFF (DYN + 48384)   // u32 w2 pairs [64][33] = 8448
#define FB_OFF  A1_OFF
#define T_OFF   HID_OFF
#define UB_OFF  W1P_OFF
#define SMEM_TOTAL 71168
#define FEA_S 68

typedef unsigned long long u64t;

__device__ __forceinline__ float4 ld4(const float* p) { return *reinterpret_cast<const float4*>(p); }
__device__ __forceinline__ ulonglong2 ld2u(const float* p) { return *reinterpret_cast<const ulonglong2*>(p); }

__device__ __forceinline__ uint32_t smem_to_u32(const void* p) {
    uint32_t a;
    asm("{ .reg .u64 t; cvta.to.shared.u64 t, %1; cvt.u32.u64 %0, t; }" : "=r"(a) : "l"(p));
    return a;
}
__device__ __forceinline__ uint32_t packbf(float lo, float hi) {
    uint32_t r; asm("cvt.rn.bf16x2.f32 %0, %1, %2;" : "=r"(r) : "f"(hi), "f"(lo)); return r;
}
__device__ __forceinline__ u64t fma2(u64t a, u64t b, u64t c) {
    u64t d; asm("fma.rn.f32x2 %0, %1, %2, %3;" : "=l"(d) : "l"(a), "l"(b), "l"(c)); return d;
}
__device__ __forceinline__ float hadd2(u64t v) {
    float lo, hi; asm("mov.b64 {%0, %1}, %2;" : "=f"(lo), "=f"(hi) : "l"(v)); return lo + hi;
}

__device__ __forceinline__ void mma16816(float* c, const uint32_t* a, uint32_t b0, uint32_t b1) {
    asm volatile("mma.sync.aligned.m16n8k16.row.col.f32.bf16.bf16.f32 "
        "{%0,%1,%2,%3}, {%4,%5,%6,%7}, {%8,%9}, {%0,%1,%2,%3};"
        : "+f"(c[0]), "+f"(c[1]), "+f"(c[2]), "+f"(c[3])
        : "r"(a[0]), "r"(a[1]), "r"(a[2]), "r"(a[3]), "r"(b0), "r"(b1));
}
__device__ __forceinline__ void ldmat4(uint32_t* a, uint32_t addr) {
    asm volatile("ldmatrix.sync.aligned.m8n8.x4.shared.b16 {%0,%1,%2,%3}, [%4];"
        : "=r"(a[0]), "=r"(a[1]), "=r"(a[2]), "=r"(a[3]) : "r"(addr));
}

// =================== fused kernel: all 7 phases, block = 64 px ===================
__global__ __launch_bounds__(NTHR, 3)
void scab_fused(const float* __restrict__ x,
                const float* __restrict__ wcmp, const float* __restrict__ wexp,
                const float* __restrict__ w1, const float* __restrict__ b1,
                const float* __restrict__ w2, const float* __restrict__ b2,
                const float* __restrict__ wr, const float* __restrict__ br,
                const float* __restrict__ wo, const float* __restrict__ bo,
                float* __restrict__ out)
{
    extern __shared__ char smc[];
    float* emb   = (float*)(smc + E_OFF);
    float* strip = (float*)(smc + E_OFF);
    float* fea   = (float*)(smc + E_OFF);
    float* Ts    = (float*)(smc + T_OFF);
    uint32_t* w1p = (uint32_t*)(smc + W1P_OFF);
    uint32_t* w2p = (uint32_t*)(smc + W2P_OFF);
    uint32_t* wcb = (uint32_t*)(smc + WCB_OFF);
    uint32_t* web = (uint32_t*)(smc + WEB_OFF);
    float* wrs  = (float*)(smc + WRS_OFF);
    float* wos  = (float*)(smc + WOS_OFF);
    float* b1s  = (float*)(smc + B1S_OFF);
    float* b2s  = (float*)(smc + B2S_OFF);
    float* brs  = (float*)(smc + BRS_OFF);
    float* bos  = (float*)(smc + BOS_OFF);
    float* rs_s = (float*)(smc + RS_OFF);
    float* of_s = (float*)(smc + OF_OFF);
    float4* cw  = (float4*)(smc + CW_OFF);
    int4*   ci  = (int4*)(smc + CI_OFF);
    const uint32_t smb = smem_to_u32(smc);

    const int t = threadIdx.x;
    const int wid = t >> 5;
    const int lane = t & 31;
    const int oy = blockIdx.y;
    const int bz = blockIdx.z;
    const int ox0 = blockIdx.x * TILE;
    const float* xb = x + (size_t)bz * C * H * W;

    // ---- stage ALL weights ----
    for (int i = t; i < 64 * 40; i += NTHR) {
        int n = i / 40, kp = i - n * 40, k = kp * 2;
        float v0 = (k     < 68) ? w1[n * 68 + k    ] : 0.0f;
        float v1 = (k + 1 < 68) ? w1[n * 68 + k + 1] : 0.0f;
        w1p[n * 41 + kp] = packbf(v0, v1);
    }
    for (int i = t; i < 64 * 32; i += NTHR) {
        int n = i / 32, kp = i - n * 32, k = kp * 2;
        w2p[n * 33 + kp] = packbf(w2[n * 64 + k], w2[n * 64 + k + 1]);
    }
    for (int i = t; i < 32 * 32; i += NTHR) {
        int n = i >> 5, kp = i & 31;
        wcb[n * 33 + kp] = packbf(wcmp[n * 64 + 2 * kp], wcmp[n * 64 + 2 * kp + 1]);
    }
    for (int i = t; i < 64 * 16; i += NTHR) {
        int n = i >> 4, kp = i & 15;
        int ed0 = 2 * kp, ed1 = 2 * kp + 1;
        float v0 = wexp[(((ed0 >> 3) * 64) + n) * 8 + (ed0 & 7)];
        float v1 = wexp[(((ed1 >> 3) * 64) + n) * 8 + (ed1 & 7)];
        web[n * 17 + kp] = packbf(v0, v1);
    }
    if (t < 256) wrs[t] = wr[t];
    if (t < 128) wos[t] = wo[t];
    if (t < 64) { b1s[t] = b1[t]; b2s[t] = b2[t]; }
    if (t < 4) brs[t] = br[t];
    if (t < 2) bos[t] = bo[t];

    const float inv127 = 2.0f / 127.0f;

    // ---- phase 1a: stage + vertical lerp -> strip[c][j], 64x34 ----
    float gx_blk = ((ox0 + 0.5f) / 2.0f - 0.5f) * inv127 - 1.0f;
    float fx_blk = ((gx_blk + 1.0f) * (float)W - 1.0f) * 0.5f;
    const int m_blk = (int)floorf(fx_blk);
    {
        float gy = ((oy + 0.5f) / 2.0f - 0.5f) * inv127 - 1.0f;
        float fy = ((gy + 1.0f) * (float)H - 1.0f) * 0.5f;
        float y0f = floorf(fy);
        float wy1 = fy - y0f, wy0 = 1.0f - wy1;
        int y0 = (int)y0f;
        bool vy0 = (y0 >= 0) && (y0 <= H - 1);
        bool vy1 = (y0 >= -1) && (y0 <= H - 2);
        int yi0 = min(max(y0, 0), H - 1);
        int yi1 = min(max(y0 + 1, 0), H - 1);
        #pragma unroll 1
        for (int i = t; i < 64 * 34; i += NTHR) {
            int c = i / 34, j = i - c * 34;
            int xs = m_blk + j;
            bool vx = (xs >= 0) && (xs <= W - 1);
            int xc = min(max(xs, 0), W - 1);
            const float* base = xb + c * (H * W);
            float v0 = (vx && vy0) ? __ldg(base + yi0 * W + xc) : 0.0f;
            float v1 = (vx && vy1) ? __ldg(base + yi1 * W + xc) : 0.0f;
            strip[c * 34 + j] = v0 * wy0 + v1 * wy1;
        }
    }
    __syncthreads();

    // ---- phase 1b: horizontal lerp + coords -> A1 bf16 [p][88] ----
    {
        const int p  = t & 63;
        const int cb = t >> 6;
        const int ox = ox0 + p;
        float gx = ((ox + 0.5f) / 2.0f - 0.5f) * inv127 - 1.0f;
        float fx = ((gx + 1.0f) * (float)W - 1.0f) * 0.5f;
        float x0f = floorf(fx);
        float wx1 = fx - x0f, wx0 = 1.0f - wx1;
        int j0 = (int)x0f - m_blk;
        char* a1 = smc + A1_OFF + p * 176;
        #define A1PAIR(col, v0, v1) \
            (*(uint32_t*)(a1 + (col) * 2) = packbf((v0), (v1)))
        if (cb == 0) {
            float ah = (oy + 0.5f) / 2.0f;
            float aw = (ox + 0.5f) / 2.0f;
            A1PAIR(0, 0.5f, 0.5f);
            A1PAIR(2, ah - floorf(ah + 0.001f) - 0.5f, aw - floorf(aw + 0.001f) - 0.5f);
        }
        #pragma unroll 1
        for (int c2 = 0; c2 < 8; c2++) {
            int ch = cb * 16 + 2 * c2;
            float u0 = strip[ch * 34 + j0] * wx0 + strip[ch * 34 + j0 + 1] * wx1;
            float u1 = strip[(ch + 1) * 34 + j0] * wx0 + strip[(ch + 1) * 34 + j0 + 1] * wx1;
            A1PAIR(4 + ch, u0, u1);
        }
        if (cb == 3) {
            #pragma unroll
            for (int z = 68; z < 80; z += 2) A1PAIR(z, 0.0f, 0.0f);
        }
        #undef A1PAIR
    }
    __syncthreads();

    const int mt = wid >> 1;
    const int nh = wid & 1;
    const int r0 = lane >> 2;
    const int q  = lane & 3;

    // ---- layer1: hid = relu(A1 . w1^T + b1) ----
    {
        float acc[4][4];
        #pragma unroll
        for (int nt = 0; nt < 4; nt++)
            #pragma unroll
            for (int i = 0; i < 4; i++) acc[nt][i] = 0.0f;
        #pragma unroll
        for (int kc = 0; kc < 5; kc++) {
            uint32_t a[4];
            ldmat4(a, smb + A1_OFF +
                   (uint32_t)(((mt * 16 + (lane & 15)) * 88 + kc * 16 + (lane >> 4) * 8) * 2));
            #pragma unroll
            for (int nt = 0; nt < 4; nt++) {
                int n = nh * 32 + nt * 8 + r0;
                uint32_t b0 = w1p[n * 41 + kc * 8 + q];
                uint32_t b1f = w1p[n * 41 + kc * 8 + q + 4];
                mma16816(acc[nt], a, b0, b1f);
            }
        }
        #pragma unroll
        for (int nt = 0; nt < 4; nt++) {
            int c0 = nh * 32 + nt * 8 + q * 2;
            float bb0 = b1s[c0], bb1 = b1s[c0 + 1];
            uint32_t lo = packbf(fmaxf(acc[nt][0] + bb0, 0.0f), fmaxf(acc[nt][1] + bb1, 0.0f));
            uint32_t hi = packbf(fmaxf(acc[nt][2] + bb0, 0.0f), fmaxf(acc[nt][3] + bb1, 0.0f));
            *(uint32_t*)(smc + HID_OFF + ((mt * 16 + r0) * 72 + c0) * 2)     = lo;
            *(uint32_t*)(smc + HID_OFF + ((mt * 16 + r0 + 8) * 72 + c0) * 2) = hi;
        }
    }
    __syncthreads();

    // ---- layer2: emb = relu(hid . w2^T + b2) -> fp32 (aliases strip; strip dead) ----
    {
        float acc[4][4];
        #pragma unroll
        for (int nt = 0; nt < 4; nt++)
            #pragma unroll
            for (int i = 0; i < 4; i++) acc[nt][i] = 0.0f;
        #pragma unroll
        for (int kc = 0; kc < 4; kc++) {
            uint32_t a[4];
            ldmat4(a, smb + HID_OFF +
                   (uint32_t)(((mt * 16 + (lane & 15)) * 72 + kc * 16 + (lane >> 4) * 8) * 2));
            #pragma unroll
            for (int nt = 0; nt < 4; nt++) {
                int n = nh * 32 + nt * 8 + r0;
                uint32_t b0 = w2p[n * 33 + kc * 8 + q];
                uint32_t b1f = w2p[n * 33 + kc * 8 + q + 4];
                mma16816(acc[nt], a, b0, b1f);
            }
        }
        #pragma unroll
        for (int nt = 0; nt < 4; nt++) {
            int c0 = nh * 32 + nt * 8 + q * 2;
            float bb0 = b2s[c0], bb1 = b2s[c0 + 1];
            float2 lo = make_float2(fmaxf(acc[nt][0] + bb0, 0.0f), fmaxf(acc[nt][1] + bb1, 0.0f));
            float2 hi = make_float2(fmaxf(acc[nt][2] + bb0, 0.0f), fmaxf(acc[nt][3] + bb1, 0.0f));
            *(float2*)(emb + (mt * 16 + r0) * 68 + c0)     = lo;
            *(float2*)(emb + (mt * 16 + r0 + 8) * 68 + c0) = hi;
        }
    }
    __syncthreads();

    // ---- phase 4: r (sigmoid) + offsets -> smem ----
    {
        const int p = t >> 2, e = t & 3;
        const float* erow = emb + p * 68;
        const float* wrr = wrs + e * 64;
        const float* wor = wos + (e & 1) * 64;
        u64t rA = 0ull, rB = 0ull, oA = 0ull, oB = 0ull;
        #pragma unroll
        for (int i = 0; i < 16; i++) {
            ulonglong2 ev  = ld2u(erow + i * 4);
            ulonglong2 wrv = ld2u(wrr + i * 4);
            ulonglong2 wov = ld2u(wor + i * 4);
            rA = fma2(wrv.x, ev.x, rA);
            rB = fma2(wrv.y, ev.y, rB);
            oA = fma2(wov.x, ev.x, oA);
            oB = fma2(wov.y, ev.y, oB);
        }
        float accR = hadd2(rA) + hadd2(rB) + brs[e];
        rs_s[p * 4 + e] = 1.0f / (1.0f + __expf(-accR));
        if (e < 2) of_s[p * 2 + e] = hadd2(oA) + hadd2(oB) + bos[e];
    }
    __syncthreads();

    // ---- phase 5 coeffs: one thread per pixel (validity folded into weights) ----
    if (t < 64) {
        const int p = t;
        const int ox = ox0 + p;
        float gx = ((ox + 0.5f) / 2.0f - 0.5f) * inv127 - 1.0f;
        float gy = ((oy + 0.5f) / 2.0f - 0.5f) * inv127 - 1.0f;
        float ix = gx + of_s[p * 2 + 0] * inv127;
        float iy = gy + of_s[p * 2 + 1] * inv127;
        float fx = ((ix + 1.0f) * (float)W - 1.0f) * 0.5f;
        float fy = ((iy + 1.0f) * (float)H - 1.0f) * 0.5f;
        float x0f = floorf(fx), y0f = floorf(fy);
        float wx1 = fx - x0f, wy1 = fy - y0f;
        float wx0 = 1.0f - wx1, wy0 = 1.0f - wy1;
        int x0 = (int)x0f, y0 = (int)y0f;
        bool vx0 = (x0f >= 0.0f) && (x0f <= (float)(W - 1));
        bool vx1 = (x0f >= -1.0f) && (x0f <= (float)(W - 2));
        bool vy0 = (y0f >= 0.0f) && (y0f <= (float)(H - 1));
        bool vy1 = (y0f >= -1.0f) && (y0f <= (float)(H - 2));
        int xi0 = min(max(x0, 0), W - 1), yi0 = min(max(y0, 0), H - 1);
        int xi1 = min(max(x0 + 1, 0), W - 1), yi1 = min(max(y0 + 1, 0), H - 1);
        cw[p] = make_float4((vx0 && vy0) ? wx0 * wy0 : 0.0f,
                            (vx1 && vy0) ? wx1 * wy0 : 0.0f,
                            (vx0 && vy1) ? wx0 * wy1 : 0.0f,
                            (vx1 && vy1) ? wx1 * wy1 : 0.0f);
        ci[p] = make_int4(yi0 * W + xi0, yi0 * W + xi1, yi1 * W + xi0, yi1 * W + xi1);
    }
    __syncthreads();

    // ---- phase 5: offset sample -> fea fp32 (aliases emb, emb dead) + feab bf16 ----
    {
        const int p  = t & 63;
        const int cb = t >> 6;
        float4 w4 = cw[p];
        int4   i4 = ci[p];
        #pragma unroll 1
        for (int k4 = 0; k4 < 4; k4++) {
            float4 v;
            #pragma unroll
            for (int kk = 0; kk < 4; kk++) {
                int c = cb * 16 + k4 * 4 + kk;
                const float* base = xb + c * (H * W);
                ((float*)&v)[kk] = w4.x * __ldg(base + i4.x) + w4.y * __ldg(base + i4.y)
                                 + w4.z * __ldg(base + i4.z) + w4.w * __ldg(base + i4.w);
            }
            *reinterpret_cast<float4*>(&fea[p * FEA_S + cb * 16 + k4 * 4]) = v;
            uint2 pk = make_uint2(packbf(v.x, v.y), packbf(v.z, v.w));
            *(uint2*)(smc + FB_OFF + (p * 72 + cb * 16 + k4 * 4) * 2) = pk;
        }
    }
    __syncthreads();

    // ---- G1: T[64,32] = feab . wc^T ----
    {
        float acc[2][4];
        #pragma unroll
        for (int nt = 0; nt < 2; nt++)
            #pragma unroll
            for (int i = 0; i < 4; i++) acc[nt][i] = 0.0f;
        #pragma unroll
        for (int kc = 0; kc < 4; kc++) {
            uint32_t a[4];
            ldmat4(a, smb + FB_OFF +
                   (uint32_t)(((mt * 16 + (lane & 15)) * 72 + kc * 16 + (lane >> 4) * 8) * 2));
            #pragma unroll
            for (int nt = 0; nt < 2; nt++) {
                int n = nh * 16 + nt * 8 + r0;
                uint32_t b0 = wcb[n * 33 + kc * 8 + q];
                uint32_t b1f = wcb[n * 33 + kc * 8 + q + 4];
                mma16816(acc[nt], a, b0, b1f);
            }
        }
        #pragma unroll
        for (int nt = 0; nt < 2; nt++) {
            int c0 = nh * 16 + nt * 8 + q * 2;
            *(float2*)(Ts + (mt * 16 + r0) * 36 + c0)     = make_float2(acc[nt][0], acc[nt][1]);
            *(float2*)(Ts + (mt * 16 + r0 + 8) * 36 + c0) = make_float2(acc[nt][2], acc[nt][3]);
        }
    }
    __syncthreads();

    // ---- glue: comp_d = sum_e r_e T[e*8+d]; u = r_e*comp_d -> bf16 (aliases w1p) ----
    if (t < 64) {
        float4 rv = ld4(&rs_s[t * 4]);
        float Tv[32];
        #pragma unroll
        for (int i = 0; i < 8; i++)
            *reinterpret_cast<float4*>(&Tv[i * 4]) = ld4(&Ts[t * 36 + i * 4]);
        float comp[8];
        #pragma unroll
        for (int d = 0; d < 8; d++)
            comp[d] = rv.x * Tv[d] + rv.y * Tv[8 + d] + rv.z * Tv[16 + d] + rv.w * Tv[24 + d];
        uint32_t up[16];
        #pragma unroll
        for (int e = 0; e < 4; e++) {
            float re = ((const float*)&rv)[e];
            #pragma unroll
            for (int dp = 0; dp < 4; dp++)
                up[e * 4 + dp] = packbf(re * comp[2 * dp], re * comp[2 * dp + 1]);
        }
        #pragma unroll
        for (int i = 0; i < 4; i++)
            *(uint4*)(smc + UB_OFF + t * 80 + i * 16) = *reinterpret_cast<uint4*>(&up[i * 4]);
    }
    __syncthreads();

    // ---- G2: corr = u . wexp'^T ; out = fea + corr ----
    {
        float acc[4][4];
        #pragma unroll
        for (int nt = 0; nt < 4; nt++)
            #pragma unroll
            for (int i = 0; i < 4; i++) acc[nt][i] = 0.0f;
        #pragma unroll
        for (int kc = 0; kc < 2; kc++) {
            uint32_t a[4];
            ldmat4(a, smb + UB_OFF +
                   (uint32_t)(((mt * 16 + (lane & 15)) * 40 + kc * 16 + (lane >> 4) * 8) * 2));
            #pragma unroll
            for (int nt = 0; nt < 4; nt++) {
                int n = nh * 32 + nt * 8 + r0;
                uint32_t b0 = web[n * 17 + kc * 8 + q];
                uint32_t b1f = web[n * 17 + kc * 8 + q + 4];
                mma16816(acc[nt], a, b0, b1f);
            }
        }
        const int p0 = mt * 16 + r0, p1 = p0 + 8;
        #pragma unroll
        for (int nt = 0; nt < 4; nt++) {
            int c0 = nh * 32 + nt * 8 + q * 2;
            float2 f0 = *(const float2*)(fea + p0 * FEA_S + c0);
            float2 f1 = *(const float2*)(fea + p1 * FEA_S + c0);
            size_t base0 = (((size_t)bz * C + c0) * OUT + oy) * OUT + ox0;
            size_t base1 = base0 + (size_t)OUT * OUT;
            out[base0 + p0] = f0.x + acc[nt][0];
            out[base1 + p0] = f0.y + acc[nt][1];
            out[base0 + p1] = f1.x + acc[nt][2];
            out[base1 + p1] = f1.y + acc[nt][3];
        }
    }
}

extern "C" void kernel_launch(void* const* d_in, const int* in_sizes, int n_in,
                              void* d_out, int out_size) {
    (void)in_sizes; (void)n_in; (void)out_size;
    const float* x    = (const float*)d_in[0];
    const float* wcmp = (const float*)d_in[1];
    const float* wexp = (const float*)d_in[2];
    const float* w1   = (const float*)d_in[3];
    const float* b1   = (const float*)d_in[4];
    const float* w2   = (const float*)d_in[5];
    const float* b2   = (const float*)d_in[6];
    const float* wr   = (const float*)d_in[7];
    const float* br   = (const float*)d_in[8];
    const float* wo   = (const float*)d_in[9];
    const float* bo   = (const float*)d_in[10];
    float* out = (float*)d_out;

    cudaFuncSetAttribute(scab_fused, cudaFuncAttributeMaxDynamicSharedMemorySize, SMEM_TOTAL);
    dim3 grid(OUT / TILE, OUT, Bz);
    scab_fused<<<grid, NTHR, SMEM_TOTAL>>>(x, wcmp, wexp, w1, b1, w2, b2, wr, br, wo, bo, out);
}

// round 14
// speedup vs baseline: 3.4127x; 1.2336x over previous
#include <cuda_runtime.h>
#include <cuda_bf16.h>
#include <cstdint>
#include <math.h>

// Problem constants (fixed by setup_inputs)
#define Bz   2
#define C    64
#define H    128
#define W    128
#define OUT  256
#define TILE 64
#define NTHR 256
#define NTILES (Bz * OUT * (OUT / TILE))   // 2048
#define NBLK 444                           // 148 SMs x 3 resident blocks

// ================= fused smem layout (bytes) =================
// persistent region (staged once per block)
#define WCB_OFF 0        // u32 wc pairs [32][33] = 4224
#define WEB_OFF 4224     // u32 wexp' pairs [64][17] = 4352
#define WRS_OFF 8576     // fp32 wr [4][64] = 1024
#define WOS_OFF 9600     // fp32 wo [2][64] = 512
#define B1S_OFF 10112    // fp32 [64]
#define B2S_OFF 10368    // fp32 [64]
#define BRS_OFF 10624    // fp32 [4]
#define BOS_OFF 10640    // fp32 [2]
#define RS_OFF  10656    // fp32 rs[64][4] = 1024
#define OF_OFF  11680    // fp32 offs[64][2] = 512
#define CW_OFF  12192    // float4 cw[64] = 1024
#define CI_OFF  13216    // int4 ci[64] = 1024
#define W1P_OFF 14336    // u32 w1 pairs [64][41] = 10496 (persistent)
#define W2P_OFF 24832    // u32 w2 pairs [64][33] = 8448  (persistent)
#define DYN     33280
// dynamic region (per-tile, phases alias)
#define E_OFF   (DYN + 0)       // fp32 strip[64][34] / emb[64][68] / fea[64][68] = 17408
#define A1_OFF  (DYN + 17408)   // bf16 A1 [64 x 88] = 11264 ; feab [64 x 72] ; then u [64 x 40]
#define HID_OFF (DYN + 28672)   // bf16 hid [64 x 72] = 9216 ; later fp32 T [64][36]
#define FB_OFF  A1_OFF
#define UB_OFF  A1_OFF          // u aliases feab (dead after G1; rewritten next iter after sync)
#define T_OFF   HID_OFF
#define SMEM_TOTAL 71168        // DYN (33280) + dynamic (37888)
#define FEA_S 68

typedef unsigned long long u64t;

__device__ __forceinline__ float4 ld4(const float* p) { return *reinterpret_cast<const float4*>(p); }
__device__ __forceinline__ ulonglong2 ld2u(const float* p) { return *reinterpret_cast<const ulonglong2*>(p); }

__device__ __forceinline__ uint32_t smem_to_u32(const void* p) {
    uint32_t a;
    asm("{ .reg .u64 t; cvta.to.shared.u64 t, %1; cvt.u32.u64 %0, t; }" : "=r"(a) : "l"(p));
    return a;
}
__device__ __forceinline__ uint32_t packbf(float lo, float hi) {
    uint32_t r; asm("cvt.rn.bf16x2.f32 %0, %1, %2;" : "=r"(r) : "f"(hi), "f"(lo)); return r;
}
__device__ __forceinline__ u64t fma2(u64t a, u64t b, u64t c) {
    u64t d; asm("fma.rn.f32x2 %0, %1, %2, %3;" : "=l"(d) : "l"(a), "l"(b), "l"(c)); return d;
}
__device__ __forceinline__ float hadd2(u64t v) {
    float lo, hi; asm("mov.b64 {%0, %1}, %2;" : "=f"(lo), "=f"(hi) : "l"(v)); return lo + hi;
}

__device__ __forceinline__ void mma16816(float* c, const uint32_t* a, uint32_t b0, uint32_t b1) {
    asm volatile("mma.sync.aligned.m16n8k16.row.col.f32.bf16.bf16.f32 "
        "{%0,%1,%2,%3}, {%4,%5,%6,%7}, {%8,%9}, {%0,%1,%2,%3};"
        : "+f"(c[0]), "+f"(c[1]), "+f"(c[2]), "+f"(c[3])
        : "r"(a[0]), "r"(a[1]), "r"(a[2]), "r"(a[3]), "r"(b0), "r"(b1));
}
__device__ __forceinline__ void ldmat4(uint32_t* a, uint32_t addr) {
    asm volatile("ldmatrix.sync.aligned.m8n8.x4.shared.b16 {%0,%1,%2,%3}, [%4];"
        : "=r"(a[0]), "=r"(a[1]), "=r"(a[2]), "=r"(a[3]) : "r"(addr));
}

// =================== persistent fused kernel: stage once, loop tiles ===================
__global__ __launch_bounds__(NTHR, 3)
void scab_fused(const float* __restrict__ x,
                const float* __restrict__ wcmp, const float* __restrict__ wexp,
                const float* __restrict__ w1, const float* __restrict__ b1,
                const float* __restrict__ w2, const float* __restrict__ b2,
                const float* __restrict__ wr, const float* __restrict__ br,
                const float* __restrict__ wo, const float* __restrict__ bo,
                float* __restrict__ out)
{
    extern __shared__ char smc[];
    float* emb   = (float*)(smc + E_OFF);
    float* strip = (float*)(smc + E_OFF);
    float* fea   = (float*)(smc + E_OFF);
    float* Ts    = (float*)(smc + T_OFF);
    uint32_t* w1p = (uint32_t*)(smc + W1P_OFF);
    uint32_t* w2p = (uint32_t*)(smc + W2P_OFF);
    uint32_t* wcb = (uint32_t*)(smc + WCB_OFF);
    uint32_t* web = (uint32_t*)(smc + WEB_OFF);
    float* wrs  = (float*)(smc + WRS_OFF);
    float* wos  = (float*)(smc + WOS_OFF);
    float* b1s  = (float*)(smc + B1S_OFF);
    float* b2s  = (float*)(smc + B2S_OFF);
    float* brs  = (float*)(smc + BRS_OFF);
    float* bos  = (float*)(smc + BOS_OFF);
    float* rs_s = (float*)(smc + RS_OFF);
    float* of_s = (float*)(smc + OF_OFF);
    float4* cw  = (float4*)(smc + CW_OFF);
    int4*   ci  = (int4*)(smc + CI_OFF);
    const uint32_t smb = smem_to_u32(smc);

    const int t = threadIdx.x;
    const int wid = t >> 5;
    const int lane = t & 31;

    // ---- stage ALL weights ONCE per block ----
    for (int i = t; i < 64 * 40; i += NTHR) {
        int n = i / 40, kp = i - n * 40, k = kp * 2;
        float v0 = (k     < 68) ? w1[n * 68 + k    ] : 0.0f;
        float v1 = (k + 1 < 68) ? w1[n * 68 + k + 1] : 0.0f;
        w1p[n * 41 + kp] = packbf(v0, v1);
    }
    for (int i = t; i < 64 * 32; i += NTHR) {
        int n = i / 32, kp = i - n * 32, k = kp * 2;
        w2p[n * 33 + kp] = packbf(w2[n * 64 + k], w2[n * 64 + k + 1]);
    }
    for (int i = t; i < 32 * 32; i += NTHR) {
        int n = i >> 5, kp = i & 31;
        wcb[n * 33 + kp] = packbf(wcmp[n * 64 + 2 * kp], wcmp[n * 64 + 2 * kp + 1]);
    }
    for (int i = t; i < 64 * 16; i += NTHR) {
        int n = i >> 4, kp = i & 15;
        int ed0 = 2 * kp, ed1 = 2 * kp + 1;
        float v0 = wexp[(((ed0 >> 3) * 64) + n) * 8 + (ed0 & 7)];
        float v1 = wexp[(((ed1 >> 3) * 64) + n) * 8 + (ed1 & 7)];
        web[n * 17 + kp] = packbf(v0, v1);
    }
    if (t < 256) wrs[t] = wr[t];
    if (t < 128) wos[t] = wo[t];
    if (t < 64) { b1s[t] = b1[t]; b2s[t] = b2[t]; }
    if (t < 4) brs[t] = br[t];
    if (t < 2) bos[t] = bo[t];
    __syncthreads();

    const float inv127 = 2.0f / 127.0f;
    const int mt = wid >> 1;
    const int nh = wid & 1;
    const int r0 = lane >> 2;
    const int q  = lane & 3;

    // ---- persistent loop over tiles ----
    for (int tile = blockIdx.x; tile < NTILES; tile += NBLK) {
        const int ox0 = (tile & 3) * TILE;
        const int oy  = (tile >> 2) & 255;
        const int bz  = tile >> 10;
        const float* xb = x + (size_t)bz * C * H * W;

        // ---- phase 1a: stage + vertical lerp -> strip[c][j], 64x34 ----
        float gx_blk = ((ox0 + 0.5f) / 2.0f - 0.5f) * inv127 - 1.0f;
        float fx_blk = ((gx_blk + 1.0f) * (float)W - 1.0f) * 0.5f;
        const int m_blk = (int)floorf(fx_blk);
        {
            float gy = ((oy + 0.5f) / 2.0f - 0.5f) * inv127 - 1.0f;
            float fy = ((gy + 1.0f) * (float)H - 1.0f) * 0.5f;
            float y0f = floorf(fy);
            float wy1 = fy - y0f, wy0 = 1.0f - wy1;
            int y0 = (int)y0f;
            bool vy0 = (y0 >= 0) && (y0 <= H - 1);
            bool vy1 = (y0 >= -1) && (y0 <= H - 2);
            int yi0 = min(max(y0, 0), H - 1);
            int yi1 = min(max(y0 + 1, 0), H - 1);
            #pragma unroll 1
            for (int i = t; i < 64 * 34; i += NTHR) {
                int c = i / 34, j = i - c * 34;
                int xs = m_blk + j;
                bool vx = (xs >= 0) && (xs <= W - 1);
                int xc = min(max(xs, 0), W - 1);
                const float* base = xb + c * (H * W);
                float v0 = (vx && vy0) ? __ldg(base + yi0 * W + xc) : 0.0f;
                float v1 = (vx && vy1) ? __ldg(base + yi1 * W + xc) : 0.0f;
                strip[c * 34 + j] = v0 * wy0 + v1 * wy1;
            }
        }
        __syncthreads();

        // ---- phase 1b: horizontal lerp + coords -> A1 bf16 [p][88] ----
        {
            const int p  = t & 63;
            const int cb = t >> 6;
            const int ox = ox0 + p;
            float gx = ((ox + 0.5f) / 2.0f - 0.5f) * inv127 - 1.0f;
            float fx = ((gx + 1.0f) * (float)W - 1.0f) * 0.5f;
            float x0f = floorf(fx);
            float wx1 = fx - x0f, wx0 = 1.0f - wx1;
            int j0 = (int)x0f - m_blk;
            char* a1 = smc + A1_OFF + p * 176;
            #define A1PAIR(col, v0, v1) \
                (*(uint32_t*)(a1 + (col) * 2) = packbf((v0), (v1)))
            if (cb == 0) {
                float ah = (oy + 0.5f) / 2.0f;
                float aw = (ox + 0.5f) / 2.0f;
                A1PAIR(0, 0.5f, 0.5f);
                A1PAIR(2, ah - floorf(ah + 0.001f) - 0.5f, aw - floorf(aw + 0.001f) - 0.5f);
            }
            #pragma unroll 1
            for (int c2 = 0; c2 < 8; c2++) {
                int ch = cb * 16 + 2 * c2;
                float u0 = strip[ch * 34 + j0] * wx0 + strip[ch * 34 + j0 + 1] * wx1;
                float u1 = strip[(ch + 1) * 34 + j0] * wx0 + strip[(ch + 1) * 34 + j0 + 1] * wx1;
                A1PAIR(4 + ch, u0, u1);
            }
            if (cb == 3) {
                #pragma unroll
                for (int z = 68; z < 80; z += 2) A1PAIR(z, 0.0f, 0.0f);
            }
            #undef A1PAIR
        }
        __syncthreads();

        // ---- layer1: hid = relu(A1 . w1^T + b1) ----
        {
            float acc[4][4];
            #pragma unroll
            for (int nt = 0; nt < 4; nt++)
                #pragma unroll
                for (int i = 0; i < 4; i++) acc[nt][i] = 0.0f;
            #pragma unroll
            for (int kc = 0; kc < 5; kc++) {
                uint32_t a[4];
                ldmat4(a, smb + A1_OFF +
                       (uint32_t)(((mt * 16 + (lane & 15)) * 88 + kc * 16 + (lane >> 4) * 8) * 2));
                #pragma unroll
                for (int nt = 0; nt < 4; nt++) {
                    int n = nh * 32 + nt * 8 + r0;
                    uint32_t b0 = w1p[n * 41 + kc * 8 + q];
                    uint32_t b1f = w1p[n * 41 + kc * 8 + q + 4];
                    mma16816(acc[nt], a, b0, b1f);
                }
            }
            #pragma unroll
            for (int nt = 0; nt < 4; nt++) {
                int c0 = nh * 32 + nt * 8 + q * 2;
                float bb0 = b1s[c0], bb1 = b1s[c0 + 1];
                uint32_t lo = packbf(fmaxf(acc[nt][0] + bb0, 0.0f), fmaxf(acc[nt][1] + bb1, 0.0f));
                uint32_t hi = packbf(fmaxf(acc[nt][2] + bb0, 0.0f), fmaxf(acc[nt][3] + bb1, 0.0f));
                *(uint32_t*)(smc + HID_OFF + ((mt * 16 + r0) * 72 + c0) * 2)     = lo;
                *(uint32_t*)(smc + HID_OFF + ((mt * 16 + r0 + 8) * 72 + c0) * 2) = hi;
            }
        }
        __syncthreads();

        // ---- layer2: emb = relu(hid . w2^T + b2) -> fp32 (aliases strip) ----
        {
            float acc[4][4];
            #pragma unroll
            for (int nt = 0; nt < 4; nt++)
                #pragma unroll
                for (int i = 0; i < 4; i++) acc[nt][i] = 0.0f;
            #pragma unroll
            for (int kc = 0; kc < 4; kc++) {
                uint32_t a[4];
                ldmat4(a, smb + HID_OFF +
                       (uint32_t)(((mt * 16 + (lane & 15)) * 72 + kc * 16 + (lane >> 4) * 8) * 2));
                #pragma unroll
                for (int nt = 0; nt < 4; nt++) {
                    int n = nh * 32 + nt * 8 + r0;
                    uint32_t b0 = w2p[n * 33 + kc * 8 + q];
                    uint32_t b1f = w2p[n * 33 + kc * 8 + q + 4];
                    mma16816(acc[nt], a, b0, b1f);
                }
            }
            #pragma unroll
            for (int nt = 0; nt < 4; nt++) {
                int c0 = nh * 32 + nt * 8 + q * 2;
                float bb0 = b2s[c0], bb1 = b2s[c0 + 1];
                float2 lo = make_float2(fmaxf(acc[nt][0] + bb0, 0.0f), fmaxf(acc[nt][1] + bb1, 0.0f));
                float2 hi = make_float2(fmaxf(acc[nt][2] + bb0, 0.0f), fmaxf(acc[nt][3] + bb1, 0.0f));
                *(float2*)(emb + (mt * 16 + r0) * 68 + c0)     = lo;
                *(float2*)(emb + (mt * 16 + r0 + 8) * 68 + c0) = hi;
            }
        }
        __syncthreads();

        // ---- phase 4: r (sigmoid) + offsets -> smem ----
        {
            const int p = t >> 2, e = t & 3;
            const float* erow = emb + p * 68;
            const float* wrr = wrs + e * 64;
            const float* wor = wos + (e & 1) * 64;
            u64t rA = 0ull, rB = 0ull, oA = 0ull, oB = 0ull;
            #pragma unroll
            for (int i = 0; i < 16; i++) {
                ulonglong2 ev  = ld2u(erow + i * 4);
                ulonglong2 wrv = ld2u(wrr + i * 4);
                ulonglong2 wov = ld2u(wor + i * 4);
                rA = fma2(wrv.x, ev.x, rA);
                rB = fma2(wrv.y, ev.y, rB);
                oA = fma2(wov.x, ev.x, oA);
                oB = fma2(wov.y, ev.y, oB);
            }
            float accR = hadd2(rA) + hadd2(rB) + brs[e];
            rs_s[p * 4 + e] = 1.0f / (1.0f + __expf(-accR));
            if (e < 2) of_s[p * 2 + e] = hadd2(oA) + hadd2(oB) + bos[e];
        }
        __syncthreads();

        // ---- phase 5 coeffs: one thread per pixel ----
        if (t < 64) {
            const int p = t;
            const int ox = ox0 + p;
            float gx = ((ox + 0.5f) / 2.0f - 0.5f) * inv127 - 1.0f;
            float gy = ((oy + 0.5f) / 2.0f - 0.5f) * inv127 - 1.0f;
            float ix = gx + of_s[p * 2 + 0] * inv127;
            float iy = gy + of_s[p * 2 + 1] * inv127;
            float fx = ((ix + 1.0f) * (float)W - 1.0f) * 0.5f;
            float fy = ((iy + 1.0f) * (float)H - 1.0f) * 0.5f;
            float x0f = floorf(fx), y0f = floorf(fy);
            float wx1 = fx - x0f, wy1 = fy - y0f;
            float wx0 = 1.0f - wx1, wy0 = 1.0f - wy1;
            int x0 = (int)x0f, y0 = (int)y0f;
            bool vx0 = (x0f >= 0.0f) && (x0f <= (float)(W - 1));
            bool vx1 = (x0f >= -1.0f) && (x0f <= (float)(W - 2));
            bool vy0 = (y0f >= 0.0f) && (y0f <= (float)(H - 1));
            bool vy1 = (y0f >= -1.0f) && (y0f <= (float)(H - 2));
            int xi0 = min(max(x0, 0), W - 1), yi0 = min(max(y0, 0), H - 1);
            int xi1 = min(max(x0 + 1, 0), W - 1), yi1 = min(max(y0 + 1, 0), H - 1);
            cw[p] = make_float4((vx0 && vy0) ? wx0 * wy0 : 0.0f,
                                (vx1 && vy0) ? wx1 * wy0 : 0.0f,
                                (vx0 && vy1) ? wx0 * wy1 : 0.0f,
                                (vx1 && vy1) ? wx1 * wy1 : 0.0f);
            ci[p] = make_int4(yi0 * W + xi0, yi0 * W + xi1, yi1 * W + xi0, yi1 * W + xi1);
        }
        __syncthreads();

        // ---- phase 5: offset sample -> fea fp32 (aliases emb) + feab bf16 ----
        {
            const int p  = t & 63;
            const int cb = t >> 6;
            float4 w4 = cw[p];
            int4   i4 = ci[p];
            #pragma unroll 1
            for (int k4 = 0; k4 < 4; k4++) {
                float4 v;
                #pragma unroll
                for (int kk = 0; kk < 4; kk++) {
                    int c = cb * 16 + k4 * 4 + kk;
                    const float* base = xb + c * (H * W);
                    ((float*)&v)[kk] = w4.x * __ldg(base + i4.x) + w4.y * __ldg(base + i4.y)
                                     + w4.z * __ldg(base + i4.z) + w4.w * __ldg(base + i4.w);
                }
                *reinterpret_cast<float4*>(&fea[p * FEA_S + cb * 16 + k4 * 4]) = v;
                uint2 pk = make_uint2(packbf(v.x, v.y), packbf(v.z, v.w));
                *(uint2*)(smc + FB_OFF + (p * 72 + cb * 16 + k4 * 4) * 2) = pk;
            }
        }
        __syncthreads();

        // ---- G1: T[64,32] = feab . wc^T ----
        {
            float acc[2][4];
            #pragma unroll
            for (int nt = 0; nt < 2; nt++)
                #pragma unroll
                for (int i = 0; i < 4; i++) acc[nt][i] = 0.0f;
            #pragma unroll
            for (int kc = 0; kc < 4; kc++) {
                uint32_t a[4];
                ldmat4(a, smb + FB_OFF +
                       (uint32_t)(((mt * 16 + (lane & 15)) * 72 + kc * 16 + (lane >> 4) * 8) * 2));
                #pragma unroll
                for (int nt = 0; nt < 2; nt++) {
                    int n = nh * 16 + nt * 8 + r0;
                    uint32_t b0 = wcb[n * 33 + kc * 8 + q];
                    uint32_t b1f = wcb[n * 33 + kc * 8 + q + 4];
                    mma16816(acc[nt], a, b0, b1f);
                }
            }
            #pragma unroll
            for (int nt = 0; nt < 2; nt++) {
                int c0 = nh * 16 + nt * 8 + q * 2;
                *(float2*)(Ts + (mt * 16 + r0) * 36 + c0)     = make_float2(acc[nt][0], acc[nt][1]);
                *(float2*)(Ts + (mt * 16 + r0 + 8) * 36 + c0) = make_float2(acc[nt][2], acc[nt][3]);
            }
        }
        __syncthreads();

        // ---- glue: comp_d = sum_e r_e T[e*8+d]; u = r_e*comp_d -> bf16 (aliases feab) ----
        if (t < 64) {
            float4 rv = ld4(&rs_s[t * 4]);
            float Tv[32];
            #pragma unroll
            for (int i = 0; i < 8; i++)
                *reinterpret_cast<float4*>(&Tv[i * 4]) = ld4(&Ts[t * 36 + i * 4]);
            float comp[8];
            #pragma unroll
            for (int d = 0; d < 8; d++)
                comp[d] = rv.x * Tv[d] + rv.y * Tv[8 + d] + rv.z * Tv[16 + d] + rv.w * Tv[24 + d];
            uint32_t up[16];
            #pragma unroll
            for (int e = 0; e < 4; e++) {
                float re = ((const float*)&rv)[e];
                #pragma unroll
                for (int dp = 0; dp < 4; dp++)
                    up[e * 4 + dp] = packbf(re * comp[2 * dp], re * comp[2 * dp + 1]);
            }
            #pragma unroll
            for (int i = 0; i < 4; i++)
                *(uint4*)(smc + UB_OFF + t * 80 + i * 16) = *reinterpret_cast<uint4*>(&up[i * 4]);
        }
        __syncthreads();

        // ---- G2: corr = u . wexp'^T ; out = fea + corr ----
        {
            float acc[4][4];
            #pragma unroll
            for (int nt = 0; nt < 4; nt++)
                #pragma unroll
                for (int i = 0; i < 4; i++) acc[nt][i] = 0.0f;
            #pragma unroll
            for (int kc = 0; kc < 2; kc++) {
                uint32_t a[4];
                ldmat4(a, smb + UB_OFF +
                       (uint32_t)(((mt * 16 + (lane & 15)) * 40 + kc * 16 + (lane >> 4) * 8) * 2));
                #pragma unroll
                for (int nt = 0; nt < 4; nt++) {
                    int n = nh * 32 + nt * 8 + r0;
                    uint32_t b0 = web[n * 17 + kc * 8 + q];
                    uint32_t b1f = web[n * 17 + kc * 8 + q + 4];
                    mma16816(acc[nt], a, b0, b1f);
                }
            }
            const int p0 = mt * 16 + r0, p1 = p0 + 8;
            #pragma unroll
            for (int nt = 0; nt < 4; nt++) {
                int c0 = nh * 32 + nt * 8 + q * 2;
                float2 f0 = *(const float2*)(fea + p0 * FEA_S + c0);
                float2 f1 = *(const float2*)(fea + p1 * FEA_S + c0);
                size_t base0 = (((size_t)bz * C + c0) * OUT + oy) * OUT + ox0;
                size_t base1 = base0 + (size_t)OUT * OUT;
                out[base0 + p0] = f0.x + acc[nt][0];
                out[base1 + p0] = f0.y + acc[nt][1];
                out[base0 + p1] = f1.x + acc[nt][2];
                out[base1 + p1] = f1.y + acc[nt][3];
            }
        }
        __syncthreads();   // protect dynamic-region aliases across loop iterations
    }
}

extern "C" void kernel_launch(void* const* d_in, const int* in_sizes, int n_in,
                              void* d_out, int out_size) {
    (void)in_sizes; (void)n_in; (void)out_size;
    const float* x    = (const float*)d_in[0];
    const float* wcmp = (const float*)d_in[1];
    const float* wexp = (const float*)d_in[2];
    const float* w1   = (const float*)d_in[3];
    const float* b1   = (const float*)d_in[4];
    const float* w2   = (const float*)d_in[5];
    const float* b2   = (const float*)d_in[6];
    const float* wr   = (const float*)d_in[7];
    const float* br   = (const float*)d_in[8];
    const float* wo   = (const float*)d_in[9];
    const float* bo   = (const float*)d_in[10];
    float* out = (float*)d_out;

    cudaFuncSetAttribute(scab_fused, cudaFuncAttributeMaxDynamicSharedMemorySize, SMEM_TOTAL);
    scab_fused<<<NBLK, NTHR, SMEM_TOTAL>>>(x, wcmp, wexp, w1, b1, w2, b2, wr, br, wo, bo, out);
}

// round 15
// speedup vs baseline: 4.4308x; 1.2983x over previous
#include <cuda_runtime.h>
#include <cuda_bf16.h>
#include <cstdint>
#include <math.h>

// Problem constants (fixed by setup_inputs)
#define Bz   2
#define C    64
#define H    128
#define W    128
#define OUT  256
#define TILE 64
#define NTHR 256
#define NTILES (Bz * OUT * (OUT / TILE))   // 2048
#define NBLK 444                           // 148 SMs x 3 resident blocks

// ================= fused smem layout (bytes) =================
// persistent region (staged once per block)
#define WCB_OFF 0        // u32 wc pairs [32][33] = 4224
#define WEB_OFF 4224     // u32 wexp' pairs [64][17] = 4352
#define WHB_OFF 8576     // u32 head pairs [8][33] = 1056  (wr rows 0-3, wo rows 4-5, zero 6-7)
#define B1S_OFF 10112    // fp32 [64]
#define B2S_OFF 10368    // fp32 [64]
#define BRS_OFF 10624    // fp32 [4]
#define BOS_OFF 10640    // fp32 [2]
#define RS_OFF  10656    // fp32 rs[64][4] = 1024
#define OF_OFF  11680    // fp32 offs[64][2] = 512
#define CW_OFF  12192    // float4 cw[64] = 1024
#define CI_OFF  13216    // int4 ci[64] = 1024
#define W1P_OFF 14336    // u32 w1 pairs [64][41] = 10496 (persistent)
#define W2P_OFF 24832    // u32 w2 pairs [64][33] = 8448  (persistent)
#define DYN     33280
// dynamic region (per-tile, phases alias)
#define E_OFF   (DYN + 0)       // fp32 strip[64][34] / bf16 embb[64 x 72] / fp32 fea[64][68] = 17408
#define A1_OFF  (DYN + 17408)   // bf16 A1 [64 x 88] = 11264 ; feab [64 x 72] ; then u [64 x 40]
#define HID_OFF (DYN + 28672)   // bf16 hid [64 x 72] = 9216 ; later fp32 T [64][36]
#define FB_OFF  A1_OFF
#define UB_OFF  A1_OFF          // u aliases feab (dead after G1)
#define T_OFF   HID_OFF
#define SMEM_TOTAL 71168        // DYN (33280) + dynamic (37888)
#define FEA_S 68

typedef unsigned long long u64t;

__device__ __forceinline__ float4 ld4(const float* p) { return *reinterpret_cast<const float4*>(p); }

__device__ __forceinline__ uint32_t smem_to_u32(const void* p) {
    uint32_t a;
    asm("{ .reg .u64 t; cvta.to.shared.u64 t, %1; cvt.u32.u64 %0, t; }" : "=r"(a) : "l"(p));
    return a;
}
__device__ __forceinline__ uint32_t packbf(float lo, float hi) {
    uint32_t r; asm("cvt.rn.bf16x2.f32 %0, %1, %2;" : "=r"(r) : "f"(hi), "f"(lo)); return r;
}

__device__ __forceinline__ void mma16816(float* c, const uint32_t* a, uint32_t b0, uint32_t b1) {
    asm volatile("mma.sync.aligned.m16n8k16.row.col.f32.bf16.bf16.f32 "
        "{%0,%1,%2,%3}, {%4,%5,%6,%7}, {%8,%9}, {%0,%1,%2,%3};"
        : "+f"(c[0]), "+f"(c[1]), "+f"(c[2]), "+f"(c[3])
        : "r"(a[0]), "r"(a[1]), "r"(a[2]), "r"(a[3]), "r"(b0), "r"(b1));
}
__device__ __forceinline__ void ldmat4(uint32_t* a, uint32_t addr) {
    asm volatile("ldmatrix.sync.aligned.m8n8.x4.shared.b16 {%0,%1,%2,%3}, [%4];"
        : "=r"(a[0]), "=r"(a[1]), "=r"(a[2]), "=r"(a[3]) : "r"(addr));
}

// =================== persistent fused kernel ===================
__global__ __launch_bounds__(NTHR, 3)
void scab_fused(const float* __restrict__ x,
                const float* __restrict__ wcmp, const float* __restrict__ wexp,
                const float* __restrict__ w1, const float* __restrict__ b1,
                const float* __restrict__ w2, const float* __restrict__ b2,
                const float* __restrict__ wr, const float* __restrict__ br,
                const float* __restrict__ wo, const float* __restrict__ bo,
                float* __restrict__ out)
{
    extern __shared__ char smc[];
    float* strip = (float*)(smc + E_OFF);
    float* fea   = (float*)(smc + E_OFF);
    float* Ts    = (float*)(smc + T_OFF);
    uint32_t* w1p = (uint32_t*)(smc + W1P_OFF);
    uint32_t* w2p = (uint32_t*)(smc + W2P_OFF);
    uint32_t* wcb = (uint32_t*)(smc + WCB_OFF);
    uint32_t* web = (uint32_t*)(smc + WEB_OFF);
    uint32_t* whb = (uint32_t*)(smc + WHB_OFF);
    float* b1s  = (float*)(smc + B1S_OFF);
    float* b2s  = (float*)(smc + B2S_OFF);
    float* brs  = (float*)(smc + BRS_OFF);
    float* bos  = (float*)(smc + BOS_OFF);
    float* rs_s = (float*)(smc + RS_OFF);
    float* of_s = (float*)(smc + OF_OFF);
    float4* cw  = (float4*)(smc + CW_OFF);
    int4*   ci  = (int4*)(smc + CI_OFF);
    const uint32_t smb = smem_to_u32(smc);

    const int t = threadIdx.x;
    const int wid = t >> 5;
    const int lane = t & 31;

    // ---- stage ALL weights ONCE per block ----
    for (int i = t; i < 64 * 40; i += NTHR) {
        int n = i / 40, kp = i - n * 40, k = kp * 2;
        float v0 = (k     < 68) ? w1[n * 68 + k    ] : 0.0f;
        float v1 = (k + 1 < 68) ? w1[n * 68 + k + 1] : 0.0f;
        w1p[n * 41 + kp] = packbf(v0, v1);
    }
    for (int i = t; i < 64 * 32; i += NTHR) {
        int n = i / 32, kp = i - n * 32, k = kp * 2;
        w2p[n * 33 + kp] = packbf(w2[n * 64 + k], w2[n * 64 + k + 1]);
    }
    for (int i = t; i < 32 * 32; i += NTHR) {
        int n = i >> 5, kp = i & 31;
        wcb[n * 33 + kp] = packbf(wcmp[n * 64 + 2 * kp], wcmp[n * 64 + 2 * kp + 1]);
    }
    for (int i = t; i < 64 * 16; i += NTHR) {
        int n = i >> 4, kp = i & 15;
        int ed0 = 2 * kp, ed1 = 2 * kp + 1;
        float v0 = wexp[(((ed0 >> 3) * 64) + n) * 8 + (ed0 & 7)];
        float v1 = wexp[(((ed1 >> 3) * 64) + n) * 8 + (ed1 & 7)];
        web[n * 17 + kp] = packbf(v0, v1);
    }
    if (t < 256) {  // head weights: rows 0-3 = wr, 4-5 = wo, 6-7 = 0
        int n = t >> 5, kp = t & 31, k = kp * 2;
        float v0 = 0.0f, v1 = 0.0f;
        if (n < 4)      { v0 = wr[n * 64 + k];       v1 = wr[n * 64 + k + 1]; }
        else if (n < 6) { v0 = wo[(n - 4) * 64 + k]; v1 = wo[(n - 4) * 64 + k + 1]; }
        whb[n * 33 + kp] = packbf(v0, v1);
    }
    if (t < 64) { b1s[t] = b1[t]; b2s[t] = b2[t]; }
    if (t < 4) brs[t] = br[t];
    if (t < 2) bos[t] = bo[t];
    __syncthreads();

    const float inv127 = 2.0f / 127.0f;
    const int mt = wid >> 1;
    const int nh = wid & 1;
    const int r0 = lane >> 2;
    const int q  = lane & 3;

    // ---- persistent loop over tiles ----
    for (int tile = blockIdx.x; tile < NTILES; tile += NBLK) {
        const int ox0 = (tile & 3) * TILE;
        const int oy  = (tile >> 2) & 255;
        const int bz  = tile >> 10;
        const float* xb = x + (size_t)bz * C * H * W;

        // ---- phase 1a: stage + vertical lerp -> strip[c][j], 64x34 ----
        float gx_blk = ((ox0 + 0.5f) / 2.0f - 0.5f) * inv127 - 1.0f;
        float fx_blk = ((gx_blk + 1.0f) * (float)W - 1.0f) * 0.5f;
        const int m_blk = (int)floorf(fx_blk);
        {
            float gy = ((oy + 0.5f) / 2.0f - 0.5f) * inv127 - 1.0f;
            float fy = ((gy + 1.0f) * (float)H - 1.0f) * 0.5f;
            float y0f = floorf(fy);
            float wy1 = fy - y0f, wy0 = 1.0f - wy1;
            int y0 = (int)y0f;
            bool vy0 = (y0 >= 0) && (y0 <= H - 1);
            bool vy1 = (y0 >= -1) && (y0 <= H - 2);
            int yi0 = min(max(y0, 0), H - 1);
            int yi1 = min(max(y0 + 1, 0), H - 1);
            #pragma unroll 1
            for (int i = t; i < 64 * 34; i += NTHR) {
                int c = i / 34, j = i - c * 34;
                int xs = m_blk + j;
                bool vx = (xs >= 0) && (xs <= W - 1);
                int xc = min(max(xs, 0), W - 1);
                const float* base = xb + c * (H * W);
                float v0 = (vx && vy0) ? __ldg(base + yi0 * W + xc) : 0.0f;
                float v1 = (vx && vy1) ? __ldg(base + yi1 * W + xc) : 0.0f;
                strip[c * 34 + j] = v0 * wy0 + v1 * wy1;
            }
        }
        __syncthreads();

        // ---- phase 1b: horizontal lerp + coords -> A1 bf16 [p][88] ----
        {
            const int p  = t & 63;
            const int cb = t >> 6;
            const int ox = ox0 + p;
            float gx = ((ox + 0.5f) / 2.0f - 0.5f) * inv127 - 1.0f;
            float fx = ((gx + 1.0f) * (float)W - 1.0f) * 0.5f;
            float x0f = floorf(fx);
            float wx1 = fx - x0f, wx0 = 1.0f - wx1;
            int j0 = (int)x0f - m_blk;
            char* a1 = smc + A1_OFF + p * 176;
            #define A1PAIR(col, v0, v1) \
                (*(uint32_t*)(a1 + (col) * 2) = packbf((v0), (v1)))
            if (cb == 0) {
                float ah = (oy + 0.5f) / 2.0f;
                float aw = (ox + 0.5f) / 2.0f;
                A1PAIR(0, 0.5f, 0.5f);
                A1PAIR(2, ah - floorf(ah + 0.001f) - 0.5f, aw - floorf(aw + 0.001f) - 0.5f);
            }
            #pragma unroll 1
            for (int c2 = 0; c2 < 8; c2++) {
                int ch = cb * 16 + 2 * c2;
                float u0 = strip[ch * 34 + j0] * wx0 + strip[ch * 34 + j0 + 1] * wx1;
                float u1 = strip[(ch + 1) * 34 + j0] * wx0 + strip[(ch + 1) * 34 + j0 + 1] * wx1;
                A1PAIR(4 + ch, u0, u1);
            }
            if (cb == 3) {
                #pragma unroll
                for (int z = 68; z < 80; z += 2) A1PAIR(z, 0.0f, 0.0f);
            }
            #undef A1PAIR
        }
        __syncthreads();

        // ---- layer1: hid = relu(A1 . w1^T + b1) ----
        {
            float acc[4][4];
            #pragma unroll
            for (int nt = 0; nt < 4; nt++)
                #pragma unroll
                for (int i = 0; i < 4; i++) acc[nt][i] = 0.0f;
            #pragma unroll
            for (int kc = 0; kc < 5; kc++) {
                uint32_t a[4];
                ldmat4(a, smb + A1_OFF +
                       (uint32_t)(((mt * 16 + (lane & 15)) * 88 + kc * 16 + (lane >> 4) * 8) * 2));
                #pragma unroll
                for (int nt = 0; nt < 4; nt++) {
                    int n = nh * 32 + nt * 8 + r0;
                    uint32_t b0 = w1p[n * 41 + kc * 8 + q];
                    uint32_t b1f = w1p[n * 41 + kc * 8 + q + 4];
                    mma16816(acc[nt], a, b0, b1f);
                }
            }
            #pragma unroll
            for (int nt = 0; nt < 4; nt++) {
                int c0 = nh * 32 + nt * 8 + q * 2;
                float bb0 = b1s[c0], bb1 = b1s[c0 + 1];
                uint32_t lo = packbf(fmaxf(acc[nt][0] + bb0, 0.0f), fmaxf(acc[nt][1] + bb1, 0.0f));
                uint32_t hi = packbf(fmaxf(acc[nt][2] + bb0, 0.0f), fmaxf(acc[nt][3] + bb1, 0.0f));
                *(uint32_t*)(smc + HID_OFF + ((mt * 16 + r0) * 72 + c0) * 2)     = lo;
                *(uint32_t*)(smc + HID_OFF + ((mt * 16 + r0 + 8) * 72 + c0) * 2) = hi;
            }
        }
        __syncthreads();

        // ---- layer2: embb = relu(hid . w2^T + b2) -> bf16 [64 x 72] (aliases strip) ----
        {
            float acc[4][4];
            #pragma unroll
            for (int nt = 0; nt < 4; nt++)
                #pragma unroll
                for (int i = 0; i < 4; i++) acc[nt][i] = 0.0f;
            #pragma unroll
            for (int kc = 0; kc < 4; kc++) {
                uint32_t a[4];
                ldmat4(a, smb + HID_OFF +
                       (uint32_t)(((mt * 16 + (lane & 15)) * 72 + kc * 16 + (lane >> 4) * 8) * 2));
                #pragma unroll
                for (int nt = 0; nt < 4; nt++) {
                    int n = nh * 32 + nt * 8 + r0;
                    uint32_t b0 = w2p[n * 33 + kc * 8 + q];
                    uint32_t b1f = w2p[n * 33 + kc * 8 + q + 4];
                    mma16816(acc[nt], a, b0, b1f);
                }
            }
            #pragma unroll
            for (int nt = 0; nt < 4; nt++) {
                int c0 = nh * 32 + nt * 8 + q * 2;
                float bb0 = b2s[c0], bb1 = b2s[c0 + 1];
                uint32_t lo = packbf(fmaxf(acc[nt][0] + bb0, 0.0f), fmaxf(acc[nt][1] + bb1, 0.0f));
                uint32_t hi = packbf(fmaxf(acc[nt][2] + bb0, 0.0f), fmaxf(acc[nt][3] + bb1, 0.0f));
                *(uint32_t*)(smc + E_OFF + ((mt * 16 + r0) * 72 + c0) * 2)     = lo;
                *(uint32_t*)(smc + E_OFF + ((mt * 16 + r0 + 8) * 72 + c0) * 2) = hi;
            }
        }
        __syncthreads();

        // ---- heads GEMM: [r|offs] = embb . [wr;wo]^T  (M=64, N=8, K=64), warps 0-3 ----
        if (wid < 4) {
            float acc[4] = {0.0f, 0.0f, 0.0f, 0.0f};
            #pragma unroll
            for (int kc = 0; kc < 4; kc++) {
                uint32_t a[4];
                ldmat4(a, smb + E_OFF +
                       (uint32_t)(((wid * 16 + (lane & 15)) * 72 + kc * 16 + (lane >> 4) * 8) * 2));
                uint32_t b0 = whb[r0 * 33 + kc * 8 + q];
                uint32_t b1f = whb[r0 * 33 + kc * 8 + q + 4];
                mma16816(acc, a, b0, b1f);
            }
            const int p0 = wid * 16 + r0, p1 = p0 + 8;
            const int c0 = 2 * q, c1 = 2 * q + 1;
            #pragma unroll
            for (int h = 0; h < 2; h++) {
                int col = (h == 0) ? c0 : c1;
                float v0 = acc[h], v1 = acc[2 + h];
                if (col < 4) {
                    float bb = brs[col];
                    rs_s[p0 * 4 + col] = 1.0f / (1.0f + __expf(-(v0 + bb)));
                    rs_s[p1 * 4 + col] = 1.0f / (1.0f + __expf(-(v1 + bb)));
                } else if (col < 6) {
                    float bb = bos[col - 4];
                    of_s[p0 * 2 + (col - 4)] = v0 + bb;
                    of_s[p1 * 2 + (col - 4)] = v1 + bb;
                }
            }
        }
        __syncthreads();

        // ---- phase 5 coeffs: one thread per pixel ----
        if (t < 64) {
            const int p = t;
            const int ox = ox0 + p;
            float gx = ((ox + 0.5f) / 2.0f - 0.5f) * inv127 - 1.0f;
            float gy = ((oy + 0.5f) / 2.0f - 0.5f) * inv127 - 1.0f;
            float ix = gx + of_s[p * 2 + 0] * inv127;
            float iy = gy + of_s[p * 2 + 1] * inv127;
            float fx = ((ix + 1.0f) * (float)W - 1.0f) * 0.5f;
            float fy = ((iy + 1.0f) * (float)H - 1.0f) * 0.5f;
            float x0f = floorf(fx), y0f = floorf(fy);
            float wx1 = fx - x0f, wy1 = fy - y0f;
            float wx0 = 1.0f - wx1, wy0 = 1.0f - wy1;
            int x0 = (int)x0f, y0 = (int)y0f;
            bool vx0 = (x0f >= 0.0f) && (x0f <= (float)(W - 1));
            bool vx1 = (x0f >= -1.0f) && (x0f <= (float)(W - 2));
            bool vy0 = (y0f >= 0.0f) && (y0f <= (float)(H - 1));
            bool vy1 = (y0f >= -1.0f) && (y0f <= (float)(H - 2));
            int xi0 = min(max(x0, 0), W - 1), yi0 = min(max(y0, 0), H - 1);
            int xi1 = min(max(x0 + 1, 0), W - 1), yi1 = min(max(y0 + 1, 0), H - 1);
            cw[p] = make_float4((vx0 && vy0) ? wx0 * wy0 : 0.0f,
                                (vx1 && vy0) ? wx1 * wy0 : 0.0f,
                                (vx0 && vy1) ? wx0 * wy1 : 0.0f,
                                (vx1 && vy1) ? wx1 * wy1 : 0.0f);
            ci[p] = make_int4(yi0 * W + xi0, yi0 * W + xi1, yi1 * W + xi0, yi1 * W + xi1);
        }
        __syncthreads();

        // ---- phase 5: offset sample -> fea fp32 (aliases embb, dead) + feab bf16 ----
        {
            const int p  = t & 63;
            const int cb = t >> 6;
            float4 w4 = cw[p];
            int4   i4 = ci[p];
            #pragma unroll 1
            for (int k4 = 0; k4 < 4; k4++) {
                float4 v;
                #pragma unroll
                for (int kk = 0; kk < 4; kk++) {
                    int c = cb * 16 + k4 * 4 + kk;
                    const float* base = xb + c * (H * W);
                    ((float*)&v)[kk] = w4.x * __ldg(base + i4.x) + w4.y * __ldg(base + i4.y)
                                     + w4.z * __ldg(base + i4.z) + w4.w * __ldg(base + i4.w);
                }
                *reinterpret_cast<float4*>(&fea[p * FEA_S + cb * 16 + k4 * 4]) = v;
                uint2 pk = make_uint2(packbf(v.x, v.y), packbf(v.z, v.w));
                *(uint2*)(smc + FB_OFF + (p * 72 + cb * 16 + k4 * 4) * 2) = pk;
            }
        }
        __syncthreads();

        // ---- G1: T[64,32] = feab . wc^T ----
        {
            float acc[2][4];
            #pragma unroll
            for (int nt = 0; nt < 2; nt++)
                #pragma unroll
                for (int i = 0; i < 4; i++) acc[nt][i] = 0.0f;
            #pragma unroll
            for (int kc = 0; kc < 4; kc++) {
                uint32_t a[4];
                ldmat4(a, smb + FB_OFF +
                       (uint32_t)(((mt * 16 + (lane & 15)) * 72 + kc * 16 + (lane >> 4) * 8) * 2));
                #pragma unroll
                for (int nt = 0; nt < 2; nt++) {
                    int n = nh * 16 + nt * 8 + r0;
                    uint32_t b0 = wcb[n * 33 + kc * 8 + q];
                    uint32_t b1f = wcb[n * 33 + kc * 8 + q + 4];
                    mma16816(acc[nt], a, b0, b1f);
                }
            }
            #pragma unroll
            for (int nt = 0; nt < 2; nt++) {
                int c0 = nh * 16 + nt * 8 + q * 2;
                *(float2*)(Ts + (mt * 16 + r0) * 36 + c0)     = make_float2(acc[nt][0], acc[nt][1]);
                *(float2*)(Ts + (mt * 16 + r0 + 8) * 36 + c0) = make_float2(acc[nt][2], acc[nt][3]);
            }
        }
        __syncthreads();

        // ---- glue: comp_d = sum_e r_e T[e*8+d]; u = r_e*comp_d -> bf16 (aliases feab) ----
        if (t < 64) {
            float4 rv = ld4(&rs_s[t * 4]);
            float Tv[32];
            #pragma unroll
            for (int i = 0; i < 8; i++)
                *reinterpret_cast<float4*>(&Tv[i * 4]) = ld4(&Ts[t * 36 + i * 4]);
            float comp[8];
            #pragma unroll
            for (int d = 0; d < 8; d++)
                comp[d] = rv.x * Tv[d] + rv.y * Tv[8 + d] + rv.z * Tv[16 + d] + rv.w * Tv[24 + d];
            uint32_t up[16];
            #pragma unroll
            for (int e = 0; e < 4; e++) {
                float re = ((const float*)&rv)[e];
                #pragma unroll
                for (int dp = 0; dp < 4; dp++)
                    up[e * 4 + dp] = packbf(re * comp[2 * dp], re * comp[2 * dp + 1]);
            }
            #pragma unroll
            for (int i = 0; i < 4; i++)
                *(uint4*)(smc + UB_OFF + t * 80 + i * 16) = *reinterpret_cast<uint4*>(&up[i * 4]);
        }
        __syncthreads();

        // ---- G2: corr = u . wexp'^T ; out = fea + corr ----
        {
            float acc[4][4];
            #pragma unroll
            for (int nt = 0; nt < 4; nt++)
                #pragma unroll
                for (int i = 0; i < 4; i++) acc[nt][i] = 0.0f;
            #pragma unroll
            for (int kc = 0; kc < 2; kc++) {
                uint32_t a[4];
                ldmat4(a, smb + UB_OFF +
                       (uint32_t)(((mt * 16 + (lane & 15)) * 40 + kc * 16 + (lane >> 4) * 8) * 2));
                #pragma unroll
                for (int nt = 0; nt < 4; nt++) {
                    int n = nh * 32 + nt * 8 + r0;
                    uint32_t b0 = web[n * 17 + kc * 8 + q];
                    uint32_t b1f = web[n * 17 + kc * 8 + q + 4];
                    mma16816(acc[nt], a, b0, b1f);
                }
            }
            const int p0 = mt * 16 + r0, p1 = p0 + 8;
            #pragma unroll
            for (int nt = 0; nt < 4; nt++) {
                int c0 = nh * 32 + nt * 8 + q * 2;
                float2 f0 = *(const float2*)(fea + p0 * FEA_S + c0);
                float2 f1 = *(const float2*)(fea + p1 * FEA_S + c0);
                size_t base0 = (((size_t)bz * C + c0) * OUT + oy) * OUT + ox0;
                size_t base1 = base0 + (size_t)OUT * OUT;
                out[base0 + p0] = f0.x + acc[nt][0];
                out[base1 + p0] = f0.y + acc[nt][1];
                out[base0 + p1] = f1.x + acc[nt][2];
                out[base1 + p1] = f1.y + acc[nt][3];
            }
        }
        __syncthreads();   // protect dynamic-region aliases across loop iterations
    }
}

extern "C" void kernel_launch(void* const* d_in, const int* in_sizes, int n_in,
                              void* d_out, int out_size) {
    (void)in_sizes; (void)n_in; (void)out_size;
    const float* x    = (const float*)d_in[0];
    const float* wcmp = (const float*)d_in[1];
    const float* wexp = (const float*)d_in[2];
    const float* w1   = (const float*)d_in[3];
    const float* b1   = (const float*)d_in[4];
    const float* w2   = (const float*)d_in[5];
    const float* b2   = (const float*)d_in[6];
    const float* wr   = (const float*)d_in[7];
    const float* br   = (const float*)d_in[8];
    const float* wo   = (const float*)d_in[9];
    const float* bo   = (const float*)d_in[10];
    float* out = (float*)d_out;

    cudaFuncSetAttribute(scab_fused, cudaFuncAttributeMaxDynamicSharedMemorySize, SMEM_TOTAL);
    scab_fused<<<NBLK, NTHR, SMEM_TOTAL>>>(x, wcmp, wexp, w1, b1, w2, b2, wr, br, wo, bo, out);
}

// round 16
// speedup vs baseline: 4.5150x; 1.0190x over previous
#include <cuda_runtime.h>
#include <cuda_bf16.h>
#include <cstdint>
#include <math.h>

// Problem constants (fixed by setup_inputs)
#define Bz   2
#define C    64
#define H    128
#define W    128
#define OUT  256
#define TILE 64
#define NTHR 256
#define NTILES (Bz * OUT * (OUT / TILE))   // 2048
#define NBLK 444                           // 148 SMs x 3 resident blocks

// ================= fused smem layout (bytes) =================
// persistent region (staged once per block)
#define WCB_OFF 0        // u32 wc pairs [32][33] = 4224
#define WEB_OFF 4224     // u32 wexp' pairs [64][17] = 4352
#define WHB_OFF 8576     // u32 head pairs [8][33] = 1056  (wr rows 0-3, wo rows 4-5, zero 6-7)
#define B1S_OFF 10112    // fp32 [64]
#define B2S_OFF 10368    // fp32 [64]
#define BRS_OFF 10624    // fp32 [4]
#define BOS_OFF 10640    // fp32 [2]
#define RS_OFF  10656    // fp32 rs[64][4] = 1024
#define CW_OFF  11680    // float4 cw[64] = 1024
#define CI_OFF  12704    // int4 ci[64] = 1024
#define W1P_OFF 14336    // u32 w1 pairs [64][41] = 10496 (persistent)  (gap ok)
#define W2P_OFF 24832    // u32 w2 pairs [64][33] = 8448  (persistent)
#define DYN     33280
// dynamic region (per-tile, phases alias)
#define E_OFF   (DYN + 0)       // bf16 embb[64 x 72] / fp32 fea[64][68] = 17408
#define A1_OFF  (DYN + 17408)   // bf16 A1 [64 x 88] = 11264 ; feab [64 x 72] ; then u [64 x 40]
#define HID_OFF (DYN + 28672)   // fp32 strip[64][34] / bf16 hid [64 x 72] / fp32 T [64][36] = 9216
#define FB_OFF  A1_OFF
#define UB_OFF  A1_OFF          // u aliases feab (dead after G1)
#define T_OFF   HID_OFF
#define STR_OFF HID_OFF         // strip aliases HID/T region (dead across tile boundary)
#define SMEM_TOTAL 71168        // DYN (33280) + dynamic (37888)
#define FEA_S 68

typedef unsigned long long u64t;

__device__ __forceinline__ float4 ld4(const float* p) { return *reinterpret_cast<const float4*>(p); }

__device__ __forceinline__ uint32_t smem_to_u32(const void* p) {
    uint32_t a;
    asm("{ .reg .u64 t; cvta.to.shared.u64 t, %1; cvt.u32.u64 %0, t; }" : "=r"(a) : "l"(p));
    return a;
}
__device__ __forceinline__ uint32_t packbf(float lo, float hi) {
    uint32_t r; asm("cvt.rn.bf16x2.f32 %0, %1, %2;" : "=r"(r) : "f"(hi), "f"(lo)); return r;
}

__device__ __forceinline__ void mma16816(float* c, const uint32_t* a, uint32_t b0, uint32_t b1) {
    asm volatile("mma.sync.aligned.m16n8k16.row.col.f32.bf16.bf16.f32 "
        "{%0,%1,%2,%3}, {%4,%5,%6,%7}, {%8,%9}, {%0,%1,%2,%3};"
        : "+f"(c[0]), "+f"(c[1]), "+f"(c[2]), "+f"(c[3])
        : "r"(a[0]), "r"(a[1]), "r"(a[2]), "r"(a[3]), "r"(b0), "r"(b1));
}
__device__ __forceinline__ void ldmat4(uint32_t* a, uint32_t addr) {
    asm volatile("ldmatrix.sync.aligned.m8n8.x4.shared.b16 {%0,%1,%2,%3}, [%4];"
        : "=r"(a[0]), "=r"(a[1]), "=r"(a[2]), "=r"(a[3]) : "r"(addr));
}

// Compute folded bilinear coeffs/indices for one pixel (validity folded into weights)
__device__ __forceinline__ void sample_coeffs(float fx, float fy, float4* wout, int4* iout) {
    float x0f = floorf(fx), y0f = floorf(fy);
    float wx1 = fx - x0f, wy1 = fy - y0f;
    float wx0 = 1.0f - wx1, wy0 = 1.0f - wy1;
    int x0 = (int)x0f, y0 = (int)y0f;
    bool vx0 = (x0f >= 0.0f) && (x0f <= (float)(W - 1));
    bool vx1 = (x0f >= -1.0f) && (x0f <= (float)(W - 2));
    bool vy0 = (y0f >= 0.0f) && (y0f <= (float)(H - 1));
    bool vy1 = (y0f >= -1.0f) && (y0f <= (float)(H - 2));
    int xi0 = min(max(x0, 0), W - 1), yi0 = min(max(y0, 0), H - 1);
    int xi1 = min(max(x0 + 1, 0), W - 1), yi1 = min(max(y0 + 1, 0), H - 1);
    *wout = make_float4((vx0 && vy0) ? wx0 * wy0 : 0.0f,
                        (vx1 && vy0) ? wx1 * wy0 : 0.0f,
                        (vx0 && vy1) ? wx0 * wy1 : 0.0f,
                        (vx1 && vy1) ? wx1 * wy1 : 0.0f);
    *iout = make_int4(yi0 * W + xi0, yi0 * W + xi1, yi1 * W + xi0, yi1 * W + xi1);
}

// =================== persistent fused kernel ===================
__global__ __launch_bounds__(NTHR, 3)
void scab_fused(const float* __restrict__ x,
                const float* __restrict__ wcmp, const float* __restrict__ wexp,
                const float* __restrict__ w1, const float* __restrict__ b1,
                const float* __restrict__ w2, const float* __restrict__ b2,
                const float* __restrict__ wr, const float* __restrict__ br,
                const float* __restrict__ wo, const float* __restrict__ bo,
                float* __restrict__ out)
{
    extern __shared__ char smc[];
    float* strip = (float*)(smc + STR_OFF);
    float* fea   = (float*)(smc + E_OFF);
    float* Ts    = (float*)(smc + T_OFF);
    uint32_t* w1p = (uint32_t*)(smc + W1P_OFF);
    uint32_t* w2p = (uint32_t*)(smc + W2P_OFF);
    uint32_t* wcb = (uint32_t*)(smc + WCB_OFF);
    uint32_t* web = (uint32_t*)(smc + WEB_OFF);
    uint32_t* whb = (uint32_t*)(smc + WHB_OFF);
    float* b1s  = (float*)(smc + B1S_OFF);
    float* b2s  = (float*)(smc + B2S_OFF);
    float* brs  = (float*)(smc + BRS_OFF);
    float* bos  = (float*)(smc + BOS_OFF);
    float* rs_s = (float*)(smc + RS_OFF);
    float4* cw  = (float4*)(smc + CW_OFF);
    int4*   ci  = (int4*)(smc + CI_OFF);
    const uint32_t smb = smem_to_u32(smc);

    const int t = threadIdx.x;
    const int wid = t >> 5;
    const int lane = t & 31;

    // ---- stage ALL weights ONCE per block ----
    for (int i = t; i < 64 * 40; i += NTHR) {
        int n = i / 40, kp = i - n * 40, k = kp * 2;
        float v0 = (k     < 68) ? w1[n * 68 + k    ] : 0.0f;
        float v1 = (k + 1 < 68) ? w1[n * 68 + k + 1] : 0.0f;
        w1p[n * 41 + kp] = packbf(v0, v1);
    }
    for (int i = t; i < 64 * 32; i += NTHR) {
        int n = i / 32, kp = i - n * 32, k = kp * 2;
        w2p[n * 33 + kp] = packbf(w2[n * 64 + k], w2[n * 64 + k + 1]);
    }
    for (int i = t; i < 32 * 32; i += NTHR) {
        int n = i >> 5, kp = i & 31;
        wcb[n * 33 + kp] = packbf(wcmp[n * 64 + 2 * kp], wcmp[n * 64 + 2 * kp + 1]);
    }
    for (int i = t; i < 64 * 16; i += NTHR) {
        int n = i >> 4, kp = i & 15;
        int ed0 = 2 * kp, ed1 = 2 * kp + 1;
        float v0 = wexp[(((ed0 >> 3) * 64) + n) * 8 + (ed0 & 7)];
        float v1 = wexp[(((ed1 >> 3) * 64) + n) * 8 + (ed1 & 7)];
        web[n * 17 + kp] = packbf(v0, v1);
    }
    if (t < 256) {  // head weights: rows 0-3 = wr, 4-5 = wo, 6-7 = 0
        int n = t >> 5, kp = t & 31, k = kp * 2;
        float v0 = 0.0f, v1 = 0.0f;
        if (n < 4)      { v0 = wr[n * 64 + k];       v1 = wr[n * 64 + k + 1]; }
        else if (n < 6) { v0 = wo[(n - 4) * 64 + k]; v1 = wo[(n - 4) * 64 + k + 1]; }
        whb[n * 33 + kp] = packbf(v0, v1);
    }
    if (t < 64) { b1s[t] = b1[t]; b2s[t] = b2[t]; }
    if (t < 4) brs[t] = br[t];
    if (t < 2) bos[t] = bo[t];
    __syncthreads();

    const float inv127 = 2.0f / 127.0f;
    const int mt = wid >> 1;
    const int nh = wid & 1;
    const int r0 = lane >> 2;
    const int q  = lane & 3;

    // ---- persistent loop over tiles ----
    for (int tile = blockIdx.x; tile < NTILES; tile += NBLK) {
        const int ox0 = (tile & 3) * TILE;
        const int oy  = (tile >> 2) & 255;
        const int bz  = tile >> 10;
        const float* xb = x + (size_t)bz * C * H * W;

        // ---- phase 1a: stage + vertical lerp -> strip[c][j], 64x34 (aliases HID/T) ----
        float gx_blk = ((ox0 + 0.5f) / 2.0f - 0.5f) * inv127 - 1.0f;
        float fx_blk = ((gx_blk + 1.0f) * (float)W - 1.0f) * 0.5f;
        const int m_blk = (int)floorf(fx_blk);
        {
            float gy = ((oy + 0.5f) / 2.0f - 0.5f) * inv127 - 1.0f;
            float fy = ((gy + 1.0f) * (float)H - 1.0f) * 0.5f;
            float y0f = floorf(fy);
            float wy1 = fy - y0f, wy0 = 1.0f - wy1;
            int y0 = (int)y0f;
            bool vy0 = (y0 >= 0) && (y0 <= H - 1);
            bool vy1 = (y0 >= -1) && (y0 <= H - 2);
            int yi0 = min(max(y0, 0), H - 1);
            int yi1 = min(max(y0 + 1, 0), H - 1);
            #pragma unroll 1
            for (int i = t; i < 64 * 34; i += NTHR) {
                int c = i / 34, j = i - c * 34;
                int xs = m_blk + j;
                bool vx = (xs >= 0) && (xs <= W - 1);
                int xc = min(max(xs, 0), W - 1);
                const float* base = xb + c * (H * W);
                float v0 = (vx && vy0) ? __ldg(base + yi0 * W + xc) : 0.0f;
                float v1 = (vx && vy1) ? __ldg(base + yi1 * W + xc) : 0.0f;
                strip[c * 34 + j] = v0 * wy0 + v1 * wy1;
            }
        }
        __syncthreads();

        // ---- phase 1b: horizontal lerp + coords -> A1 bf16 [p][88] ----
        {
            const int p  = t & 63;
            const int cb = t >> 6;
            const int ox = ox0 + p;
            float gx = ((ox + 0.5f) / 2.0f - 0.5f) * inv127 - 1.0f;
            float fx = ((gx + 1.0f) * (float)W - 1.0f) * 0.5f;
            float x0f = floorf(fx);
            float wx1 = fx - x0f, wx0 = 1.0f - wx1;
            int j0 = (int)x0f - m_blk;
            char* a1 = smc + A1_OFF + p * 176;
            #define A1PAIR(col, v0, v1) \
                (*(uint32_t*)(a1 + (col) * 2) = packbf((v0), (v1)))
            if (cb == 0) {
                float ah = (oy + 0.5f) / 2.0f;
                float aw = (ox + 0.5f) / 2.0f;
                A1PAIR(0, 0.5f, 0.5f);
                A1PAIR(2, ah - floorf(ah + 0.001f) - 0.5f, aw - floorf(aw + 0.001f) - 0.5f);
            }
            #pragma unroll 1
            for (int c2 = 0; c2 < 8; c2++) {
                int ch = cb * 16 + 2 * c2;
                float u0 = strip[ch * 34 + j0] * wx0 + strip[ch * 34 + j0 + 1] * wx1;
                float u1 = strip[(ch + 1) * 34 + j0] * wx0 + strip[(ch + 1) * 34 + j0 + 1] * wx1;
                A1PAIR(4 + ch, u0, u1);
            }
            if (cb == 3) {
                #pragma unroll
                for (int z = 68; z < 80; z += 2) A1PAIR(z, 0.0f, 0.0f);
            }
            #undef A1PAIR
        }
        __syncthreads();

        // ---- layer1: hid = relu(A1 . w1^T + b1) -> HID (strip dead) ----
        {
            float acc[4][4];
            #pragma unroll
            for (int nt = 0; nt < 4; nt++)
                #pragma unroll
                for (int i = 0; i < 4; i++) acc[nt][i] = 0.0f;
            #pragma unroll
            for (int kc = 0; kc < 5; kc++) {
                uint32_t a[4];
                ldmat4(a, smb + A1_OFF +
                       (uint32_t)(((mt * 16 + (lane & 15)) * 88 + kc * 16 + (lane >> 4) * 8) * 2));
                #pragma unroll
                for (int nt = 0; nt < 4; nt++) {
                    int n = nh * 32 + nt * 8 + r0;
                    uint32_t b0 = w1p[n * 41 + kc * 8 + q];
                    uint32_t b1f = w1p[n * 41 + kc * 8 + q + 4];
                    mma16816(acc[nt], a, b0, b1f);
                }
            }
            __syncthreads();   // all strip reads (1b) done before hid overwrites region
            #pragma unroll
            for (int nt = 0; nt < 4; nt++) {
                int c0 = nh * 32 + nt * 8 + q * 2;
                float bb0 = b1s[c0], bb1 = b1s[c0 + 1];
                uint32_t lo = packbf(fmaxf(acc[nt][0] + bb0, 0.0f), fmaxf(acc[nt][1] + bb1, 0.0f));
                uint32_t hi = packbf(fmaxf(acc[nt][2] + bb0, 0.0f), fmaxf(acc[nt][3] + bb1, 0.0f));
                *(uint32_t*)(smc + HID_OFF + ((mt * 16 + r0) * 72 + c0) * 2)     = lo;
                *(uint32_t*)(smc + HID_OFF + ((mt * 16 + r0 + 8) * 72 + c0) * 2) = hi;
            }
        }
        __syncthreads();

        // ---- layer2: embb = relu(hid . w2^T + b2) -> bf16 [64 x 72] (E region) ----
        {
            float acc[4][4];
            #pragma unroll
            for (int nt = 0; nt < 4; nt++)
                #pragma unroll
                for (int i = 0; i < 4; i++) acc[nt][i] = 0.0f;
            #pragma unroll
            for (int kc = 0; kc < 4; kc++) {
                uint32_t a[4];
                ldmat4(a, smb + HID_OFF +
                       (uint32_t)(((mt * 16 + (lane & 15)) * 72 + kc * 16 + (lane >> 4) * 8) * 2));
                #pragma unroll
                for (int nt = 0; nt < 4; nt++) {
                    int n = nh * 32 + nt * 8 + r0;
                    uint32_t b0 = w2p[n * 33 + kc * 8 + q];
                    uint32_t b1f = w2p[n * 33 + kc * 8 + q + 4];
                    mma16816(acc[nt], a, b0, b1f);
                }
            }
            #pragma unroll
            for (int nt = 0; nt < 4; nt++) {
                int c0 = nh * 32 + nt * 8 + q * 2;
                float bb0 = b2s[c0], bb1 = b2s[c0 + 1];
                uint32_t lo = packbf(fmaxf(acc[nt][0] + bb0, 0.0f), fmaxf(acc[nt][1] + bb1, 0.0f));
                uint32_t hi = packbf(fmaxf(acc[nt][2] + bb0, 0.0f), fmaxf(acc[nt][3] + bb1, 0.0f));
                *(uint32_t*)(smc + E_OFF + ((mt * 16 + r0) * 72 + c0) * 2)     = lo;
                *(uint32_t*)(smc + E_OFF + ((mt * 16 + r0 + 8) * 72 + c0) * 2) = hi;
            }
        }
        __syncthreads();

        // ---- heads GEMM + fused sample-2 coeffs. warps 0-3 ----
        if (wid < 4) {
            float acc[4] = {0.0f, 0.0f, 0.0f, 0.0f};
            #pragma unroll
            for (int kc = 0; kc < 4; kc++) {
                uint32_t a[4];
                ldmat4(a, smb + E_OFF +
                       (uint32_t)(((wid * 16 + (lane & 15)) * 72 + kc * 16 + (lane >> 4) * 8) * 2));
                uint32_t b0 = whb[r0 * 33 + kc * 8 + q];
                uint32_t b1f = whb[r0 * 33 + kc * 8 + q + 4];
                mma16816(acc, a, b0, b1f);
            }
            const int p0 = wid * 16 + r0, p1 = p0 + 8;
            if (q < 2) {
                // r columns 0..3: sigmoid -> rs_s
                int c0 = 2 * q, c1 = 2 * q + 1;
                rs_s[p0 * 4 + c0] = 1.0f / (1.0f + __expf(-(acc[0] + brs[c0])));
                rs_s[p0 * 4 + c1] = 1.0f / (1.0f + __expf(-(acc[1] + brs[c1])));
                rs_s[p1 * 4 + c0] = 1.0f / (1.0f + __expf(-(acc[2] + brs[c0])));
                rs_s[p1 * 4 + c1] = 1.0f / (1.0f + __expf(-(acc[3] + brs[c1])));
            } else if (q == 2) {
                // offsets (cols 4,5) for both pixels -> fold directly into bilinear coeffs
                float of00 = acc[0] + bos[0], of01 = acc[1] + bos[1];
                float of10 = acc[2] + bos[0], of11 = acc[3] + bos[1];
                #pragma unroll
                for (int h = 0; h < 2; h++) {
                    int p  = (h == 0) ? p0 : p1;
                    float o0 = (h == 0) ? of00 : of10;
                    float o1 = (h == 0) ? of01 : of11;
                    int ox = ox0 + p;
                    float gx = ((ox + 0.5f) / 2.0f - 0.5f) * inv127 - 1.0f;
                    float gy = ((oy + 0.5f) / 2.0f - 0.5f) * inv127 - 1.0f;
                    float ix = gx + o0 * inv127;
                    float iy = gy + o1 * inv127;
                    float fx = ((ix + 1.0f) * (float)W - 1.0f) * 0.5f;
                    float fy = ((iy + 1.0f) * (float)H - 1.0f) * 0.5f;
                    float4 w4; int4 i4;
                    sample_coeffs(fx, fy, &w4, &i4);
                    cw[p] = w4;
                    ci[p] = i4;
                }
            }
        }
        __syncthreads();

        // ---- phase 5: offset sample -> fea fp32 (aliases embb, dead) + feab bf16 ----
        {
            const int p  = t & 63;
            const int cb = t >> 6;
            float4 w4 = cw[p];
            int4   i4 = ci[p];
            #pragma unroll 1
            for (int k4 = 0; k4 < 4; k4++) {
                float4 v;
                #pragma unroll
                for (int kk = 0; kk < 4; kk++) {
                    int c = cb * 16 + k4 * 4 + kk;
                    const float* base = xb + c * (H * W);
                    ((float*)&v)[kk] = w4.x * __ldg(base + i4.x) + w4.y * __ldg(base + i4.y)
                                     + w4.z * __ldg(base + i4.z) + w4.w * __ldg(base + i4.w);
                }
                *reinterpret_cast<float4*>(&fea[p * FEA_S + cb * 16 + k4 * 4]) = v;
                uint2 pk = make_uint2(packbf(v.x, v.y), packbf(v.z, v.w));
                *(uint2*)(smc + FB_OFF + (p * 72 + cb * 16 + k4 * 4) * 2) = pk;
            }
        }
        __syncthreads();

        // ---- G1: T[64,32] = feab . wc^T (T aliases HID; hid dead) ----
        {
            float acc[2][4];
            #pragma unroll
            for (int nt = 0; nt < 2; nt++)
                #pragma unroll
                for (int i = 0; i < 4; i++) acc[nt][i] = 0.0f;
            #pragma unroll
            for (int kc = 0; kc < 4; kc++) {
                uint32_t a[4];
                ldmat4(a, smb + FB_OFF +
                       (uint32_t)(((mt * 16 + (lane & 15)) * 72 + kc * 16 + (lane >> 4) * 8) * 2));
                #pragma unroll
                for (int nt = 0; nt < 2; nt++) {
                    int n = nh * 16 + nt * 8 + r0;
                    uint32_t b0 = wcb[n * 33 + kc * 8 + q];
                    uint32_t b1f = wcb[n * 33 + kc * 8 + q + 4];
                    mma16816(acc[nt], a, b0, b1f);
                }
            }
            #pragma unroll
            for (int nt = 0; nt < 2; nt++) {
                int c0 = nh * 16 + nt * 8 + q * 2;
                *(float2*)(Ts + (mt * 16 + r0) * 36 + c0)     = make_float2(acc[nt][0], acc[nt][1]);
                *(float2*)(Ts + (mt * 16 + r0 + 8) * 36 + c0) = make_float2(acc[nt][2], acc[nt][3]);
            }
        }
        __syncthreads();

        // ---- glue: comp_d = sum_e r_e T[e*8+d]; u = r_e*comp_d -> bf16 (aliases feab) ----
        if (t < 64) {
            float4 rv = ld4(&rs_s[t * 4]);
            float Tv[32];
            #pragma unroll
            for (int i = 0; i < 8; i++)
                *reinterpret_cast<float4*>(&Tv[i * 4]) = ld4(&Ts[t * 36 + i * 4]);
            float comp[8];
            #pragma unroll
            for (int d = 0; d < 8; d++)
                comp[d] = rv.x * Tv[d] + rv.y * Tv[8 + d] + rv.z * Tv[16 + d] + rv.w * Tv[24 + d];
            uint32_t up[16];
            #pragma unroll
            for (int e = 0; e < 4; e++) {
                float re = ((const float*)&rv)[e];
                #pragma unroll
                for (int dp = 0; dp < 4; dp++)
                    up[e * 4 + dp] = packbf(re * comp[2 * dp], re * comp[2 * dp + 1]);
            }
            #pragma unroll
            for (int i = 0; i < 4; i++)
                *(uint4*)(smc + UB_OFF + t * 80 + i * 16) = *reinterpret_cast<uint4*>(&up[i * 4]);
        }
        __syncthreads();

        // ---- G2: corr = u . wexp'^T ; out = fea + corr ----
        {
            float acc[4][4];
            #pragma unroll
            for (int nt = 0; nt < 4; nt++)
                #pragma unroll
                for (int i = 0; i < 4; i++) acc[nt][i] = 0.0f;
            #pragma unroll
            for (int kc = 0; kc < 2; kc++) {
                uint32_t a[4];
                ldmat4(a, smb + UB_OFF +
                       (uint32_t)(((mt * 16 + (lane & 15)) * 40 + kc * 16 + (lane >> 4) * 8) * 2));
                #pragma unroll
                for (int nt = 0; nt < 4; nt++) {
                    int n = nh * 32 + nt * 8 + r0;
                    uint32_t b0 = web[n * 17 + kc * 8 + q];
                    uint32_t b1f = web[n * 17 + kc * 8 + q + 4];
                    mma16816(acc[nt], a, b0, b1f);
                }
            }
            const int p0 = mt * 16 + r0, p1 = p0 + 8;
            #pragma unroll
            for (int nt = 0; nt < 4; nt++) {
                int c0 = nh * 32 + nt * 8 + q * 2;
                float2 f0 = *(const float2*)(fea + p0 * FEA_S + c0);
                float2 f1 = *(const float2*)(fea + p1 * FEA_S + c0);
                size_t base0 = (((size_t)bz * C + c0) * OUT + oy) * OUT + ox0;
                size_t base1 = base0 + (size_t)OUT * OUT;
                out[base0 + p0] = f0.x + acc[nt][0];
                out[base1 + p0] = f0.y + acc[nt][1];
                out[base0 + p1] = f1.x + acc[nt][2];
                out[base1 + p1] = f1.y + acc[nt][3];
            }
        }
        // NOTE: no loop-end sync needed — next-tile 1a writes only the strip(T) region,
        // which no warp touches after the glue->G2 barrier; warps reach 1a only after
        // their own G2, and the 1a->1b barrier covers all cross-warp hazards on A1/E.
    }
}

extern "C" void kernel_launch(void* const* d_in, const int* in_sizes, int n_in,
                              void* d_out, int out_size) {
    (void)in_sizes; (void)n_in; (void)out_size;
    const float* x    = (const float*)d_in[0];
    const float* wcmp = (const float*)d_in[1];
    const float* wexp = (const float*)d_in[2];
    const float* w1   = (const float*)d_in[3];
    const float* b1   = (const float*)d_in[4];
    const float* w2   = (const float*)d_in[5];
    const float* b2   = (const float*)d_in[6];
    const float* wr   = (const float*)d_in[7];
    const float* br   = (const float*)d_in[8];
    const float* wo   = (const float*)d_in[9];
    const float* bo   = (const float*)d_in[10];
    float* out = (float*)d_out;

    cudaFuncSetAttribute(scab_fused, cudaFuncAttributeMaxDynamicSharedMemorySize, SMEM_TOTAL);
    scab_fused<<<NBLK, NTHR, SMEM_TOTAL>>>(x, wcmp, wexp, w1, b1, w2, b2, wr, br, wo, bo, out);
}

// round 17
// speedup vs baseline: 4.5173x; 1.0005x over previous
#include <cuda_runtime.h>
#include <cuda_bf16.h>
#include <cstdint>
#include <math.h>

// Problem constants (fixed by setup_inputs)
#define Bz   2
#define C    64
#define H    128
#define W    128
#define OUT  256
#define TILE 64
#define NTHR 256
#define NTILES (Bz * OUT * (OUT / TILE))   // 2048
#define NBLK 444                           // 148 SMs x 3 resident blocks

// ================= fused smem layout (bytes) =================
// persistent region (staged once per block)
#define WCB_OFF 0        // u32 wc pairs [32][33] = 4224
#define WEB_OFF 4224     // u32 wexp' pairs [64][17] = 4352
#define WHB_OFF 8576     // u32 head pairs [8][33] = 1056
#define B1S_OFF 10112    // fp32 [64]
#define B2S_OFF 10368    // fp32 [64]
#define BRS_OFF 10624    // fp32 [4]
#define BOS_OFF 10640    // fp32 [2]
#define RS_OFF  10656    // fp32 rs[64][4] = 1024
#define CW_OFF  11680    // float4 cw[64] = 1024
#define CI_OFF  12704    // int4 ci[64] = 1024
#define W1P_OFF 14336    // u32 w1 pairs [64][41] = 10496
#define W2P_OFF 24832    // u32 w2 pairs [64][33] = 8448
#define DYN     33280
// dynamic region (per-tile, phases alias)
#define E_OFF   (DYN + 0)       // bf16 embb[64 x 72] / fp32 fea[64][68] = 17408
#define A1_OFF  (DYN + 17408)   // bf16 A1 [64 x 88] = 11264 ; feab [64 x 72]
#define HID_OFF (DYN + 28672)   // fp32 strip[64][34] / bf16 hid [64 x 72] / fp32 T [64][36] = 9216
#define FB_OFF  A1_OFF
#define T_OFF   HID_OFF
#define STR_OFF HID_OFF
#define SMEM_TOTAL 71168
#define FEA_S 68

typedef unsigned long long u64t;

__device__ __forceinline__ float4 ld4(const float* p) { return *reinterpret_cast<const float4*>(p); }

__device__ __forceinline__ uint32_t smem_to_u32(const void* p) {
    uint32_t a;
    asm("{ .reg .u64 t; cvta.to.shared.u64 t, %1; cvt.u32.u64 %0, t; }" : "=r"(a) : "l"(p));
    return a;
}
__device__ __forceinline__ uint32_t packbf(float lo, float hi) {
    uint32_t r; asm("cvt.rn.bf16x2.f32 %0, %1, %2;" : "=r"(r) : "f"(hi), "f"(lo)); return r;
}

__device__ __forceinline__ void mma16816(float* c, const uint32_t* a, uint32_t b0, uint32_t b1) {
    asm volatile("mma.sync.aligned.m16n8k16.row.col.f32.bf16.bf16.f32 "
        "{%0,%1,%2,%3}, {%4,%5,%6,%7}, {%8,%9}, {%0,%1,%2,%3};"
        : "+f"(c[0]), "+f"(c[1]), "+f"(c[2]), "+f"(c[3])
        : "r"(a[0]), "r"(a[1]), "r"(a[2]), "r"(a[3]), "r"(b0), "r"(b1));
}
__device__ __forceinline__ void ldmat4(uint32_t* a, uint32_t addr) {
    asm volatile("ldmatrix.sync.aligned.m8n8.x4.shared.b16 {%0,%1,%2,%3}, [%4];"
        : "=r"(a[0]), "=r"(a[1]), "=r"(a[2]), "=r"(a[3]) : "r"(addr));
}

// folded bilinear coeffs/indices for one pixel (validity folded into weights)
__device__ __forceinline__ void sample_coeffs(float fx, float fy, float4* wout, int4* iout) {
    float x0f = floorf(fx), y0f = floorf(fy);
    float wx1 = fx - x0f, wy1 = fy - y0f;
    float wx0 = 1.0f - wx1, wy0 = 1.0f - wy1;
    int x0 = (int)x0f, y0 = (int)y0f;
    bool vx0 = (x0f >= 0.0f) && (x0f <= (float)(W - 1));
    bool vx1 = (x0f >= -1.0f) && (x0f <= (float)(W - 2));
    bool vy0 = (y0f >= 0.0f) && (y0f <= (float)(H - 1));
    bool vy1 = (y0f >= -1.0f) && (y0f <= (float)(H - 2));
    int xi0 = min(max(x0, 0), W - 1), yi0 = min(max(y0, 0), H - 1);
    int xi1 = min(max(x0 + 1, 0), W - 1), yi1 = min(max(y0 + 1, 0), H - 1);
    *wout = make_float4((vx0 && vy0) ? wx0 * wy0 : 0.0f,
                        (vx1 && vy0) ? wx1 * wy0 : 0.0f,
                        (vx0 && vy1) ? wx0 * wy1 : 0.0f,
                        (vx1 && vy1) ? wx1 * wy1 : 0.0f);
    *iout = make_int4(yi0 * W + xi0, yi0 * W + xi1, yi1 * W + xi0, yi1 * W + xi1);
}

// =================== persistent fused kernel ===================
__global__ __launch_bounds__(NTHR, 3)
void scab_fused(const float* __restrict__ x,
                const float* __restrict__ wcmp, const float* __restrict__ wexp,
                const float* __restrict__ w1, const float* __restrict__ b1,
                const float* __restrict__ w2, const float* __restrict__ b2,
                const float* __restrict__ wr, const float* __restrict__ br,
                const float* __restrict__ wo, const float* __restrict__ bo,
                float* __restrict__ out)
{
    extern __shared__ char smc[];
    float* strip = (float*)(smc + STR_OFF);
    float* fea   = (float*)(smc + E_OFF);
    float* Ts    = (float*)(smc + T_OFF);
    uint32_t* w1p = (uint32_t*)(smc + W1P_OFF);
    uint32_t* w2p = (uint32_t*)(smc + W2P_OFF);
    uint32_t* wcb = (uint32_t*)(smc + WCB_OFF);
    uint32_t* web = (uint32_t*)(smc + WEB_OFF);
    uint32_t* whb = (uint32_t*)(smc + WHB_OFF);
    float* b1s  = (float*)(smc + B1S_OFF);
    float* b2s  = (float*)(smc + B2S_OFF);
    float* brs  = (float*)(smc + BRS_OFF);
    float* bos  = (float*)(smc + BOS_OFF);
    float* rs_s = (float*)(smc + RS_OFF);
    float4* cw  = (float4*)(smc + CW_OFF);
    int4*   ci  = (int4*)(smc + CI_OFF);
    const uint32_t smb = smem_to_u32(smc);

    const int t = threadIdx.x;
    const int wid = t >> 5;
    const int lane = t & 31;

    // ---- stage ALL weights ONCE per block ----
    for (int i = t; i < 64 * 40; i += NTHR) {
        int n = i / 40, kp = i - n * 40, k = kp * 2;
        float v0 = (k     < 68) ? w1[n * 68 + k    ] : 0.0f;
        float v1 = (k + 1 < 68) ? w1[n * 68 + k + 1] : 0.0f;
        w1p[n * 41 + kp] = packbf(v0, v1);
    }
    for (int i = t; i < 64 * 32; i += NTHR) {
        int n = i / 32, kp = i - n * 32, k = kp * 2;
        w2p[n * 33 + kp] = packbf(w2[n * 64 + k], w2[n * 64 + k + 1]);
    }
    for (int i = t; i < 32 * 32; i += NTHR) {
        int n = i >> 5, kp = i & 31;
        wcb[n * 33 + kp] = packbf(wcmp[n * 64 + 2 * kp], wcmp[n * 64 + 2 * kp + 1]);
    }
    for (int i = t; i < 64 * 16; i += NTHR) {
        int n = i >> 4, kp = i & 15;
        int ed0 = 2 * kp, ed1 = 2 * kp + 1;
        float v0 = wexp[(((ed0 >> 3) * 64) + n) * 8 + (ed0 & 7)];
        float v1 = wexp[(((ed1 >> 3) * 64) + n) * 8 + (ed1 & 7)];
        web[n * 17 + kp] = packbf(v0, v1);
    }
    if (t < 256) {  // head weights: rows 0-3 = wr, 4-5 = wo, 6-7 = 0
        int n = t >> 5, kp = t & 31, k = kp * 2;
        float v0 = 0.0f, v1 = 0.0f;
        if (n < 4)      { v0 = wr[n * 64 + k];       v1 = wr[n * 64 + k + 1]; }
        else if (n < 6) { v0 = wo[(n - 4) * 64 + k]; v1 = wo[(n - 4) * 64 + k + 1]; }
        whb[n * 33 + kp] = packbf(v0, v1);
    }
    if (t < 64) { b1s[t] = b1[t]; b2s[t] = b2[t]; }
    if (t < 4) brs[t] = br[t];
    if (t < 2) bos[t] = bo[t];
    __syncthreads();

    const float inv127 = 2.0f / 127.0f;
    const int mt = wid >> 1;
    const int nh = wid & 1;
    const int r0 = lane >> 2;
    const int q  = lane & 3;

    // ---- persistent loop over tiles ----
    for (int tile = blockIdx.x; tile < NTILES; tile += NBLK) {
        const int ox0 = (tile & 3) * TILE;
        const int oy  = (tile >> 2) & 255;
        const int bz  = tile >> 10;
        const float* xb = x + (size_t)bz * C * H * W;

        // ---- phase 1a: stage + vertical lerp -> strip[c][j], 64x34 (aliases HID/T) ----
        float gx_blk = ((ox0 + 0.5f) / 2.0f - 0.5f) * inv127 - 1.0f;
        float fx_blk = ((gx_blk + 1.0f) * (float)W - 1.0f) * 0.5f;
        const int m_blk = (int)floorf(fx_blk);
        {
            float gy = ((oy + 0.5f) / 2.0f - 0.5f) * inv127 - 1.0f;
            float fy = ((gy + 1.0f) * (float)H - 1.0f) * 0.5f;
            float y0f = floorf(fy);
            float wy1 = fy - y0f, wy0 = 1.0f - wy1;
            int y0 = (int)y0f;
            bool vy0 = (y0 >= 0) && (y0 <= H - 1);
            bool vy1 = (y0 >= -1) && (y0 <= H - 2);
            int yi0 = min(max(y0, 0), H - 1);
            int yi1 = min(max(y0 + 1, 0), H - 1);
            #pragma unroll 3
            for (int i = t; i < 64 * 34; i += NTHR) {
                int c = i / 34, j = i - c * 34;
                int xs = m_blk + j;
                bool vx = (xs >= 0) && (xs <= W - 1);
                int xc = min(max(xs, 0), W - 1);
                const float* base = xb + c * (H * W);
                float v0 = (vx && vy0) ? __ldg(base + yi0 * W + xc) : 0.0f;
                float v1 = (vx && vy1) ? __ldg(base + yi1 * W + xc) : 0.0f;
                strip[c * 34 + j] = v0 * wy0 + v1 * wy1;
            }
        }
        __syncthreads();

        // ---- phase 1b: horizontal lerp + coords -> A1 bf16 [p][88] ----
        {
            const int p  = t & 63;
            const int cb = t >> 6;
            const int ox = ox0 + p;
            float gx = ((ox + 0.5f) / 2.0f - 0.5f) * inv127 - 1.0f;
            float fx = ((gx + 1.0f) * (float)W - 1.0f) * 0.5f;
            float x0f = floorf(fx);
            float wx1 = fx - x0f, wx0 = 1.0f - wx1;
            int j0 = (int)x0f - m_blk;
            char* a1 = smc + A1_OFF + p * 176;
            #define A1PAIR(col, v0, v1) \
                (*(uint32_t*)(a1 + (col) * 2) = packbf((v0), (v1)))
            if (cb == 0) {
                float ah = (oy + 0.5f) / 2.0f;
                float aw = (ox + 0.5f) / 2.0f;
                A1PAIR(0, 0.5f, 0.5f);
                A1PAIR(2, ah - floorf(ah + 0.001f) - 0.5f, aw - floorf(aw + 0.001f) - 0.5f);
            }
            #pragma unroll 1
            for (int c2 = 0; c2 < 8; c2++) {
                int ch = cb * 16 + 2 * c2;
                float u0 = strip[ch * 34 + j0] * wx0 + strip[ch * 34 + j0 + 1] * wx1;
                float u1 = strip[(ch + 1) * 34 + j0] * wx0 + strip[(ch + 1) * 34 + j0 + 1] * wx1;
                A1PAIR(4 + ch, u0, u1);
            }
            if (cb == 3) {
                #pragma unroll
                for (int z = 68; z < 80; z += 2) A1PAIR(z, 0.0f, 0.0f);
            }
            #undef A1PAIR
        }
        __syncthreads();

        // ---- layer1: hid = relu(A1 . w1^T + b1) -> HID (strip dead) ----
        {
            float acc[4][4];
            #pragma unroll
            for (int nt = 0; nt < 4; nt++)
                #pragma unroll
                for (int i = 0; i < 4; i++) acc[nt][i] = 0.0f;
            #pragma unroll
            for (int kc = 0; kc < 5; kc++) {
                uint32_t a[4];
                ldmat4(a, smb + A1_OFF +
                       (uint32_t)(((mt * 16 + (lane & 15)) * 88 + kc * 16 + (lane >> 4) * 8) * 2));
                #pragma unroll
                for (int nt = 0; nt < 4; nt++) {
                    int n = nh * 32 + nt * 8 + r0;
                    uint32_t b0 = w1p[n * 41 + kc * 8 + q];
                    uint32_t b1f = w1p[n * 41 + kc * 8 + q + 4];
                    mma16816(acc[nt], a, b0, b1f);
                }
            }
            __syncthreads();   // all strip reads (1b) done before hid overwrites region
            #pragma unroll
            for (int nt = 0; nt < 4; nt++) {
                int c0 = nh * 32 + nt * 8 + q * 2;
                float bb0 = b1s[c0], bb1 = b1s[c0 + 1];
                uint32_t lo = packbf(fmaxf(acc[nt][0] + bb0, 0.0f), fmaxf(acc[nt][1] + bb1, 0.0f));
                uint32_t hi = packbf(fmaxf(acc[nt][2] + bb0, 0.0f), fmaxf(acc[nt][3] + bb1, 0.0f));
                *(uint32_t*)(smc + HID_OFF + ((mt * 16 + r0) * 72 + c0) * 2)     = lo;
                *(uint32_t*)(smc + HID_OFF + ((mt * 16 + r0 + 8) * 72 + c0) * 2) = hi;
            }
        }
        __syncthreads();

        // ---- layer2: embb = relu(hid . w2^T + b2) -> bf16 [64 x 72] (E region) ----
        {
            float acc[4][4];
            #pragma unroll
            for (int nt = 0; nt < 4; nt++)
                #pragma unroll
                for (int i = 0; i < 4; i++) acc[nt][i] = 0.0f;
            #pragma unroll
            for (int kc = 0; kc < 4; kc++) {
                uint32_t a[4];
                ldmat4(a, smb + HID_OFF +
                       (uint32_t)(((mt * 16 + (lane & 15)) * 72 + kc * 16 + (lane >> 4) * 8) * 2));
                #pragma unroll
                for (int nt = 0; nt < 4; nt++) {
                    int n = nh * 32 + nt * 8 + r0;
                    uint32_t b0 = w2p[n * 33 + kc * 8 + q];
                    uint32_t b1f = w2p[n * 33 + kc * 8 + q + 4];
                    mma16816(acc[nt], a, b0, b1f);
                }
            }
            #pragma unroll
            for (int nt = 0; nt < 4; nt++) {
                int c0 = nh * 32 + nt * 8 + q * 2;
                float bb0 = b2s[c0], bb1 = b2s[c0 + 1];
                uint32_t lo = packbf(fmaxf(acc[nt][0] + bb0, 0.0f), fmaxf(acc[nt][1] + bb1, 0.0f));
                uint32_t hi = packbf(fmaxf(acc[nt][2] + bb0, 0.0f), fmaxf(acc[nt][3] + bb1, 0.0f));
                *(uint32_t*)(smc + E_OFF + ((mt * 16 + r0) * 72 + c0) * 2)     = lo;
                *(uint32_t*)(smc + E_OFF + ((mt * 16 + r0 + 8) * 72 + c0) * 2) = hi;
            }
        }
        __syncthreads();

        // ---- heads GEMM + fused sample-2 coeffs. warps 0-3 ----
        if (wid < 4) {
            float acc[4] = {0.0f, 0.0f, 0.0f, 0.0f};
            #pragma unroll
            for (int kc = 0; kc < 4; kc++) {
                uint32_t a[4];
                ldmat4(a, smb + E_OFF +
                       (uint32_t)(((wid * 16 + (lane & 15)) * 72 + kc * 16 + (lane >> 4) * 8) * 2));
                uint32_t b0 = whb[r0 * 33 + kc * 8 + q];
                uint32_t b1f = whb[r0 * 33 + kc * 8 + q + 4];
                mma16816(acc, a, b0, b1f);
            }
            const int p0 = wid * 16 + r0, p1 = p0 + 8;
            if (q < 2) {
                int c0 = 2 * q, c1 = 2 * q + 1;
                rs_s[p0 * 4 + c0] = 1.0f / (1.0f + __expf(-(acc[0] + brs[c0])));
                rs_s[p0 * 4 + c1] = 1.0f / (1.0f + __expf(-(acc[1] + brs[c1])));
                rs_s[p1 * 4 + c0] = 1.0f / (1.0f + __expf(-(acc[2] + brs[c0])));
                rs_s[p1 * 4 + c1] = 1.0f / (1.0f + __expf(-(acc[3] + brs[c1])));
            } else if (q == 2) {
                float of00 = acc[0] + bos[0], of01 = acc[1] + bos[1];
                float of10 = acc[2] + bos[0], of11 = acc[3] + bos[1];
                #pragma unroll
                for (int h = 0; h < 2; h++) {
                    int p  = (h == 0) ? p0 : p1;
                    float o0 = (h == 0) ? of00 : of10;
                    float o1 = (h == 0) ? of01 : of11;
                    int ox = ox0 + p;
                    float gx = ((ox + 0.5f) / 2.0f - 0.5f) * inv127 - 1.0f;
                    float gy = ((oy + 0.5f) / 2.0f - 0.5f) * inv127 - 1.0f;
                    float ix = gx + o0 * inv127;
                    float iy = gy + o1 * inv127;
                    float fx = ((ix + 1.0f) * (float)W - 1.0f) * 0.5f;
                    float fy = ((iy + 1.0f) * (float)H - 1.0f) * 0.5f;
                    float4 w4; int4 i4;
                    sample_coeffs(fx, fy, &w4, &i4);
                    cw[p] = w4;
                    ci[p] = i4;
                }
            }
        }
        __syncthreads();

        // ---- phase 5: offset sample -> fea fp32 (aliases embb, dead) + feab bf16 ----
        {
            const int p  = t & 63;
            const int cb = t >> 6;
            float4 w4 = cw[p];
            int4   i4 = ci[p];
            #pragma unroll 1
            for (int k4 = 0; k4 < 4; k4++) {
                float4 v;
                #pragma unroll
                for (int kk = 0; kk < 4; kk++) {
                    int c = cb * 16 + k4 * 4 + kk;
                    const float* base = xb + c * (H * W);
                    ((float*)&v)[kk] = w4.x * __ldg(base + i4.x) + w4.y * __ldg(base + i4.y)
                                     + w4.z * __ldg(base + i4.z) + w4.w * __ldg(base + i4.w);
                }
                *reinterpret_cast<float4*>(&fea[p * FEA_S + cb * 16 + k4 * 4]) = v;
                uint2 pk = make_uint2(packbf(v.x, v.y), packbf(v.z, v.w));
                *(uint2*)(smc + FB_OFF + (p * 72 + cb * 16 + k4 * 4) * 2) = pk;
            }
        }
        __syncthreads();

        // ---- G1: T[64,32] = feab . wc^T (T aliases HID; hid dead) ----
        {
            float acc[2][4];
            #pragma unroll
            for (int nt = 0; nt < 2; nt++)
                #pragma unroll
                for (int i = 0; i < 4; i++) acc[nt][i] = 0.0f;
            #pragma unroll
            for (int kc = 0; kc < 4; kc++) {
                uint32_t a[4];
                ldmat4(a, smb + FB_OFF +
                       (uint32_t)(((mt * 16 + (lane & 15)) * 72 + kc * 16 + (lane >> 4) * 8) * 2));
                #pragma unroll
                for (int nt = 0; nt < 2; nt++) {
                    int n = nh * 16 + nt * 8 + r0;
                    uint32_t b0 = wcb[n * 33 + kc * 8 + q];
                    uint32_t b1f = wcb[n * 33 + kc * 8 + q + 4];
                    mma16816(acc[nt], a, b0, b1f);
                }
            }
            #pragma unroll
            for (int nt = 0; nt < 2; nt++) {
                int c0 = nh * 16 + nt * 8 + q * 2;
                *(float2*)(Ts + (mt * 16 + r0) * 36 + c0)     = make_float2(acc[nt][0], acc[nt][1]);
                *(float2*)(Ts + (mt * 16 + r0 + 8) * 36 + c0) = make_float2(acc[nt][2], acc[nt][3]);
            }
        }
        __syncthreads();

        // ---- G2: u built IN-REGISTERS from Ts (glue phase eliminated);
        //      corr = u . wexp'^T ; out = fea + corr ----
        {
            const int p0 = mt * 16 + r0, p1 = p0 + 8;
            float4 rv0 = ld4(&rs_s[p0 * 4]);
            float4 rv1 = ld4(&rs_s[p1 * 4]);
            // comp_{2q}, comp_{2q+1} for both pixels: comp_d = sum_e r_e * T[p][e*8+d]
            float2 c0v = make_float2(0.0f, 0.0f), c1v = make_float2(0.0f, 0.0f);
            #pragma unroll
            for (int e = 0; e < 4; e++) {
                float2 t0 = *(const float2*)(Ts + p0 * 36 + e * 8 + 2 * q);
                float2 t1 = *(const float2*)(Ts + p1 * 36 + e * 8 + 2 * q);
                float re0 = ((const float*)&rv0)[e];
                float re1 = ((const float*)&rv1)[e];
                c0v.x = fmaf(re0, t0.x, c0v.x); c0v.y = fmaf(re0, t0.y, c0v.y);
                c1v.x = fmaf(re1, t1.x, c1v.x); c1v.y = fmaf(re1, t1.y, c1v.y);
            }
            // A fragments: chunk kc covers u-cols 16kc..16kc+15 -> e = 2kc (a0,a1), 2kc+1 (a2,a3); d = 2q,2q+1
            float acc[4][4];
            #pragma unroll
            for (int nt = 0; nt < 4; nt++)
                #pragma unroll
                for (int i = 0; i < 4; i++) acc[nt][i] = 0.0f;
            #pragma unroll
            for (int kc = 0; kc < 2; kc++) {
                float reA0 = ((const float*)&rv0)[2 * kc];
                float reB0 = ((const float*)&rv0)[2 * kc + 1];
                float reA1 = ((const float*)&rv1)[2 * kc];
                float reB1 = ((const float*)&rv1)[2 * kc + 1];
                uint32_t afr[4];
                afr[0] = packbf(reA0 * c0v.x, reA0 * c0v.y);
                afr[1] = packbf(reA1 * c1v.x, reA1 * c1v.y);
                afr[2] = packbf(reB0 * c0v.x, reB0 * c0v.y);
                afr[3] = packbf(reB1 * c1v.x, reB1 * c1v.y);
                #pragma unroll
                for (int nt = 0; nt < 4; nt++) {
                    int n = nh * 32 + nt * 8 + r0;
                    uint32_t b0 = web[n * 17 + kc * 8 + q];
                    uint32_t b1f = web[n * 17 + kc * 8 + q + 4];
                    mma16816(acc[nt], afr, b0, b1f);
                }
            }
            #pragma unroll
            for (int nt = 0; nt < 4; nt++) {
                int c0 = nh * 32 + nt * 8 + q * 2;
                float2 f0 = *(const float2*)(fea + p0 * FEA_S + c0);
                float2 f1 = *(const float2*)(fea + p1 * FEA_S + c0);
                size_t base0 = (((size_t)bz * C + c0) * OUT + oy) * OUT + ox0;
                size_t base1 = base0 + (size_t)OUT * OUT;
                out[base0 + p0] = f0.x + acc[nt][0];
                out[base1 + p0] = f0.y + acc[nt][1];
                out[base0 + p1] = f1.x + acc[nt][2];
                out[base1 + p1] = f1.y + acc[nt][3];
            }
        }
        __syncthreads();   // next-tile 1a writes strip (aliases Ts, read above)
    }
}

extern "C" void kernel_launch(void* const* d_in, const int* in_sizes, int n_in,
                              void* d_out, int out_size) {
    (void)in_sizes; (void)n_in; (void)out_size;
    const float* x    = (const float*)d_in[0];
    const float* wcmp = (const float*)d_in[1];
    const float* wexp = (const float*)d_in[2];
    const float* w1   = (const float*)d_in[3];
    const float* b1   = (const float*)d_in[4];
    const float* w2   = (const float*)d_in[5];
    const float* b2   = (const float*)d_in[6];
    const float* wr   = (const float*)d_in[7];
    const float* br   = (const float*)d_in[8];
    const float* wo   = (const float*)d_in[9];
    const float* bo   = (const float*)d_in[10];
    float* out = (float*)d_out;

    cudaFuncSetAttribute(scab_fused, cudaFuncAttributeMaxDynamicSharedMemorySize, SMEM_TOTAL);
    scab_fused<<<NBLK, NTHR, SMEM_TOTAL>>>(x, wcmp, wexp, w1, b1, w2, b2, wr, br, wo, bo, out);
}